// round 10
// baseline (speedup 1.0000x reference)
#include <cuda_runtime.h>
#include <math.h>

#define HW 4096

__device__ float g_enc[64 * HW];
__device__ float g_feat[256 * HW];
__device__ float g_fq[HW * 256];
__device__ float g_fk[HW * 256];
__device__ float g_fv[HW * 256];
__device__ float g_off1[HW * 256];
__device__ float g_act[HW * 256];
__device__ float g_offmap[HW * 98];
__device__ float g_attn[4096 * 49 * 8];
__device__ int   g_kidx[4096 * 49];
__device__ float g_skipv[4096 * 3];
__device__ float g_hidden[4096 * 256];
__device__ float g_Wi1T[12546 * 256];
__device__ float g_Wi1Tlo[12546 * 256];
__device__ float g_Wc1T[98 * 256];
__device__ float g_Wc2T[256 * 49];
// conv weights transformed to [tap][ci][co], tf32 hi/lo
__device__ float g_WchTh[9 * 64 * 256],  g_WchTl[9 * 64 * 256];
__device__ float g_WqTh[9 * 256 * 256],  g_WqTl[9 * 256 * 256];
__device__ float g_WkTh[9 * 256 * 256],  g_WkTl[9 * 256 * 256];
__device__ float g_WvTh[9 * 256 * 256],  g_WvTl[9 * 256 * 256];

__device__ __forceinline__ float totf32(float x) {
    float r; asm("cvt.rna.tf32.f32 %0, %1;" : "=f"(r) : "f"(x)); return r;
}
__device__ __forceinline__ void mma_tf32(float* c, const unsigned* a, const unsigned* b) {
    asm volatile("mma.sync.aligned.m16n8k8.row.col.f32.tf32.tf32.f32 "
        "{%0,%1,%2,%3}, {%4,%5,%6,%7}, {%8,%9}, {%0,%1,%2,%3};"
        : "+f"(c[0]), "+f"(c[1]), "+f"(c[2]), "+f"(c[3])
        : "r"(a[0]), "r"(a[1]), "r"(a[2]), "r"(a[3]), "r"(b[0]), "r"(b[1]));
}

// ---------------- transpose + optional tf32 hi/lo split ---------------------
__global__ void transpose_kernel(const float* __restrict__ src, float* __restrict__ dst,
                                 float* __restrict__ dst_lo, int rows, int cols)
{
    __shared__ float tile[32][33];
    int c0 = blockIdx.x * 32, r0 = blockIdx.y * 32;
    int tx = threadIdx.x, ty = threadIdx.y;
#pragma unroll
    for (int i = 0; i < 32; i += 8) {
        int r = r0 + ty + i, c = c0 + tx;
        tile[ty + i][tx] = (r < rows && c < cols) ? src[r * cols + c] : 0.f;
    }
    __syncthreads();
#pragma unroll
    for (int i = 0; i < 32; i += 8) {
        int r = c0 + ty + i, c = r0 + tx;
        if (r < cols && c < rows) {
            float v = tile[tx][ty + i];
            if (dst_lo) {
                float hi = totf32(v);
                dst[r * rows + c] = hi;
                dst_lo[r * rows + c] = totf32(v - hi);
            } else {
                dst[r * rows + c] = v;
            }
        }
    }
}

// ---------------- conv weight transform: W[co][ci][tap] -> [tap][ci][co] hi/lo
__global__ void wtrans_kernel(const float* __restrict__ W, float* __restrict__ Th,
                              float* __restrict__ Tl, int CIN)
{
    int tap = blockIdx.x / CIN, ci = blockIdx.x % CIN, co = threadIdx.x;
    float v = W[co * CIN * 9 + ci * 9 + tap];
    float hi = totf32(v);
    Th[(tap * CIN + ci) * 256 + co] = hi;
    Tl[(tap * CIN + ci) * 256 + co] = totf32(v - hi);
}

// ---------------- 3x3 conv via tf32 mma, 3-term split -----------------------
// grid (32 strips, COUT/64), block 256 (8 warps). Strip = image rows 2s,2s+1.
// dyn smem: s_feat[4][66][36] (9504 f) + s_wh[32][72] + s_wl[32][72] = 56448 B
template <int CIN, bool PIXMAJOR>
__global__ void __launch_bounds__(256) convmma_kernel(
    const float* __restrict__ in, const float* __restrict__ Th,
    const float* __restrict__ Tl, const float* __restrict__ B,
    float* __restrict__ out)
{
    extern __shared__ float smx[];
    float* s_feat = smx;           // [(ry*66+h)*36 + ci]
    float* s_wh = smx + 9504;      // [ci][72]
    float* s_wl = smx + 11808;

    const int t = threadIdx.x;
    const int s = blockIdx.x;            // strip
    const int cobase = blockIdx.y * 64;
    const int w = t >> 5, lane = t & 31;
    const int r = lane >> 2, cl = lane & 3;
    const int wrow = w >> 2;             // 0/1: which image row of strip
    const int x0 = (w & 3) * 16;

    float cfrag[8][4];
#pragma unroll
    for (int nt = 0; nt < 8; nt++)
#pragma unroll
        for (int i = 0; i < 4; i++) cfrag[nt][i] = 0.f;

    for (int cb = 0; cb < CIN; cb += 32) {
        __syncthreads();
        // stage feat strip rows 2s-1..2s+2 with x halo, 32 ci
        for (int i = t; i < 4 * 66 * 32; i += 256) {
            int tmp = i / 66, h = i - tmp * 66;
            int ci = tmp & 31, ry = tmp >> 5;
            int row = 2 * s - 1 + ry, x = h - 1;
            float v = 0.f;
            if ((unsigned)row < 64u && (unsigned)x < 64u)
                v = in[(cb + ci) * HW + row * 64 + x];
            s_feat[(ry * 66 + h) * 36 + ci] = v;
        }
#pragma unroll
        for (int tap = 0; tap < 9; tap++) {
            const int dy = tap / 3, dx = tap % 3;
            __syncthreads();
            { // stage weights [32 ci][64 co] hi+lo
                const float4* sh = (const float4*)(Th + (tap * CIN + cb) * 256 + cobase);
                const float4* sl = (const float4*)(Tl + (tap * CIN + cb) * 256 + cobase);
#pragma unroll
                for (int i = 0; i < 2; i++) {
                    int fi = t + i * 256;
                    int ci = fi >> 4, co4 = fi & 15;
                    ((float4*)(s_wh + ci * 72))[co4] = sh[ci * 64 + co4];
                    ((float4*)(s_wl + ci * 72))[co4] = sl[ci * 64 + co4];
                }
            }
            __syncthreads();
            const int rb = (wrow + dy) * 66 + x0 + dx;
#pragma unroll
            for (int ks = 0; ks < 4; ks++) {
                int c0 = ks * 8;
                float a0 = s_feat[(rb + r) * 36 + c0 + cl];
                float a1 = s_feat[(rb + r + 8) * 36 + c0 + cl];
                float a2 = s_feat[(rb + r) * 36 + c0 + cl + 4];
                float a3 = s_feat[(rb + r + 8) * 36 + c0 + cl + 4];
                float h0 = totf32(a0), h1 = totf32(a1), h2 = totf32(a2), h3 = totf32(a3);
                unsigned ah[4] = {__float_as_uint(h0), __float_as_uint(h1),
                                  __float_as_uint(h2), __float_as_uint(h3)};
                unsigned al[4] = {__float_as_uint(totf32(a0 - h0)), __float_as_uint(totf32(a1 - h1)),
                                  __float_as_uint(totf32(a2 - h2)), __float_as_uint(totf32(a3 - h3))};
#pragma unroll
                for (int nt = 0; nt < 8; nt++) {
                    int co = nt * 8 + r;
                    unsigned bh[2] = {__float_as_uint(s_wh[(c0 + cl) * 72 + co]),
                                      __float_as_uint(s_wh[(c0 + cl + 4) * 72 + co])};
                    unsigned bl[2] = {__float_as_uint(s_wl[(c0 + cl) * 72 + co]),
                                      __float_as_uint(s_wl[(c0 + cl + 4) * 72 + co])};
                    mma_tf32(cfrag[nt], ah, bh);
                    mma_tf32(cfrag[nt], al, bh);
                    mma_tf32(cfrag[nt], ah, bl);
                }
            }
        }
    }
    // store: row m of tile -> pixel (2s+wrow)*64 + x0+m ; col -> cobase+...
    const int pixrow = (2 * s + wrow) * 64 + x0;
#pragma unroll
    for (int nt = 0; nt < 8; nt++) {
#pragma unroll
        for (int i = 0; i < 4; i++) {
            int m = r + (i >> 1) * 8;
            int co = cobase + nt * 8 + 2 * cl + (i & 1);
            float v = cfrag[nt][i] + B[co];
            if (PIXMAJOR) out[(pixrow + m) * 256 + co] = v;
            else out[co * HW + pixrow + m] = v;
        }
    }
}

// ---------------- scalar 3x3 conv (enc only). grid(4,4,COUT/16), block 128 --
template <int CIN, int COUT, bool RELU>
__global__ void __launch_bounds__(128) conv3x3_kernel(
    const float* __restrict__ in, const float* __restrict__ W,
    const float* __restrict__ B, float* __restrict__ out)
{
    __shared__ float s_in[18 * 18];
    __shared__ float s_w[16 * 9];
    const int tid = threadIdx.x;
    const int cog = tid >> 6, qid = tid & 63;
    const int qy = qid >> 3, qx = qid & 7;
    const int ty0 = blockIdx.y * 16, tx0 = blockIdx.x * 16;
    const int cobase = blockIdx.z * 16;

    int l_src[3]; bool l_ok[3];
#pragma unroll
    for (int t = 0; t < 3; t++) {
        int i = tid + t * 128; l_ok[t] = false; l_src[t] = 0;
        if (i < 324) {
            int r = i / 18, c = i % 18;
            int y = ty0 + r - 1, x = tx0 + c - 1;
            l_ok[t] = (y >= 0 && y < 64 && x >= 0 && x < 64);
            l_src[t] = y * 64 + x;
        }
    }
    float acc[2][2][8];
#pragma unroll
    for (int a = 0; a < 2; a++)
#pragma unroll
        for (int b = 0; b < 2; b++)
#pragma unroll
            for (int j = 0; j < 8; j++) acc[a][b][j] = 0.f;

    for (int ci = 0; ci < CIN; ci++) {
        const float* inc = in + ci * HW;
#pragma unroll
        for (int t = 0; t < 3; t++) {
            int i = tid + t * 128;
            if (i < 324) s_in[i] = l_ok[t] ? inc[l_src[t]] : 0.f;
        }
#pragma unroll
        for (int i = tid; i < 144; i += 128)
            s_w[i] = W[((cobase + i / 9) * CIN + ci) * 9 + i % 9];
        __syncthreads();
        float p[4][4];
#pragma unroll
        for (int r = 0; r < 4; r++)
#pragma unroll
            for (int c = 0; c < 4; c++)
                p[r][c] = s_in[(qy * 2 + r) * 18 + qx * 2 + c];
#pragma unroll
        for (int j = 0; j < 8; j++) {
            const float* w = &s_w[(cog * 8 + j) * 9];
#pragma unroll
            for (int oy = 0; oy < 2; oy++)
#pragma unroll
                for (int ox = 0; ox < 2; ox++)
                    acc[oy][ox][j] += w[0]*p[oy][ox]   + w[1]*p[oy][ox+1]   + w[2]*p[oy][ox+2]
                                    + w[3]*p[oy+1][ox] + w[4]*p[oy+1][ox+1] + w[5]*p[oy+1][ox+2]
                                    + w[6]*p[oy+2][ox] + w[7]*p[oy+2][ox+1] + w[8]*p[oy+2][ox+2];
        }
        __syncthreads();
    }
#pragma unroll
    for (int oy = 0; oy < 2; oy++)
#pragma unroll
        for (int ox = 0; ox < 2; ox++) {
            int pix = (ty0 + qy * 2 + oy) * 64 + tx0 + qx * 2 + ox;
#pragma unroll
            for (int j = 0; j < 8; j++) {
                int co = cobase + cog * 8 + j;
                float v = acc[oy][ox][j] + B[co];
                if (RELU) v = fmaxf(v, 0.f);
                out[co * HW + pix] = v;
            }
        }
}

// ---------------- grouped 5x5 pad2, groups 8. grid(4,4,8), block 256 --------
__global__ void __launch_bounds__(256) conv5x5g_kernel(
    const float* __restrict__ in, const float* __restrict__ W,
    const float* __restrict__ B, float* __restrict__ out)
{
    __shared__ float s_in[20 * 20];
    __shared__ float s_w[32 * 25];
    const int tid = threadIdx.x;
    const int cog = tid >> 6, qid = tid & 63;
    const int qy = qid >> 3, qx = qid & 7;
    const int ty0 = blockIdx.y * 16, tx0 = blockIdx.x * 16;
    const int grp = blockIdx.z;

    int l_src[2]; bool l_ok[2];
#pragma unroll
    for (int t = 0; t < 2; t++) {
        int i = tid + t * 256; l_ok[t] = false; l_src[t] = 0;
        if (i < 400) {
            int r = i / 20, c = i % 20;
            int y = ty0 + r - 2, x = tx0 + c - 2;
            l_ok[t] = (y >= 0 && y < 64 && x >= 0 && x < 64);
            l_src[t] = y * 64 + x;
        }
    }
    float acc[2][2][8];
#pragma unroll
    for (int a = 0; a < 2; a++)
#pragma unroll
        for (int b = 0; b < 2; b++)
#pragma unroll
            for (int j = 0; j < 8; j++) acc[a][b][j] = 0.f;

    for (int cil = 0; cil < 32; cil++) {
        const float* inc = in + (grp * 32 + cil) * HW;
#pragma unroll
        for (int t = 0; t < 2; t++) {
            int i = tid + t * 256;
            if (i < 400) s_in[i] = l_ok[t] ? inc[l_src[t]] : 0.f;
        }
        for (int i = tid; i < 800; i += 256)
            s_w[i] = W[((grp * 32 + i / 25) * 32 + cil) * 25 + i % 25];
        __syncthreads();
        float p[6][6];
#pragma unroll
        for (int r = 0; r < 6; r++)
#pragma unroll
            for (int c = 0; c < 6; c++)
                p[r][c] = s_in[(qy * 2 + r) * 20 + qx * 2 + c];
#pragma unroll
        for (int j = 0; j < 8; j++) {
            const float* w = &s_w[(cog * 8 + j) * 25];
#pragma unroll
            for (int oy = 0; oy < 2; oy++)
#pragma unroll
                for (int ox = 0; ox < 2; ox++) {
                    float s = 0.f;
#pragma unroll
                    for (int ky = 0; ky < 5; ky++)
#pragma unroll
                        for (int kx = 0; kx < 5; kx++)
                            s += w[ky * 5 + kx] * p[oy + ky][ox + kx];
                    acc[oy][ox][j] += s;
                }
        }
        __syncthreads();
    }
#pragma unroll
    for (int oy = 0; oy < 2; oy++)
#pragma unroll
        for (int ox = 0; ox < 2; ox++) {
            int pix = (ty0 + qy * 2 + oy) * 64 + tx0 + qx * 2 + ox;
#pragma unroll
            for (int j = 0; j < 8; j++) {
                int co = grp * 32 + cog * 8 + j;
                out[pix * 256 + co] = acc[oy][ox][j] + B[co];
            }
        }
}

// ---------------- LayerNorm + exact GELU. grid 512, block 256 ---------------
__global__ void __launch_bounds__(256) ln_gelu_kernel(
    const float* __restrict__ in, const float* __restrict__ gam,
    const float* __restrict__ bet, float* __restrict__ out)
{
    const int lane = threadIdx.x & 31, wid = threadIdx.x >> 5;
    const int pix = blockIdx.x * 8 + wid;
    float x[8];
#pragma unroll
    for (int i = 0; i < 8; i++) x[i] = in[pix * 256 + i * 32 + lane];
    float s = 0.f;
#pragma unroll
    for (int i = 0; i < 8; i++) s += x[i];
#pragma unroll
    for (int o = 16; o; o >>= 1) s += __shfl_xor_sync(0xffffffffu, s, o);
    float mu = s * (1.f / 256.f);
    float d = 0.f;
#pragma unroll
    for (int i = 0; i < 8; i++) { float t = x[i] - mu; d += t * t; }
#pragma unroll
    for (int o = 16; o; o >>= 1) d += __shfl_xor_sync(0xffffffffu, d, o);
    float inv = rsqrtf(d * (1.f / 256.f) + 1e-5f);
#pragma unroll
    for (int i = 0; i < 8; i++) {
        int c = i * 32 + lane;
        float y = (x[i] - mu) * inv * gam[c] + bet[c];
        out[pix * 256 + c] = 0.5f * y * (1.f + erff(y * 0.70710678118654752f));
    }
}

// ---------------- 1x1 conv 256->98. grid 128, block 128 ---------------------
__global__ void __launch_bounds__(128) conv1x1_kernel(
    const float* __restrict__ act, const float* __restrict__ W2, float* __restrict__ out)
{
    __shared__ float s_act[32 * 256];
    const int tid = threadIdx.x;
    const int pb = blockIdx.x * 32;
    const float4* src = (const float4*)(act + pb * 256);
    float4* dst = (float4*)s_act;
    for (int i = tid; i < 32 * 64; i += 128) dst[i] = src[i];
    __syncthreads();
    if (tid < 98) {
        float acc[32];
#pragma unroll
        for (int p = 0; p < 32; p++) acc[p] = 0.f;
        for (int c = 0; c < 256; c++) {
            float w = W2[tid * 256 + c];
#pragma unroll
            for (int p = 0; p < 32; p++) acc[p] += w * s_act[p * 256 + c];
        }
#pragma unroll
        for (int p = 0; p < 32; p++) out[(pb + p) * 98 + tid] = acc[p];
    }
}

// ---------------- per-query prep. grid 4096, block 256 ----------------------
__global__ void __launch_bounds__(256) qprep_kernel(
    const float* __restrict__ coord, const float* __restrict__ inp,
    const float* __restrict__ bc1, const float* __restrict__ bc2)
{
    __shared__ float s_q[256];
    __shared__ float s_rel[98];
    __shared__ float s_av[49 * 8];
    __shared__ float s_wc[49];
    __shared__ float s_h[256];
    __shared__ int   s_kidx[49];

    const int q = blockIdx.x;
    const int tid = threadIdx.x, lane = tid & 31, wid = tid >> 5;
    const float cy = coord[q * 2 + 0], cx = coord[q * 2 + 1];
    const float gx = ((cx + 1.f) * 64.f - 1.f) * 0.5f;
    const float gy = ((cy + 1.f) * 64.f - 1.f) * 0.5f;

    {
        float x0f = floorf(gx), y0f = floorf(gy);
        int x0 = (int)x0f, y0 = (int)y0f;
        float wx = gx - x0f, wy = gy - y0f;
        float a = 0.f;
#pragma unroll
        for (int t = 0; t < 4; t++) {
            int ix = x0 + (t & 1), iy = y0 + (t >> 1);
            float w = ((t & 1) ? wx : 1.f - wx) * ((t >> 1) ? wy : 1.f - wy);
            bool m = (ix >= 0 && ix < 64 && iy >= 0 && iy < 64);
            int pc = min(max(iy, 0), 63) * 64 + min(max(ix, 0), 63);
            float v = g_fq[pc * 256 + tid];
            a += m ? w * v : 0.f;
        }
        s_q[tid] = a;
    }

    const int ix0 = __float2int_rn(gx), iy0 = __float2int_rn(gy);
    const bool m0 = (ix0 >= 0 && ix0 < 64 && iy0 >= 0 && iy0 < 64);
    const int pix0 = min(max(iy0, 0), 63) * 64 + min(max(ix0, 0), 63);
    const float yb = m0 ? (-1.f + 0.015625f + 0.03125f * (float)iy0) : 0.f;
    const float xb = m0 ? (-1.f + 0.015625f + 0.03125f * (float)ix0) : 0.f;

    if (tid < 49) {
        const int k = tid;
        float o0 = m0 ? g_offmap[pix0 * 98 + 2 * k] : 0.f;
        float o1 = m0 ? g_offmap[pix0 * 98 + 2 * k + 1] : 0.f;
        float sy = yb + (float)(k / 7 - 3) * 0.03125f + tanhf(o0) * (2.f / 63.f);
        float sx = xb + (float)(k % 7 - 3) * 0.03125f + tanhf(o1) * (2.f / 63.f);
        s_rel[2 * k] = (cy - sy) * 64.f;
        s_rel[2 * k + 1] = (cx - sx) * 64.f;
        float gky = ((sy + 1.f) * 64.f - 1.f) * 0.5f;
        float gkx = ((sx + 1.f) * 64.f - 1.f) * 0.5f;
        int iky = __float2int_rn(gky), ikx = __float2int_rn(gkx);
        bool ok = (ikx >= 0 && ikx < 64 && iky >= 0 && iky < 64);
        s_kidx[k] = ok ? iky * 64 + ikx : -1;
        g_kidx[q * 49 + k] = s_kidx[k];
    }
    __syncthreads();

    for (int k = wid; k < 49; k += 8) {
        int pix = s_kidx[k];
        int h = lane >> 2, part = lane & 3;
        float s = 0.f;
        if (pix >= 0) {
            const float* fr = g_fk + pix * 256 + h * 32 + part * 8;
            const float* qr = s_q + h * 32 + part * 8;
#pragma unroll
            for (int i = 0; i < 8; i++) s += fr[i] * qr[i];
        }
        s += __shfl_xor_sync(0xffffffffu, s, 1);
        s += __shfl_xor_sync(0xffffffffu, s, 2);
        if (part == 0) s_av[k * 8 + h] = s * 0.17677669529663687f;
    }

    {
        float h1 = bc1[tid];
        for (int i = 0; i < 98; i++) h1 += g_Wc1T[i * 256 + tid] * s_rel[i];
        s_h[tid] = fmaxf(h1, 0.f);
    }
    __syncthreads();

    if (tid < 49) {
        float w = bc2[tid];
        for (int j = 0; j < 256; j++) w += g_Wc2T[j * 49 + tid] * s_h[j];
        s_wc[tid] = w;
    }
    if (tid >= 64 && tid < 67) {
        const int c = tid - 64;
        float gxc = fminf(fmaxf(gx, 0.f), 63.f), gyc = fminf(fmaxf(gy, 0.f), 63.f);
        float x0f = floorf(gxc), y0f = floorf(gyc);
        int x0 = (int)x0f, y0 = (int)y0f;
        float wx = gxc - x0f, wy = gyc - y0f;
        int x1 = min(x0 + 1, 63), y1 = min(y0 + 1, 63);
        const float* I = inp + c * HW;
        g_skipv[q * 3 + c] = (1.f - wx) * (1.f - wy) * I[y0 * 64 + x0]
                           + wx * (1.f - wy) * I[y0 * 64 + x1]
                           + (1.f - wx) * wy * I[y1 * 64 + x0]
                           + wx * wy * I[y1 * 64 + x1];
    }
    __syncthreads();

    if (tid < 8) {
        const int h = tid;
        float mx = -1e30f;
        for (int k = 0; k < 49; k++) mx = fmaxf(mx, s_wc[k] + s_av[k * 8 + h]);
        float sum = 0.f;
        for (int k = 0; k < 49; k++) {
            float e = expf(s_wc[k] + s_av[k * 8 + h] - mx);
            s_av[k * 8 + h] = e;
            sum += e;
        }
        float inv = 1.f / sum;
        for (int k = 0; k < 49; k++) g_attn[(q * 49 + k) * 8 + h] = s_av[k * 8 + h] * inv;
    }
}

// ---------------- big GEMM, 3-term tf32. grid 128, block 256 ----------------
// block: 64 q x 128 j (jh = half). warp: 32q x 32j (2 m-tiles, 4 n-tiles).
// dyn smem: s_a[64][260] raw fp32 (16640 f) + s_wh[32][136] + s_wl[32][136]
//           = 16640 + 4352 + 4352 floats = 101376 B
__global__ void __launch_bounds__(256) gemm_kernel(
    const float* __restrict__ cell, const float* __restrict__ bi1)
{
    extern __shared__ float sm[];
    float* s_a = sm;
    float* s_wh = sm + 16640;
    float* s_wl = sm + 20992;
    __shared__ float s_cell[128];

    const int t = threadIdx.x;
    const int qb = (blockIdx.x >> 1) * 64;
    const int jh = (blockIdx.x & 1) * 128;
    const int lane = t & 31, w = t >> 5;
    const int r = lane >> 2, cl = lane & 3;
    const int warpM = w >> 2, warpJ = w & 3;      // 2 x 4
    const int bq = t >> 2, hh = (t & 3) * 2;      // A-build: 64q x 4 head-pairs

    if (t < 128) s_cell[t] = cell[qb * 2 + t];

    float cfrag[2][4][4];
#pragma unroll
    for (int mt = 0; mt < 2; mt++)
#pragma unroll
        for (int nt = 0; nt < 4; nt++)
#pragma unroll
            for (int i = 0; i < 4; i++) cfrag[mt][nt][i] = 0.f;

    for (int k = 0; k < 49; k++) {
        __syncthreads();
        { // build A raw fp32: s_a[q][c] = fv[pix][c] * attn[q][k][c/32]
            int pix = g_kidx[(qb + bq) * 49 + k];
            const float4* frbase = (const float4*)(g_fv + (pix < 0 ? 0 : pix) * 256);
#pragma unroll
            for (int hx = hh; hx < hh + 2; hx++) {
                float aw = g_attn[((qb + bq) * 49 + k) * 8 + hx];
                if (pix < 0) aw = 0.f;
                const float4* fr = frbase + hx * 8;
                float* dst = s_a + bq * 260 + hx * 32;
#pragma unroll
                for (int i = 0; i < 8; i++) {
                    float4 v = fr[i];
                    float4 o;
                    o.x = v.x * aw; o.y = v.y * aw; o.z = v.z * aw; o.w = v.w * aw;
                    *(float4*)(dst + i * 4) = o;
                }
            }
        }
        for (int sub = 0; sub < 8; sub++) {
            __syncthreads();
            { // stage W hi+lo: rows c=0..31 (global k*256+sub*32+c), cols jh..jh+127
                const int rowg = k * 256 + sub * 32;
#pragma unroll
                for (int i = 0; i < 4; i++) {
                    int fi = t + i * 256;
                    int c = fi >> 5, jf = fi & 31;
                    ((float4*)(s_wh + c * 136))[jf] =
                        ((const float4*)(g_Wi1T + (rowg + c) * 256 + jh))[jf];
                    ((float4*)(s_wl + c * 136))[jf] =
                        ((const float4*)(g_Wi1Tlo + (rowg + c) * 256 + jh))[jf];
                }
            }
            __syncthreads();
#pragma unroll
            for (int ks = 0; ks < 4; ks++) {
                int c0 = ks * 8;
                unsigned afh[2][4], afl[2][4];
#pragma unroll
                for (int mt = 0; mt < 2; mt++) {
                    int row = warpM * 32 + mt * 16 + r;
                    float a0 = s_a[row * 260 + c0 + cl];
                    float a1 = s_a[(row + 8) * 260 + c0 + cl];
                    float a2 = s_a[row * 260 + c0 + cl + 4];
                    float a3 = s_a[(row + 8) * 260 + c0 + cl + 4];
                    float h0 = totf32(a0), h1 = totf32(a1), h2 = totf32(a2), h3 = totf32(a3);
                    afh[mt][0] = __float_as_uint(h0); afh[mt][1] = __float_as_uint(h1);
                    afh[mt][2] = __float_as_uint(h2); afh[mt][3] = __float_as_uint(h3);
                    afl[mt][0] = __float_as_uint(totf32(a0 - h0));
                    afl[mt][1] = __float_as_uint(totf32(a1 - h1));
                    afl[mt][2] = __float_as_uint(totf32(a2 - h2));
                    afl[mt][3] = __float_as_uint(totf32(a3 - h3));
                }
#pragma unroll
                for (int nt = 0; nt < 4; nt++) {
                    int jc = warpJ * 32 + nt * 8 + r;
                    unsigned bh[2] = {__float_as_uint(s_wh[(c0 + cl) * 136 + jc]),
                                      __float_as_uint(s_wh[(c0 + cl + 4) * 136 + jc])};
                    unsigned bl[2] = {__float_as_uint(s_wl[(c0 + cl) * 136 + jc]),
                                      __float_as_uint(s_wl[(c0 + cl + 4) * 136 + jc])};
#pragma unroll
                    for (int mt = 0; mt < 2; mt++) {
                        mma_tf32(cfrag[mt][nt], afh[mt], bh);
                        mma_tf32(cfrag[mt][nt], afl[mt], bh);
                        mma_tf32(cfrag[mt][nt], afh[mt], bl);
                    }
                }
            }
        }
    }

    // epilogue: h = relu(acc + bi1 + wc0*ry + wc1*rx) -> g_hidden
#pragma unroll
    for (int nt = 0; nt < 4; nt++) {
        int jl = warpJ * 32 + nt * 8 + 2 * cl;
        int jg = jh + jl;
        float b0 = bi1[jg], b1 = bi1[jg + 1];
        float w00 = g_Wi1T[12544 * 256 + jg] + g_Wi1Tlo[12544 * 256 + jg];
        float w01 = g_Wi1T[12544 * 256 + jg + 1] + g_Wi1Tlo[12544 * 256 + jg + 1];
        float w10 = g_Wi1T[12545 * 256 + jg] + g_Wi1Tlo[12545 * 256 + jg];
        float w11 = g_Wi1T[12545 * 256 + jg + 1] + g_Wi1Tlo[12545 * 256 + jg + 1];
#pragma unroll
        for (int mt = 0; mt < 2; mt++) {
#pragma unroll
            for (int half = 0; half < 2; half++) {
                int q = warpM * 32 + mt * 16 + r + half * 8;
                float ry = s_cell[q * 2 + 0] * 64.f, rx = s_cell[q * 2 + 1] * 64.f;
                float v0 = cfrag[mt][nt][half * 2 + 0] + b0 + w00 * ry + w10 * rx;
                float v1 = cfrag[mt][nt][half * 2 + 1] + b1 + w01 * ry + w11 * rx;
                g_hidden[(qb + q) * 256 + jg] = fmaxf(v0, 0.f);
                g_hidden[(qb + q) * 256 + jg + 1] = fmaxf(v1, 0.f);
            }
        }
    }
}

// ---------------- final MLP 256->3 + skip. grid 128, block 128 --------------
__global__ void __launch_bounds__(128) fin_kernel(
    const float* __restrict__ Wi2, const float* __restrict__ bi2,
    float* __restrict__ out)
{
    __shared__ float s_h[32 * 260];
    __shared__ float s_w2[768];
    const int t = threadIdx.x;
    const int qb = blockIdx.x * 32;
    const float4* src = (const float4*)(g_hidden + qb * 256);
#pragma unroll
    for (int i = 0; i < 16; i++) {
        int fi = t + i * 128;
        int q = fi >> 6, jf = fi & 63;
        ((float4*)(s_h + q * 260))[jf] = src[fi];
    }
    for (int i = t; i < 768; i += 128) s_w2[i] = Wi2[i];
    __syncthreads();
    if (t < 96) {
        int q = t / 3, c = t % 3;
        float s = 0.f;
        for (int j = 0; j < 256; j++) s += s_h[q * 260 + j] * s_w2[c * 256 + j];
        out[(qb + q) * 3 + c] = s + bi2[c] + g_skipv[(qb + q) * 3 + c];
    }
}

// ---------------- host ------------------------------------------------------
extern "C" void kernel_launch(void* const* d_in, const int* in_sizes, int n_in,
                              void* d_out, int out_size)
{
    const float* inp   = (const float*)d_in[0];
    const float* coord = (const float*)d_in[1];
    const float* cell  = (const float*)d_in[2];
    const float* W_enc = (const float*)d_in[3];
    const float* b_enc = (const float*)d_in[4];
    const float* W_ch  = (const float*)d_in[5];
    const float* b_ch  = (const float*)d_in[6];
    const float* W_q   = (const float*)d_in[7];
    const float* b_q   = (const float*)d_in[8];
    const float* W_k   = (const float*)d_in[9];
    const float* b_k   = (const float*)d_in[10];
    const float* W_v   = (const float*)d_in[11];
    const float* b_v   = (const float*)d_in[12];
    const float* W_off1= (const float*)d_in[13];
    const float* b_off1= (const float*)d_in[14];
    const float* ln_g  = (const float*)d_in[15];
    const float* ln_b  = (const float*)d_in[16];
    const float* W_off2= (const float*)d_in[17];
    const float* Wc1   = (const float*)d_in[18];
    const float* bc1   = (const float*)d_in[19];
    const float* Wc2   = (const float*)d_in[20];
    const float* bc2   = (const float*)d_in[21];
    const float* Wi1   = (const float*)d_in[22];
    const float* bi1   = (const float*)d_in[23];
    const float* Wi2   = (const float*)d_in[24];
    const float* bi2   = (const float*)d_in[25];
    float* out = (float*)d_out;

    void* p;
    cudaGetSymbolAddress(&p, g_enc);     float* enc = (float*)p;
    cudaGetSymbolAddress(&p, g_feat);    float* feat = (float*)p;
    cudaGetSymbolAddress(&p, g_fq);      float* fq = (float*)p;
    cudaGetSymbolAddress(&p, g_fk);      float* fk = (float*)p;
    cudaGetSymbolAddress(&p, g_fv);      float* fv = (float*)p;
    cudaGetSymbolAddress(&p, g_off1);    float* off1 = (float*)p;
    cudaGetSymbolAddress(&p, g_act);     float* act = (float*)p;
    cudaGetSymbolAddress(&p, g_offmap);  float* offmap = (float*)p;
    cudaGetSymbolAddress(&p, g_Wi1T);    float* wi1t = (float*)p;
    cudaGetSymbolAddress(&p, g_Wi1Tlo);  float* wi1tlo = (float*)p;
    cudaGetSymbolAddress(&p, g_Wc1T);    float* wc1t = (float*)p;
    cudaGetSymbolAddress(&p, g_Wc2T);    float* wc2t = (float*)p;
    cudaGetSymbolAddress(&p, g_WchTh);   float* wchth = (float*)p;
    cudaGetSymbolAddress(&p, g_WchTl);   float* wchtl = (float*)p;
    cudaGetSymbolAddress(&p, g_WqTh);    float* wqth = (float*)p;
    cudaGetSymbolAddress(&p, g_WqTl);    float* wqtl = (float*)p;
    cudaGetSymbolAddress(&p, g_WkTh);    float* wkth = (float*)p;
    cudaGetSymbolAddress(&p, g_WkTl);    float* wktl = (float*)p;
    cudaGetSymbolAddress(&p, g_WvTh);    float* wvth = (float*)p;
    cudaGetSymbolAddress(&p, g_WvTl);    float* wvtl = (float*)p;

    dim3 tb(32, 8);
    transpose_kernel<<<dim3(393, 8), tb>>>(Wi1, wi1t, wi1tlo, 256, 12546);
    transpose_kernel<<<dim3(4, 8), tb>>>(Wc1, wc1t, nullptr, 256, 98);
    transpose_kernel<<<dim3(8, 2), tb>>>(Wc2, wc2t, nullptr, 49, 256);
    wtrans_kernel<<<9 * 64, 256>>>(W_ch, wchth, wchtl, 64);
    wtrans_kernel<<<9 * 256, 256>>>(W_q, wqth, wqtl, 256);
    wtrans_kernel<<<9 * 256, 256>>>(W_k, wkth, wktl, 256);
    wtrans_kernel<<<9 * 256, 256>>>(W_v, wvth, wvtl, 256);

    conv3x3_kernel<3, 64, true><<<dim3(4, 4, 4), 128>>>(inp, W_enc, b_enc, enc);

    cudaFuncSetAttribute(convmma_kernel<64, false>, cudaFuncAttributeMaxDynamicSharedMemorySize, 56448);
    cudaFuncSetAttribute(convmma_kernel<256, true>, cudaFuncAttributeMaxDynamicSharedMemorySize, 56448);
    convmma_kernel<64, false><<<dim3(32, 4), 256, 56448>>>(enc, wchth, wchtl, b_ch, feat);
    convmma_kernel<256, true><<<dim3(32, 4), 256, 56448>>>(feat, wqth, wqtl, b_q, fq);
    convmma_kernel<256, true><<<dim3(32, 4), 256, 56448>>>(feat, wkth, wktl, b_k, fk);
    convmma_kernel<256, true><<<dim3(32, 4), 256, 56448>>>(feat, wvth, wvtl, b_v, fv);

    conv5x5g_kernel<<<dim3(4, 4, 8), 256>>>(feat, W_off1, b_off1, off1);
    ln_gelu_kernel<<<512, 256>>>(off1, ln_g, ln_b, act);
    conv1x1_kernel<<<128, 128>>>(act, W_off2, offmap);
    qprep_kernel<<<4096, 256>>>(coord, inp, bc1, bc2);

    cudaFuncSetAttribute(gemm_kernel, cudaFuncAttributeMaxDynamicSharedMemorySize, 101376);
    gemm_kernel<<<128, 256, 101376>>>(cell, bi1);
    fin_kernel<<<128, 128>>>(Wi2, bi2, out);
}

// round 11
// speedup vs baseline: 1.0517x; 1.0517x over previous
#include <cuda_runtime.h>
#include <math.h>

#define HW 4096

__device__ float g_enc[64 * HW];
__device__ float g_feat[256 * HW];
__device__ float g_fq[HW * 256];
__device__ float g_fk[HW * 256];
__device__ float g_fv[HW * 256];
__device__ float g_off1[HW * 256];
__device__ float g_act[HW * 256];
__device__ float g_offmap[HW * 98];
__device__ float g_attn[4096 * 49 * 8];
__device__ int   g_kidx[4096 * 49];
__device__ float g_skipv[4096 * 3];
__device__ float g_hidden[4096 * 256];
__device__ float g_Wi1T[12546 * 256];
__device__ float g_Wi1Tlo[12546 * 256];
__device__ float g_Wc1T[98 * 256];
__device__ float g_Wc2T[256 * 49];
// conv weights transformed to [tap][ci][co], tf32 hi/lo
__device__ float g_WchTh[9 * 64 * 256],  g_WchTl[9 * 64 * 256];
__device__ float g_WqTh[9 * 256 * 256],  g_WqTl[9 * 256 * 256];
__device__ float g_WkTh[9 * 256 * 256],  g_WkTl[9 * 256 * 256];
__device__ float g_WvTh[9 * 256 * 256],  g_WvTl[9 * 256 * 256];

__device__ __forceinline__ float totf32(float x) {
    float r; asm("cvt.rna.tf32.f32 %0, %1;" : "=f"(r) : "f"(x)); return r;
}
__device__ __forceinline__ void mma_tf32(float* c, const unsigned* a, const unsigned* b) {
    asm volatile("mma.sync.aligned.m16n8k8.row.col.f32.tf32.tf32.f32 "
        "{%0,%1,%2,%3}, {%4,%5,%6,%7}, {%8,%9}, {%0,%1,%2,%3};"
        : "+f"(c[0]), "+f"(c[1]), "+f"(c[2]), "+f"(c[3])
        : "r"(a[0]), "r"(a[1]), "r"(a[2]), "r"(a[3]), "r"(b[0]), "r"(b[1]));
}

// ---------------- transpose + optional tf32 hi/lo split ---------------------
__global__ void transpose_kernel(const float* __restrict__ src, float* __restrict__ dst,
                                 float* __restrict__ dst_lo, int rows, int cols)
{
    __shared__ float tile[32][33];
    int c0 = blockIdx.x * 32, r0 = blockIdx.y * 32;
    int tx = threadIdx.x, ty = threadIdx.y;
#pragma unroll
    for (int i = 0; i < 32; i += 8) {
        int r = r0 + ty + i, c = c0 + tx;
        tile[ty + i][tx] = (r < rows && c < cols) ? src[r * cols + c] : 0.f;
    }
    __syncthreads();
#pragma unroll
    for (int i = 0; i < 32; i += 8) {
        int r = c0 + ty + i, c = r0 + tx;
        if (r < cols && c < rows) {
            float v = tile[tx][ty + i];
            if (dst_lo) {
                float hi = totf32(v);
                dst[r * rows + c] = hi;
                dst_lo[r * rows + c] = totf32(v - hi);
            } else {
                dst[r * rows + c] = v;
            }
        }
    }
}

// ---------------- conv weight transform: W[co][ci][tap] -> [tap][ci][co] hi/lo
__global__ void wtrans_kernel(const float* __restrict__ W, float* __restrict__ Th,
                              float* __restrict__ Tl, int CIN)
{
    int tap = blockIdx.x / CIN, ci = blockIdx.x % CIN, co = threadIdx.x;
    float v = W[co * CIN * 9 + ci * 9 + tap];
    float hi = totf32(v);
    Th[(tap * CIN + ci) * 256 + co] = hi;
    Tl[(tap * CIN + ci) * 256 + co] = totf32(v - hi);
}

// ---------------- 3x3 conv via tf32 mma, 3-term split -----------------------
// grid (32 strips, COUT/64), block 256 (8 warps). Strip = image rows 2s,2s+1.
// dyn smem: s_feat[4][66][36] (9504 f) + s_wh[32][72] + s_wl[32][72] = 56448 B
template <int CIN, bool PIXMAJOR>
__global__ void __launch_bounds__(256) convmma_kernel(
    const float* __restrict__ in, const float* __restrict__ Th,
    const float* __restrict__ Tl, const float* __restrict__ B,
    float* __restrict__ out)
{
    extern __shared__ float smx[];
    float* s_feat = smx;           // [(ry*66+h)*36 + ci]
    float* s_wh = smx + 9504;      // [ci][72]
    float* s_wl = smx + 11808;

    const int t = threadIdx.x;
    const int s = blockIdx.x;            // strip
    const int cobase = blockIdx.y * 64;
    const int w = t >> 5, lane = t & 31;
    const int r = lane >> 2, cl = lane & 3;
    const int wrow = w >> 2;             // 0/1: which image row of strip
    const int x0 = (w & 3) * 16;

    float cfrag[8][4];
#pragma unroll
    for (int nt = 0; nt < 8; nt++)
#pragma unroll
        for (int i = 0; i < 4; i++) cfrag[nt][i] = 0.f;

    for (int cb = 0; cb < CIN; cb += 32) {
        __syncthreads();
        // stage feat strip rows 2s-1..2s+2 with x halo, 32 ci
        for (int i = t; i < 4 * 66 * 32; i += 256) {
            int tmp = i / 66, h = i - tmp * 66;
            int ci = tmp & 31, ry = tmp >> 5;
            int row = 2 * s - 1 + ry, x = h - 1;
            float v = 0.f;
            if ((unsigned)row < 64u && (unsigned)x < 64u)
                v = in[(cb + ci) * HW + row * 64 + x];
            s_feat[(ry * 66 + h) * 36 + ci] = v;
        }
#pragma unroll
        for (int tap = 0; tap < 9; tap++) {
            const int dy = tap / 3, dx = tap % 3;
            __syncthreads();
            { // stage weights [32 ci][64 co] hi+lo
                const float4* sh = (const float4*)(Th + (tap * CIN + cb) * 256 + cobase);
                const float4* sl = (const float4*)(Tl + (tap * CIN + cb) * 256 + cobase);
#pragma unroll
                for (int i = 0; i < 2; i++) {
                    int fi = t + i * 256;
                    int ci = fi >> 4, co4 = fi & 15;
                    ((float4*)(s_wh + ci * 72))[co4] = sh[ci * 64 + co4];
                    ((float4*)(s_wl + ci * 72))[co4] = sl[ci * 64 + co4];
                }
            }
            __syncthreads();
            const int rb = (wrow + dy) * 66 + x0 + dx;
#pragma unroll
            for (int ks = 0; ks < 4; ks++) {
                int c0 = ks * 8;
                float a0 = s_feat[(rb + r) * 36 + c0 + cl];
                float a1 = s_feat[(rb + r + 8) * 36 + c0 + cl];
                float a2 = s_feat[(rb + r) * 36 + c0 + cl + 4];
                float a3 = s_feat[(rb + r + 8) * 36 + c0 + cl + 4];
                float h0 = totf32(a0), h1 = totf32(a1), h2 = totf32(a2), h3 = totf32(a3);
                unsigned ah[4] = {__float_as_uint(h0), __float_as_uint(h1),
                                  __float_as_uint(h2), __float_as_uint(h3)};
                unsigned al[4] = {__float_as_uint(totf32(a0 - h0)), __float_as_uint(totf32(a1 - h1)),
                                  __float_as_uint(totf32(a2 - h2)), __float_as_uint(totf32(a3 - h3))};
#pragma unroll
                for (int nt = 0; nt < 8; nt++) {
                    int co = nt * 8 + r;
                    unsigned bh[2] = {__float_as_uint(s_wh[(c0 + cl) * 72 + co]),
                                      __float_as_uint(s_wh[(c0 + cl + 4) * 72 + co])};
                    unsigned bl[2] = {__float_as_uint(s_wl[(c0 + cl) * 72 + co]),
                                      __float_as_uint(s_wl[(c0 + cl + 4) * 72 + co])};
                    mma_tf32(cfrag[nt], ah, bh);
                    mma_tf32(cfrag[nt], al, bh);
                    mma_tf32(cfrag[nt], ah, bl);
                }
            }
        }
    }
    // store: row m of tile -> pixel (2s+wrow)*64 + x0+m ; col -> cobase+...
    const int pixrow = (2 * s + wrow) * 64 + x0;
#pragma unroll
    for (int nt = 0; nt < 8; nt++) {
#pragma unroll
        for (int i = 0; i < 4; i++) {
            int m = r + (i >> 1) * 8;
            int co = cobase + nt * 8 + 2 * cl + (i & 1);
            float v = cfrag[nt][i] + B[co];
            if (PIXMAJOR) out[(pixrow + m) * 256 + co] = v;
            else out[co * HW + pixrow + m] = v;
        }
    }
}

// ---------------- scalar 3x3 conv (enc only). grid(4,4,COUT/16), block 128 --
template <int CIN, int COUT, bool RELU>
__global__ void __launch_bounds__(128) conv3x3_kernel(
    const float* __restrict__ in, const float* __restrict__ W,
    const float* __restrict__ B, float* __restrict__ out)
{
    __shared__ float s_in[18 * 18];
    __shared__ float s_w[16 * 9];
    const int tid = threadIdx.x;
    const int cog = tid >> 6, qid = tid & 63;
    const int qy = qid >> 3, qx = qid & 7;
    const int ty0 = blockIdx.y * 16, tx0 = blockIdx.x * 16;
    const int cobase = blockIdx.z * 16;

    int l_src[3]; bool l_ok[3];
#pragma unroll
    for (int t = 0; t < 3; t++) {
        int i = tid + t * 128; l_ok[t] = false; l_src[t] = 0;
        if (i < 324) {
            int r = i / 18, c = i % 18;
            int y = ty0 + r - 1, x = tx0 + c - 1;
            l_ok[t] = (y >= 0 && y < 64 && x >= 0 && x < 64);
            l_src[t] = y * 64 + x;
        }
    }
    float acc[2][2][8];
#pragma unroll
    for (int a = 0; a < 2; a++)
#pragma unroll
        for (int b = 0; b < 2; b++)
#pragma unroll
            for (int j = 0; j < 8; j++) acc[a][b][j] = 0.f;

    for (int ci = 0; ci < CIN; ci++) {
        const float* inc = in + ci * HW;
#pragma unroll
        for (int t = 0; t < 3; t++) {
            int i = tid + t * 128;
            if (i < 324) s_in[i] = l_ok[t] ? inc[l_src[t]] : 0.f;
        }
#pragma unroll
        for (int i = tid; i < 144; i += 128)
            s_w[i] = W[((cobase + i / 9) * CIN + ci) * 9 + i % 9];
        __syncthreads();
        float p[4][4];
#pragma unroll
        for (int r = 0; r < 4; r++)
#pragma unroll
            for (int c = 0; c < 4; c++)
                p[r][c] = s_in[(qy * 2 + r) * 18 + qx * 2 + c];
#pragma unroll
        for (int j = 0; j < 8; j++) {
            const float* w = &s_w[(cog * 8 + j) * 9];
#pragma unroll
            for (int oy = 0; oy < 2; oy++)
#pragma unroll
                for (int ox = 0; ox < 2; ox++)
                    acc[oy][ox][j] += w[0]*p[oy][ox]   + w[1]*p[oy][ox+1]   + w[2]*p[oy][ox+2]
                                    + w[3]*p[oy+1][ox] + w[4]*p[oy+1][ox+1] + w[5]*p[oy+1][ox+2]
                                    + w[6]*p[oy+2][ox] + w[7]*p[oy+2][ox+1] + w[8]*p[oy+2][ox+2];
        }
        __syncthreads();
    }
#pragma unroll
    for (int oy = 0; oy < 2; oy++)
#pragma unroll
        for (int ox = 0; ox < 2; ox++) {
            int pix = (ty0 + qy * 2 + oy) * 64 + tx0 + qx * 2 + ox;
#pragma unroll
            for (int j = 0; j < 8; j++) {
                int co = cobase + cog * 8 + j;
                float v = acc[oy][ox][j] + B[co];
                if (RELU) v = fmaxf(v, 0.f);
                out[co * HW + pix] = v;
            }
        }
}

// ---------------- grouped 5x5 pad2, groups 8. grid(4,4,8), block 256 --------
__global__ void __launch_bounds__(256) conv5x5g_kernel(
    const float* __restrict__ in, const float* __restrict__ W,
    const float* __restrict__ B, float* __restrict__ out)
{
    __shared__ float s_in[20 * 20];
    __shared__ float s_w[32 * 25];
    const int tid = threadIdx.x;
    const int cog = tid >> 6, qid = tid & 63;
    const int qy = qid >> 3, qx = qid & 7;
    const int ty0 = blockIdx.y * 16, tx0 = blockIdx.x * 16;
    const int grp = blockIdx.z;

    int l_src[2]; bool l_ok[2];
#pragma unroll
    for (int t = 0; t < 2; t++) {
        int i = tid + t * 256; l_ok[t] = false; l_src[t] = 0;
        if (i < 400) {
            int r = i / 20, c = i % 20;
            int y = ty0 + r - 2, x = tx0 + c - 2;
            l_ok[t] = (y >= 0 && y < 64 && x >= 0 && x < 64);
            l_src[t] = y * 64 + x;
        }
    }
    float acc[2][2][8];
#pragma unroll
    for (int a = 0; a < 2; a++)
#pragma unroll
        for (int b = 0; b < 2; b++)
#pragma unroll
            for (int j = 0; j < 8; j++) acc[a][b][j] = 0.f;

    for (int cil = 0; cil < 32; cil++) {
        const float* inc = in + (grp * 32 + cil) * HW;
#pragma unroll
        for (int t = 0; t < 2; t++) {
            int i = tid + t * 256;
            if (i < 400) s_in[i] = l_ok[t] ? inc[l_src[t]] : 0.f;
        }
        for (int i = tid; i < 800; i += 256)
            s_w[i] = W[((grp * 32 + i / 25) * 32 + cil) * 25 + i % 25];
        __syncthreads();
        float p[6][6];
#pragma unroll
        for (int r = 0; r < 6; r++)
#pragma unroll
            for (int c = 0; c < 6; c++)
                p[r][c] = s_in[(qy * 2 + r) * 20 + qx * 2 + c];
#pragma unroll
        for (int j = 0; j < 8; j++) {
            const float* w = &s_w[(cog * 8 + j) * 25];
#pragma unroll
            for (int oy = 0; oy < 2; oy++)
#pragma unroll
                for (int ox = 0; ox < 2; ox++) {
                    float s = 0.f;
#pragma unroll
                    for (int ky = 0; ky < 5; ky++)
#pragma unroll
                        for (int kx = 0; kx < 5; kx++)
                            s += w[ky * 5 + kx] * p[oy + ky][ox + kx];
                    acc[oy][ox][j] += s;
                }
        }
        __syncthreads();
    }
#pragma unroll
    for (int oy = 0; oy < 2; oy++)
#pragma unroll
        for (int ox = 0; ox < 2; ox++) {
            int pix = (ty0 + qy * 2 + oy) * 64 + tx0 + qx * 2 + ox;
#pragma unroll
            for (int j = 0; j < 8; j++) {
                int co = grp * 32 + cog * 8 + j;
                out[pix * 256 + co] = acc[oy][ox][j] + B[co];
            }
        }
}

// ---------------- LayerNorm + exact GELU. grid 512, block 256 ---------------
__global__ void __launch_bounds__(256) ln_gelu_kernel(
    const float* __restrict__ in, const float* __restrict__ gam,
    const float* __restrict__ bet, float* __restrict__ out)
{
    const int lane = threadIdx.x & 31, wid = threadIdx.x >> 5;
    const int pix = blockIdx.x * 8 + wid;
    float x[8];
#pragma unroll
    for (int i = 0; i < 8; i++) x[i] = in[pix * 256 + i * 32 + lane];
    float s = 0.f;
#pragma unroll
    for (int i = 0; i < 8; i++) s += x[i];
#pragma unroll
    for (int o = 16; o; o >>= 1) s += __shfl_xor_sync(0xffffffffu, s, o);
    float mu = s * (1.f / 256.f);
    float d = 0.f;
#pragma unroll
    for (int i = 0; i < 8; i++) { float t = x[i] - mu; d += t * t; }
#pragma unroll
    for (int o = 16; o; o >>= 1) d += __shfl_xor_sync(0xffffffffu, d, o);
    float inv = rsqrtf(d * (1.f / 256.f) + 1e-5f);
#pragma unroll
    for (int i = 0; i < 8; i++) {
        int c = i * 32 + lane;
        float y = (x[i] - mu) * inv * gam[c] + bet[c];
        out[pix * 256 + c] = 0.5f * y * (1.f + erff(y * 0.70710678118654752f));
    }
}

// ---------------- 1x1 conv 256->98. grid 128, block 128 ---------------------
__global__ void __launch_bounds__(128) conv1x1_kernel(
    const float* __restrict__ act, const float* __restrict__ W2, float* __restrict__ out)
{
    __shared__ float s_act[32 * 256];
    const int tid = threadIdx.x;
    const int pb = blockIdx.x * 32;
    const float4* src = (const float4*)(act + pb * 256);
    float4* dst = (float4*)s_act;
    for (int i = tid; i < 32 * 64; i += 128) dst[i] = src[i];
    __syncthreads();
    if (tid < 98) {
        float acc[32];
#pragma unroll
        for (int p = 0; p < 32; p++) acc[p] = 0.f;
        for (int c = 0; c < 256; c++) {
            float w = W2[tid * 256 + c];
#pragma unroll
            for (int p = 0; p < 32; p++) acc[p] += w * s_act[p * 256 + c];
        }
#pragma unroll
        for (int p = 0; p < 32; p++) out[(pb + p) * 98 + tid] = acc[p];
    }
}

// ---------------- per-query prep. grid 4096, block 256 ----------------------
__global__ void __launch_bounds__(256) qprep_kernel(
    const float* __restrict__ coord, const float* __restrict__ inp,
    const float* __restrict__ bc1, const float* __restrict__ bc2)
{
    __shared__ float s_q[256];
    __shared__ float s_rel[98];
    __shared__ float s_av[49 * 8];
    __shared__ float s_wc[49];
    __shared__ float s_h[256];
    __shared__ int   s_kidx[49];

    const int q = blockIdx.x;
    const int tid = threadIdx.x, lane = tid & 31, wid = tid >> 5;
    const float cy = coord[q * 2 + 0], cx = coord[q * 2 + 1];
    const float gx = ((cx + 1.f) * 64.f - 1.f) * 0.5f;
    const float gy = ((cy + 1.f) * 64.f - 1.f) * 0.5f;

    {
        float x0f = floorf(gx), y0f = floorf(gy);
        int x0 = (int)x0f, y0 = (int)y0f;
        float wx = gx - x0f, wy = gy - y0f;
        float a = 0.f;
#pragma unroll
        for (int t = 0; t < 4; t++) {
            int ix = x0 + (t & 1), iy = y0 + (t >> 1);
            float w = ((t & 1) ? wx : 1.f - wx) * ((t >> 1) ? wy : 1.f - wy);
            bool m = (ix >= 0 && ix < 64 && iy >= 0 && iy < 64);
            int pc = min(max(iy, 0), 63) * 64 + min(max(ix, 0), 63);
            float v = g_fq[pc * 256 + tid];
            a += m ? w * v : 0.f;
        }
        s_q[tid] = a;
    }

    const int ix0 = __float2int_rn(gx), iy0 = __float2int_rn(gy);
    const bool m0 = (ix0 >= 0 && ix0 < 64 && iy0 >= 0 && iy0 < 64);
    const int pix0 = min(max(iy0, 0), 63) * 64 + min(max(ix0, 0), 63);
    const float yb = m0 ? (-1.f + 0.015625f + 0.03125f * (float)iy0) : 0.f;
    const float xb = m0 ? (-1.f + 0.015625f + 0.03125f * (float)ix0) : 0.f;

    if (tid < 49) {
        const int k = tid;
        float o0 = m0 ? g_offmap[pix0 * 98 + 2 * k] : 0.f;
        float o1 = m0 ? g_offmap[pix0 * 98 + 2 * k + 1] : 0.f;
        float sy = yb + (float)(k / 7 - 3) * 0.03125f + tanhf(o0) * (2.f / 63.f);
        float sx = xb + (float)(k % 7 - 3) * 0.03125f + tanhf(o1) * (2.f / 63.f);
        s_rel[2 * k] = (cy - sy) * 64.f;
        s_rel[2 * k + 1] = (cx - sx) * 64.f;
        float gky = ((sy + 1.f) * 64.f - 1.f) * 0.5f;
        float gkx = ((sx + 1.f) * 64.f - 1.f) * 0.5f;
        int iky = __float2int_rn(gky), ikx = __float2int_rn(gkx);
        bool ok = (ikx >= 0 && ikx < 64 && iky >= 0 && iky < 64);
        s_kidx[k] = ok ? iky * 64 + ikx : -1;
        g_kidx[q * 49 + k] = s_kidx[k];
    }
    __syncthreads();

    for (int k = wid; k < 49; k += 8) {
        int pix = s_kidx[k];
        int h = lane >> 2, part = lane & 3;
        float s = 0.f;
        if (pix >= 0) {
            const float* fr = g_fk + pix * 256 + h * 32 + part * 8;
            const float* qr = s_q + h * 32 + part * 8;
#pragma unroll
            for (int i = 0; i < 8; i++) s += fr[i] * qr[i];
        }
        s += __shfl_xor_sync(0xffffffffu, s, 1);
        s += __shfl_xor_sync(0xffffffffu, s, 2);
        if (part == 0) s_av[k * 8 + h] = s * 0.17677669529663687f;
    }

    {
        float h1 = bc1[tid];
        for (int i = 0; i < 98; i++) h1 += g_Wc1T[i * 256 + tid] * s_rel[i];
        s_h[tid] = fmaxf(h1, 0.f);
    }
    __syncthreads();

    if (tid < 49) {
        float w = bc2[tid];
        for (int j = 0; j < 256; j++) w += g_Wc2T[j * 49 + tid] * s_h[j];
        s_wc[tid] = w;
    }
    if (tid >= 64 && tid < 67) {
        const int c = tid - 64;
        float gxc = fminf(fmaxf(gx, 0.f), 63.f), gyc = fminf(fmaxf(gy, 0.f), 63.f);
        float x0f = floorf(gxc), y0f = floorf(gyc);
        int x0 = (int)x0f, y0 = (int)y0f;
        float wx = gxc - x0f, wy = gyc - y0f;
        int x1 = min(x0 + 1, 63), y1 = min(y0 + 1, 63);
        const float* I = inp + c * HW;
        g_skipv[q * 3 + c] = (1.f - wx) * (1.f - wy) * I[y0 * 64 + x0]
                           + wx * (1.f - wy) * I[y0 * 64 + x1]
                           + (1.f - wx) * wy * I[y1 * 64 + x0]
                           + wx * wy * I[y1 * 64 + x1];
    }
    __syncthreads();

    if (tid < 8) {
        const int h = tid;
        float mx = -1e30f;
        for (int k = 0; k < 49; k++) mx = fmaxf(mx, s_wc[k] + s_av[k * 8 + h]);
        float sum = 0.f;
        for (int k = 0; k < 49; k++) {
            float e = expf(s_wc[k] + s_av[k * 8 + h] - mx);
            s_av[k * 8 + h] = e;
            sum += e;
        }
        float inv = 1.f / sum;
        for (int k = 0; k < 49; k++) g_attn[(q * 49 + k) * 8 + h] = s_av[k * 8 + h] * inv;
    }
}

// ---------------- big GEMM, 3-term tf32, pre-split A. grid 128, block 256 ---
// block: 64 q x 128 j (jh = half). warp: 32q x 32j (2 m-tiles, 4 n-tiles).
// dyn smem: s_ah[64][260] + s_al[64][260] + s_wh[32][136] + s_wl[32][136]
//           = (16640*2 + 4352*2) floats = 167936 B
__global__ void __launch_bounds__(256) gemm_kernel(
    const float* __restrict__ cell, const float* __restrict__ bi1)
{
    extern __shared__ float sm[];
    float* s_ah = sm;
    float* s_al = sm + 16640;
    float* s_wh = sm + 33280;
    float* s_wl = sm + 37632;
    __shared__ float s_cell[128];

    const int t = threadIdx.x;
    const int qb = (blockIdx.x >> 1) * 64;
    const int jh = (blockIdx.x & 1) * 128;
    const int lane = t & 31, w = t >> 5;
    const int r = lane >> 2, cl = lane & 3;
    const int warpM = w >> 2, warpJ = w & 3;      // 2 x 4
    const int bq = t >> 2, hh = (t & 3) * 2;      // A-build: 64q x 4 head-pairs

    if (t < 128) s_cell[t] = cell[qb * 2 + t];

    float cfrag[2][4][4];
#pragma unroll
    for (int mt = 0; mt < 2; mt++)
#pragma unroll
        for (int nt = 0; nt < 4; nt++)
#pragma unroll
            for (int i = 0; i < 4; i++) cfrag[mt][nt][i] = 0.f;

    for (int k = 0; k < 49; k++) {
        __syncthreads();
        { // build A pre-split: s_ah/s_al[q][c], a = fv[pix][c]*attn[q][k][c/32]
            int pix = g_kidx[(qb + bq) * 49 + k];
            const float4* frbase = (const float4*)(g_fv + (pix < 0 ? 0 : pix) * 256);
#pragma unroll
            for (int hx = hh; hx < hh + 2; hx++) {
                float aw = g_attn[((qb + bq) * 49 + k) * 8 + hx];
                if (pix < 0) aw = 0.f;
                const float4* fr = frbase + hx * 8;
                float* dh = s_ah + bq * 260 + hx * 32;
                float* dl = s_al + bq * 260 + hx * 32;
#pragma unroll
                for (int i = 0; i < 8; i++) {
                    float4 v = fr[i];
                    float4 p, hi4, lo4;
                    p.x = v.x * aw; p.y = v.y * aw; p.z = v.z * aw; p.w = v.w * aw;
                    hi4.x = totf32(p.x); lo4.x = totf32(p.x - hi4.x);
                    hi4.y = totf32(p.y); lo4.y = totf32(p.y - hi4.y);
                    hi4.z = totf32(p.z); lo4.z = totf32(p.z - hi4.z);
                    hi4.w = totf32(p.w); lo4.w = totf32(p.w - hi4.w);
                    *(float4*)(dh + i * 4) = hi4;
                    *(float4*)(dl + i * 4) = lo4;
                }
            }
        }
        for (int sub = 0; sub < 8; sub++) {
            __syncthreads();
            { // stage W hi+lo: rows c=0..31 (global k*256+sub*32+c), cols jh..jh+127
                const int rowg = k * 256 + sub * 32;
#pragma unroll
                for (int i = 0; i < 4; i++) {
                    int fi = t + i * 256;
                    int c = fi >> 5, jf = fi & 31;
                    ((float4*)(s_wh + c * 136))[jf] =
                        ((const float4*)(g_Wi1T + (rowg + c) * 256 + jh))[jf];
                    ((float4*)(s_wl + c * 136))[jf] =
                        ((const float4*)(g_Wi1Tlo + (rowg + c) * 256 + jh))[jf];
                }
            }
            __syncthreads();
#pragma unroll
            for (int ks = 0; ks < 4; ks++) {
                int cg = sub * 32 + ks * 8;   // FIX (R11): global A column base
                int c0 = ks * 8;              // local W row base (W staged per-sub)
                unsigned afh[2][4], afl[2][4];
#pragma unroll
                for (int mt = 0; mt < 2; mt++) {
                    int row = warpM * 32 + mt * 16 + r;
                    afh[mt][0] = __float_as_uint(s_ah[row * 260 + cg + cl]);
                    afh[mt][1] = __float_as_uint(s_ah[(row + 8) * 260 + cg + cl]);
                    afh[mt][2] = __float_as_uint(s_ah[row * 260 + cg + cl + 4]);
                    afh[mt][3] = __float_as_uint(s_ah[(row + 8) * 260 + cg + cl + 4]);
                    afl[mt][0] = __float_as_uint(s_al[row * 260 + cg + cl]);
                    afl[mt][1] = __float_as_uint(s_al[(row + 8) * 260 + cg + cl]);
                    afl[mt][2] = __float_as_uint(s_al[row * 260 + cg + cl + 4]);
                    afl[mt][3] = __float_as_uint(s_al[(row + 8) * 260 + cg + cl + 4]);
                }
#pragma unroll
                for (int nt = 0; nt < 4; nt++) {
                    int jc = warpJ * 32 + nt * 8 + r;
                    unsigned bh[2] = {__float_as_uint(s_wh[(c0 + cl) * 136 + jc]),
                                      __float_as_uint(s_wh[(c0 + cl + 4) * 136 + jc])};
                    unsigned bl[2] = {__float_as_uint(s_wl[(c0 + cl) * 136 + jc]),
                                      __float_as_uint(s_wl[(c0 + cl + 4) * 136 + jc])};
#pragma unroll
                    for (int mt = 0; mt < 2; mt++) {
                        mma_tf32(cfrag[mt][nt], afh[mt], bh);
                        mma_tf32(cfrag[mt][nt], afl[mt], bh);
                        mma_tf32(cfrag[mt][nt], afh[mt], bl);
                    }
                }
            }
        }
    }

    // epilogue: h = relu(acc + bi1 + wc0*ry + wc1*rx) -> g_hidden
#pragma unroll
    for (int nt = 0; nt < 4; nt++) {
        int jl = warpJ * 32 + nt * 8 + 2 * cl;
        int jg = jh + jl;
        float b0 = bi1[jg], b1 = bi1[jg + 1];
        float w00 = g_Wi1T[12544 * 256 + jg] + g_Wi1Tlo[12544 * 256 + jg];
        float w01 = g_Wi1T[12544 * 256 + jg + 1] + g_Wi1Tlo[12544 * 256 + jg + 1];
        float w10 = g_Wi1T[12545 * 256 + jg] + g_Wi1Tlo[12545 * 256 + jg];
        float w11 = g_Wi1T[12545 * 256 + jg + 1] + g_Wi1Tlo[12545 * 256 + jg + 1];
#pragma unroll
        for (int mt = 0; mt < 2; mt++) {
#pragma unroll
            for (int half = 0; half < 2; half++) {
                int q = warpM * 32 + mt * 16 + r + half * 8;
                float ry = s_cell[q * 2 + 0] * 64.f, rx = s_cell[q * 2 + 1] * 64.f;
                float v0 = cfrag[mt][nt][half * 2 + 0] + b0 + w00 * ry + w10 * rx;
                float v1 = cfrag[mt][nt][half * 2 + 1] + b1 + w01 * ry + w11 * rx;
                g_hidden[(qb + q) * 256 + jg] = fmaxf(v0, 0.f);
                g_hidden[(qb + q) * 256 + jg + 1] = fmaxf(v1, 0.f);
            }
        }
    }
}

// ---------------- final MLP 256->3 + skip. grid 128, block 128 --------------
__global__ void __launch_bounds__(128) fin_kernel(
    const float* __restrict__ Wi2, const float* __restrict__ bi2,
    float* __restrict__ out)
{
    __shared__ float s_h[32 * 260];
    __shared__ float s_w2[768];
    const int t = threadIdx.x;
    const int qb = blockIdx.x * 32;
    const float4* src = (const float4*)(g_hidden + qb * 256);
#pragma unroll
    for (int i = 0; i < 16; i++) {
        int fi = t + i * 128;
        int q = fi >> 6, jf = fi & 63;
        ((float4*)(s_h + q * 260))[jf] = src[fi];
    }
    for (int i = t; i < 768; i += 128) s_w2[i] = Wi2[i];
    __syncthreads();
    if (t < 96) {
        int q = t / 3, c = t % 3;
        float s = 0.f;
        for (int j = 0; j < 256; j++) s += s_h[q * 260 + j] * s_w2[c * 256 + j];
        out[(qb + q) * 3 + c] = s + bi2[c] + g_skipv[(qb + q) * 3 + c];
    }
}

// ---------------- host ------------------------------------------------------
extern "C" void kernel_launch(void* const* d_in, const int* in_sizes, int n_in,
                              void* d_out, int out_size)
{
    const float* inp   = (const float*)d_in[0];
    const float* coord = (const float*)d_in[1];
    const float* cell  = (const float*)d_in[2];
    const float* W_enc = (const float*)d_in[3];
    const float* b_enc = (const float*)d_in[4];
    const float* W_ch  = (const float*)d_in[5];
    const float* b_ch  = (const float*)d_in[6];
    const float* W_q   = (const float*)d_in[7];
    const float* b_q   = (const float*)d_in[8];
    const float* W_k   = (const float*)d_in[9];
    const float* b_k   = (const float*)d_in[10];
    const float* W_v   = (const float*)d_in[11];
    const float* b_v   = (const float*)d_in[12];
    const float* W_off1= (const float*)d_in[13];
    const float* b_off1= (const float*)d_in[14];
    const float* ln_g  = (const float*)d_in[15];
    const float* ln_b  = (const float*)d_in[16];
    const float* W_off2= (const float*)d_in[17];
    const float* Wc1   = (const float*)d_in[18];
    const float* bc1   = (const float*)d_in[19];
    const float* Wc2   = (const float*)d_in[20];
    const float* bc2   = (const float*)d_in[21];
    const float* Wi1   = (const float*)d_in[22];
    const float* bi1   = (const float*)d_in[23];
    const float* Wi2   = (const float*)d_in[24];
    const float* bi2   = (const float*)d_in[25];
    float* out = (float*)d_out;

    void* p;
    cudaGetSymbolAddress(&p, g_enc);     float* enc = (float*)p;
    cudaGetSymbolAddress(&p, g_feat);    float* feat = (float*)p;
    cudaGetSymbolAddress(&p, g_fq);      float* fq = (float*)p;
    cudaGetSymbolAddress(&p, g_fk);      float* fk = (float*)p;
    cudaGetSymbolAddress(&p, g_fv);      float* fv = (float*)p;
    cudaGetSymbolAddress(&p, g_off1);    float* off1 = (float*)p;
    cudaGetSymbolAddress(&p, g_act);     float* act = (float*)p;
    cudaGetSymbolAddress(&p, g_offmap);  float* offmap = (float*)p;
    cudaGetSymbolAddress(&p, g_Wi1T);    float* wi1t = (float*)p;
    cudaGetSymbolAddress(&p, g_Wi1Tlo);  float* wi1tlo = (float*)p;
    cudaGetSymbolAddress(&p, g_Wc1T);    float* wc1t = (float*)p;
    cudaGetSymbolAddress(&p, g_Wc2T);    float* wc2t = (float*)p;
    cudaGetSymbolAddress(&p, g_WchTh);   float* wchth = (float*)p;
    cudaGetSymbolAddress(&p, g_WchTl);   float* wchtl = (float*)p;
    cudaGetSymbolAddress(&p, g_WqTh);    float* wqth = (float*)p;
    cudaGetSymbolAddress(&p, g_WqTl);    float* wqtl = (float*)p;
    cudaGetSymbolAddress(&p, g_WkTh);    float* wkth = (float*)p;
    cudaGetSymbolAddress(&p, g_WkTl);    float* wktl = (float*)p;
    cudaGetSymbolAddress(&p, g_WvTh);    float* wvth = (float*)p;
    cudaGetSymbolAddress(&p, g_WvTl);    float* wvtl = (float*)p;

    cudaFuncSetAttribute(convmma_kernel<64, false>, cudaFuncAttributeMaxDynamicSharedMemorySize, 56448);
    cudaFuncSetAttribute(convmma_kernel<256, true>, cudaFuncAttributeMaxDynamicSharedMemorySize, 56448);
    cudaFuncSetAttribute(gemm_kernel, cudaFuncAttributeMaxDynamicSharedMemorySize, 167936);

    dim3 tb(32, 8);
    // Launch order arranged so launch #6 (ncu -s 5 -c 1) is convmma_q.
    conv3x3_kernel<3, 64, true><<<dim3(4, 4, 4), 128>>>(inp, W_enc, b_enc, enc); // 1
    wtrans_kernel<<<9 * 64, 256>>>(W_ch, wchth, wchtl, 64);                      // 2
    convmma_kernel<64, false><<<dim3(32, 4), 256, 56448>>>(enc, wchth, wchtl, b_ch, feat); // 3
    wtrans_kernel<<<9 * 256, 256>>>(W_q, wqth, wqtl, 256);                       // 4
    wtrans_kernel<<<9 * 256, 256>>>(W_k, wkth, wktl, 256);                       // 5
    convmma_kernel<256, true><<<dim3(32, 4), 256, 56448>>>(feat, wqth, wqtl, b_q, fq); // 6 <- profiled
    wtrans_kernel<<<9 * 256, 256>>>(W_v, wvth, wvtl, 256);                       // 7
    convmma_kernel<256, true><<<dim3(32, 4), 256, 56448>>>(feat, wkth, wktl, b_k, fk); // 8
    convmma_kernel<256, true><<<dim3(32, 4), 256, 56448>>>(feat, wvth, wvtl, b_v, fv); // 9
    transpose_kernel<<<dim3(393, 8), tb>>>(Wi1, wi1t, wi1tlo, 256, 12546);       // 10
    transpose_kernel<<<dim3(4, 8), tb>>>(Wc1, wc1t, nullptr, 256, 98);           // 11
    transpose_kernel<<<dim3(8, 2), tb>>>(Wc2, wc2t, nullptr, 49, 256);           // 12
    conv5x5g_kernel<<<dim3(4, 4, 8), 256>>>(feat, W_off1, b_off1, off1);         // 13
    ln_gelu_kernel<<<512, 256>>>(off1, ln_g, ln_b, act);                         // 14
    conv1x1_kernel<<<128, 128>>>(act, W_off2, offmap);                           // 15
    qprep_kernel<<<4096, 256>>>(coord, inp, bc1, bc2);                           // 16
    gemm_kernel<<<128, 256, 167936>>>(cell, bi1);                                // 17
    fin_kernel<<<128, 128>>>(Wi2, bi2, out);                                     // 18
}

// round 12
// speedup vs baseline: 1.7839x; 1.6963x over previous
#include <cuda_runtime.h>
#include <math.h>

#define HW 4096

__device__ float g_enc[64 * HW];
__device__ float g_feat[256 * HW];
__device__ float g_fq[HW * 256];
__device__ float g_fk[HW * 256];
__device__ float g_fv[HW * 256];
__device__ float g_off1[HW * 256];
__device__ float g_act[HW * 256];
__device__ float g_offmap[HW * 98];
__device__ float g_attn[4096 * 49 * 8];
__device__ int   g_kidx[4096 * 49];
__device__ float g_skipv[4096 * 3];
__device__ float g_hidden[4096 * 256];
__device__ float g_Wi1T[12546 * 256];
__device__ float g_Wc1T[98 * 256];
__device__ float g_Wc2T[256 * 49];
// conv weights transformed to [tap][ci][co], tf32-rounded
__device__ float g_WchT[9 * 64 * 256];
__device__ float g_WqT[9 * 256 * 256];
__device__ float g_WkT[9 * 256 * 256];
__device__ float g_WvT[9 * 256 * 256];

__device__ __forceinline__ float totf32(float x) {
    float r; asm("cvt.rna.tf32.f32 %0, %1;" : "=f"(r) : "f"(x)); return r;
}
__device__ __forceinline__ void mma_tf32(float* c, const unsigned* a, const unsigned* b) {
    asm volatile("mma.sync.aligned.m16n8k8.row.col.f32.tf32.tf32.f32 "
        "{%0,%1,%2,%3}, {%4,%5,%6,%7}, {%8,%9}, {%0,%1,%2,%3};"
        : "+f"(c[0]), "+f"(c[1]), "+f"(c[2]), "+f"(c[3])
        : "r"(a[0]), "r"(a[1]), "r"(a[2]), "r"(a[3]), "r"(b[0]), "r"(b[1]));
}

// ---------------- transpose (optional tf32 rounding) ------------------------
__global__ void transpose_kernel(const float* __restrict__ src, float* __restrict__ dst,
                                 int rows, int cols, int tf32)
{
    __shared__ float tile[32][33];
    int c0 = blockIdx.x * 32, r0 = blockIdx.y * 32;
    int tx = threadIdx.x, ty = threadIdx.y;
#pragma unroll
    for (int i = 0; i < 32; i += 8) {
        int r = r0 + ty + i, c = c0 + tx;
        tile[ty + i][tx] = (r < rows && c < cols) ? src[r * cols + c] : 0.f;
    }
    __syncthreads();
#pragma unroll
    for (int i = 0; i < 32; i += 8) {
        int r = c0 + ty + i, c = r0 + tx;
        if (r < cols && c < rows) {
            float v = tile[tx][ty + i];
            if (tf32) v = totf32(v);
            dst[r * rows + c] = v;
        }
    }
}

// ---------------- conv weight transform (4 weight sets in one launch) -------
// W[co][ci][tap] -> T[tap][ci][co] (tf32-rounded). grid (9*256, 4), block 256.
__global__ void wtrans_all_kernel(
    const float* __restrict__ Wch, const float* __restrict__ Wq,
    const float* __restrict__ Wk, const float* __restrict__ Wv,
    float* __restrict__ Tch, float* __restrict__ Tq,
    float* __restrict__ Tk, float* __restrict__ Tv)
{
    const int which = blockIdx.y;
    const int CIN = (which == 0) ? 64 : 256;
    int tap = blockIdx.x / 256, ci = blockIdx.x % 256, co = threadIdx.x;
    if (ci >= CIN) return;
    const float* W = (which == 0) ? Wch : (which == 1) ? Wq : (which == 2) ? Wk : Wv;
    float* T = (which == 0) ? Tch : (which == 1) ? Tq : (which == 2) ? Tk : Tv;
    T[(tap * CIN + ci) * 256 + co] = totf32(W[co * CIN * 9 + ci * 9 + tap]);
}

// ---------------- 3x3 conv via tf32 mma (1-term), ch variant ----------------
// grid (32 strips, 4), block 256. dyn smem: feat 9504 + w 2304 = 47232 B
template <int CIN>
__global__ void __launch_bounds__(256) convmma_ch_kernel(
    const float* __restrict__ in, const float* __restrict__ T,
    const float* __restrict__ B, float* __restrict__ out)
{
    extern __shared__ float smx[];
    float* s_feat = smx;           // [(ry*66+h)*36 + ci]
    float* s_w = smx + 9504;       // [ci][72]

    const int t = threadIdx.x;
    const int s = blockIdx.x;
    const int cobase = blockIdx.y * 64;
    const int w = t >> 5, lane = t & 31;
    const int r = lane >> 2, cl = lane & 3;
    const int wrow = w >> 2;
    const int x0 = (w & 3) * 16;

    float cfrag[8][4];
#pragma unroll
    for (int nt = 0; nt < 8; nt++)
#pragma unroll
        for (int i = 0; i < 4; i++) cfrag[nt][i] = 0.f;

    for (int cb = 0; cb < CIN; cb += 32) {
        __syncthreads();
        for (int i = t; i < 4 * 66 * 32; i += 256) {
            int tmp = i / 66, h = i - tmp * 66;
            int ci = tmp & 31, ry = tmp >> 5;
            int row = 2 * s - 1 + ry, x = h - 1;
            float v = 0.f;
            if ((unsigned)row < 64u && (unsigned)x < 64u)
                v = in[(cb + ci) * HW + row * 64 + x];
            s_feat[(ry * 66 + h) * 36 + ci] = v;
        }
#pragma unroll
        for (int tap = 0; tap < 9; tap++) {
            const int dy = tap / 3, dx = tap % 3;
            __syncthreads();
            {
                const float4* sh = (const float4*)(T + (tap * CIN + cb) * 256 + cobase);
                for (int i = t; i < 512; i += 256) {
                    int ci = i >> 4, co4 = i & 15;
                    ((float4*)(s_w + ci * 72))[co4] = sh[ci * 64 + co4];
                }
            }
            __syncthreads();
            const int rb = (wrow + dy) * 66 + x0 + dx;
#pragma unroll
            for (int ks = 0; ks < 4; ks++) {
                int c0 = ks * 8;
                unsigned ah[4];
                ah[0] = __float_as_uint(totf32(s_feat[(rb + r) * 36 + c0 + cl]));
                ah[1] = __float_as_uint(totf32(s_feat[(rb + r + 8) * 36 + c0 + cl]));
                ah[2] = __float_as_uint(totf32(s_feat[(rb + r) * 36 + c0 + cl + 4]));
                ah[3] = __float_as_uint(totf32(s_feat[(rb + r + 8) * 36 + c0 + cl + 4]));
#pragma unroll
                for (int nt = 0; nt < 8; nt++) {
                    int co = nt * 8 + r;
                    unsigned bh[2] = {__float_as_uint(s_w[(c0 + cl) * 72 + co]),
                                      __float_as_uint(s_w[(c0 + cl + 4) * 72 + co])};
                    mma_tf32(cfrag[nt], ah, bh);
                }
            }
        }
    }
    const int pixrow = (2 * s + wrow) * 64 + x0;
#pragma unroll
    for (int nt = 0; nt < 8; nt++)
#pragma unroll
        for (int i = 0; i < 4; i++) {
            int m = r + (i >> 1) * 8;
            int co = cobase + nt * 8 + 2 * cl + (i & 1);
            out[co * HW + pixrow + m] = cfrag[nt][i] + B[co];   // chan-major
        }
}

// ---------------- fused q/k/v 3x3 conv via tf32 mma (1-term) ----------------
// grid (32 strips, 4), block 256. dyn smem: feat 9504 + 3*2304 = 65664 B
__global__ void __launch_bounds__(256) convmma_qkv_kernel(
    const float* __restrict__ in,
    const float* __restrict__ Tq, const float* __restrict__ Tk, const float* __restrict__ Tv,
    const float* __restrict__ Bq, const float* __restrict__ Bk, const float* __restrict__ Bv,
    float* __restrict__ outq, float* __restrict__ outk, float* __restrict__ outv)
{
    extern __shared__ float smx[];
    float* s_feat = smx;                 // [(ry*66+h)*36 + ci]
    float* s_w = smx + 9504;             // [conv][ci][72]

    const int t = threadIdx.x;
    const int s = blockIdx.x;
    const int cobase = blockIdx.y * 64;
    const int w = t >> 5, lane = t & 31;
    const int r = lane >> 2, cl = lane & 3;
    const int wrow = w >> 2;
    const int x0 = (w & 3) * 16;

    float cfrag[3][8][4];
#pragma unroll
    for (int cv = 0; cv < 3; cv++)
#pragma unroll
        for (int nt = 0; nt < 8; nt++)
#pragma unroll
            for (int i = 0; i < 4; i++) cfrag[cv][nt][i] = 0.f;

    for (int cb = 0; cb < 256; cb += 32) {
        __syncthreads();
        for (int i = t; i < 4 * 66 * 32; i += 256) {
            int tmp = i / 66, h = i - tmp * 66;
            int ci = tmp & 31, ry = tmp >> 5;
            int row = 2 * s - 1 + ry, x = h - 1;
            float v = 0.f;
            if ((unsigned)row < 64u && (unsigned)x < 64u)
                v = in[(cb + ci) * HW + row * 64 + x];
            s_feat[(ry * 66 + h) * 36 + ci] = v;
        }
#pragma unroll
        for (int tap = 0; tap < 9; tap++) {
            const int dy = tap / 3, dx = tap % 3;
            __syncthreads();
            { // stage weights for all three convs: [32 ci][64 co] each
                const float4* sq = (const float4*)(Tq + (tap * 256 + cb) * 256 + cobase);
                const float4* sk = (const float4*)(Tk + (tap * 256 + cb) * 256 + cobase);
                const float4* sv = (const float4*)(Tv + (tap * 256 + cb) * 256 + cobase);
                for (int i = t; i < 512; i += 256) {
                    int ci = i >> 4, co4 = i & 15;
                    ((float4*)(s_w + ci * 72))[co4] = sq[ci * 64 + co4];
                    ((float4*)(s_w + 2304 + ci * 72))[co4] = sk[ci * 64 + co4];
                    ((float4*)(s_w + 4608 + ci * 72))[co4] = sv[ci * 64 + co4];
                }
            }
            __syncthreads();
            const int rb = (wrow + dy) * 66 + x0 + dx;
#pragma unroll
            for (int ks = 0; ks < 4; ks++) {
                int c0 = ks * 8;
                unsigned ah[4];
                ah[0] = __float_as_uint(totf32(s_feat[(rb + r) * 36 + c0 + cl]));
                ah[1] = __float_as_uint(totf32(s_feat[(rb + r + 8) * 36 + c0 + cl]));
                ah[2] = __float_as_uint(totf32(s_feat[(rb + r) * 36 + c0 + cl + 4]));
                ah[3] = __float_as_uint(totf32(s_feat[(rb + r + 8) * 36 + c0 + cl + 4]));
#pragma unroll
                for (int cv = 0; cv < 3; cv++) {
                    const float* wbase = s_w + cv * 2304;
#pragma unroll
                    for (int nt = 0; nt < 8; nt++) {
                        int co = nt * 8 + r;
                        unsigned bh[2] = {__float_as_uint(wbase[(c0 + cl) * 72 + co]),
                                          __float_as_uint(wbase[(c0 + cl + 4) * 72 + co])};
                        mma_tf32(cfrag[cv][nt], ah, bh);
                    }
                }
            }
        }
    }
    const int pixrow = (2 * s + wrow) * 64 + x0;
#pragma unroll
    for (int cv = 0; cv < 3; cv++) {
        float* outp = (cv == 0) ? outq : (cv == 1) ? outk : outv;
        const float* Bp = (cv == 0) ? Bq : (cv == 1) ? Bk : Bv;
#pragma unroll
        for (int nt = 0; nt < 8; nt++)
#pragma unroll
            for (int i = 0; i < 4; i++) {
                int m = r + (i >> 1) * 8;
                int co = cobase + nt * 8 + 2 * cl + (i & 1);
                outp[(pixrow + m) * 256 + co] = cfrag[cv][nt][i] + Bp[co];  // pix-major
            }
    }
}

// ---------------- scalar 3x3 conv (enc only). grid(4,4,4), block 128 --------
template <int CIN, int COUT, bool RELU>
__global__ void __launch_bounds__(128) conv3x3_kernel(
    const float* __restrict__ in, const float* __restrict__ W,
    const float* __restrict__ B, float* __restrict__ out)
{
    __shared__ float s_in[18 * 18];
    __shared__ float s_w[16 * 9];
    const int tid = threadIdx.x;
    const int cog = tid >> 6, qid = tid & 63;
    const int qy = qid >> 3, qx = qid & 7;
    const int ty0 = blockIdx.y * 16, tx0 = blockIdx.x * 16;
    const int cobase = blockIdx.z * 16;

    int l_src[3]; bool l_ok[3];
#pragma unroll
    for (int t = 0; t < 3; t++) {
        int i = tid + t * 128; l_ok[t] = false; l_src[t] = 0;
        if (i < 324) {
            int r = i / 18, c = i % 18;
            int y = ty0 + r - 1, x = tx0 + c - 1;
            l_ok[t] = (y >= 0 && y < 64 && x >= 0 && x < 64);
            l_src[t] = y * 64 + x;
        }
    }
    float acc[2][2][8];
#pragma unroll
    for (int a = 0; a < 2; a++)
#pragma unroll
        for (int b = 0; b < 2; b++)
#pragma unroll
            for (int j = 0; j < 8; j++) acc[a][b][j] = 0.f;

    for (int ci = 0; ci < CIN; ci++) {
        const float* inc = in + ci * HW;
#pragma unroll
        for (int t = 0; t < 3; t++) {
            int i = tid + t * 128;
            if (i < 324) s_in[i] = l_ok[t] ? inc[l_src[t]] : 0.f;
        }
#pragma unroll
        for (int i = tid; i < 144; i += 128)
            s_w[i] = W[((cobase + i / 9) * CIN + ci) * 9 + i % 9];
        __syncthreads();
        float p[4][4];
#pragma unroll
        for (int r = 0; r < 4; r++)
#pragma unroll
            for (int c = 0; c < 4; c++)
                p[r][c] = s_in[(qy * 2 + r) * 18 + qx * 2 + c];
#pragma unroll
        for (int j = 0; j < 8; j++) {
            const float* w = &s_w[(cog * 8 + j) * 9];
#pragma unroll
            for (int oy = 0; oy < 2; oy++)
#pragma unroll
                for (int ox = 0; ox < 2; ox++)
                    acc[oy][ox][j] += w[0]*p[oy][ox]   + w[1]*p[oy][ox+1]   + w[2]*p[oy][ox+2]
                                    + w[3]*p[oy+1][ox] + w[4]*p[oy+1][ox+1] + w[5]*p[oy+1][ox+2]
                                    + w[6]*p[oy+2][ox] + w[7]*p[oy+2][ox+1] + w[8]*p[oy+2][ox+2];
        }
        __syncthreads();
    }
#pragma unroll
    for (int oy = 0; oy < 2; oy++)
#pragma unroll
        for (int ox = 0; ox < 2; ox++) {
            int pix = (ty0 + qy * 2 + oy) * 64 + tx0 + qx * 2 + ox;
#pragma unroll
            for (int j = 0; j < 8; j++) {
                int co = cobase + cog * 8 + j;
                float v = acc[oy][ox][j] + B[co];
                if (RELU) v = fmaxf(v, 0.f);
                out[co * HW + pix] = v;
            }
        }
}

// ---------------- grouped 5x5 pad2, groups 8. grid(4,4,8), block 256 --------
__global__ void __launch_bounds__(256) conv5x5g_kernel(
    const float* __restrict__ in, const float* __restrict__ W,
    const float* __restrict__ B, float* __restrict__ out)
{
    __shared__ float s_in[20 * 20];
    __shared__ float s_w[32 * 25];
    const int tid = threadIdx.x;
    const int cog = tid >> 6, qid = tid & 63;
    const int qy = qid >> 3, qx = qid & 7;
    const int ty0 = blockIdx.y * 16, tx0 = blockIdx.x * 16;
    const int grp = blockIdx.z;

    int l_src[2]; bool l_ok[2];
#pragma unroll
    for (int t = 0; t < 2; t++) {
        int i = tid + t * 256; l_ok[t] = false; l_src[t] = 0;
        if (i < 400) {
            int r = i / 20, c = i % 20;
            int y = ty0 + r - 2, x = tx0 + c - 2;
            l_ok[t] = (y >= 0 && y < 64 && x >= 0 && x < 64);
            l_src[t] = y * 64 + x;
        }
    }
    float acc[2][2][8];
#pragma unroll
    for (int a = 0; a < 2; a++)
#pragma unroll
        for (int b = 0; b < 2; b++)
#pragma unroll
            for (int j = 0; j < 8; j++) acc[a][b][j] = 0.f;

    for (int cil = 0; cil < 32; cil++) {
        const float* inc = in + (grp * 32 + cil) * HW;
#pragma unroll
        for (int t = 0; t < 2; t++) {
            int i = tid + t * 256;
            if (i < 400) s_in[i] = l_ok[t] ? inc[l_src[t]] : 0.f;
        }
        for (int i = tid; i < 800; i += 256)
            s_w[i] = W[((grp * 32 + i / 25) * 32 + cil) * 25 + i % 25];
        __syncthreads();
        float p[6][6];
#pragma unroll
        for (int r = 0; r < 6; r++)
#pragma unroll
            for (int c = 0; c < 6; c++)
                p[r][c] = s_in[(qy * 2 + r) * 20 + qx * 2 + c];
#pragma unroll
        for (int j = 0; j < 8; j++) {
            const float* w = &s_w[(cog * 8 + j) * 25];
#pragma unroll
            for (int oy = 0; oy < 2; oy++)
#pragma unroll
                for (int ox = 0; ox < 2; ox++) {
                    float s = 0.f;
#pragma unroll
                    for (int ky = 0; ky < 5; ky++)
#pragma unroll
                        for (int kx = 0; kx < 5; kx++)
                            s += w[ky * 5 + kx] * p[oy + ky][ox + kx];
                    acc[oy][ox][j] += s;
                }
        }
        __syncthreads();
    }
#pragma unroll
    for (int oy = 0; oy < 2; oy++)
#pragma unroll
        for (int ox = 0; ox < 2; ox++) {
            int pix = (ty0 + qy * 2 + oy) * 64 + tx0 + qx * 2 + ox;
#pragma unroll
            for (int j = 0; j < 8; j++) {
                int co = grp * 32 + cog * 8 + j;
                out[pix * 256 + co] = acc[oy][ox][j] + B[co];
            }
        }
}

// ---------------- LayerNorm + exact GELU. grid 512, block 256 ---------------
__global__ void __launch_bounds__(256) ln_gelu_kernel(
    const float* __restrict__ in, const float* __restrict__ gam,
    const float* __restrict__ bet, float* __restrict__ out)
{
    const int lane = threadIdx.x & 31, wid = threadIdx.x >> 5;
    const int pix = blockIdx.x * 8 + wid;
    float x[8];
#pragma unroll
    for (int i = 0; i < 8; i++) x[i] = in[pix * 256 + i * 32 + lane];
    float s = 0.f;
#pragma unroll
    for (int i = 0; i < 8; i++) s += x[i];
#pragma unroll
    for (int o = 16; o; o >>= 1) s += __shfl_xor_sync(0xffffffffu, s, o);
    float mu = s * (1.f / 256.f);
    float d = 0.f;
#pragma unroll
    for (int i = 0; i < 8; i++) { float t = x[i] - mu; d += t * t; }
#pragma unroll
    for (int o = 16; o; o >>= 1) d += __shfl_xor_sync(0xffffffffu, d, o);
    float inv = rsqrtf(d * (1.f / 256.f) + 1e-5f);
#pragma unroll
    for (int i = 0; i < 8; i++) {
        int c = i * 32 + lane;
        float y = (x[i] - mu) * inv * gam[c] + bet[c];
        out[pix * 256 + c] = 0.5f * y * (1.f + erff(y * 0.70710678118654752f));
    }
}

// ---------------- 1x1 conv 256->98. grid 128, block 128 ---------------------
__global__ void __launch_bounds__(128) conv1x1_kernel(
    const float* __restrict__ act, const float* __restrict__ W2, float* __restrict__ out)
{
    __shared__ float s_act[32 * 256];
    const int tid = threadIdx.x;
    const int pb = blockIdx.x * 32;
    const float4* src = (const float4*)(act + pb * 256);
    float4* dst = (float4*)s_act;
    for (int i = tid; i < 32 * 64; i += 128) dst[i] = src[i];
    __syncthreads();
    if (tid < 98) {
        float acc[32];
#pragma unroll
        for (int p = 0; p < 32; p++) acc[p] = 0.f;
        for (int c = 0; c < 256; c++) {
            float w = W2[tid * 256 + c];
#pragma unroll
            for (int p = 0; p < 32; p++) acc[p] += w * s_act[p * 256 + c];
        }
#pragma unroll
        for (int p = 0; p < 32; p++) out[(pb + p) * 98 + tid] = acc[p];
    }
}

// ---------------- per-query prep. grid 4096, block 256 ----------------------
__global__ void __launch_bounds__(256) qprep_kernel(
    const float* __restrict__ coord, const float* __restrict__ inp,
    const float* __restrict__ bc1, const float* __restrict__ bc2)
{
    __shared__ float s_q[256];
    __shared__ float s_rel[98];
    __shared__ float s_av[49 * 8];
    __shared__ float s_wc[49];
    __shared__ float s_h[256];
    __shared__ int   s_kidx[49];

    const int q = blockIdx.x;
    const int tid = threadIdx.x, lane = tid & 31, wid = tid >> 5;
    const float cy = coord[q * 2 + 0], cx = coord[q * 2 + 1];
    const float gx = ((cx + 1.f) * 64.f - 1.f) * 0.5f;
    const float gy = ((cy + 1.f) * 64.f - 1.f) * 0.5f;

    {
        float x0f = floorf(gx), y0f = floorf(gy);
        int x0 = (int)x0f, y0 = (int)y0f;
        float wx = gx - x0f, wy = gy - y0f;
        float a = 0.f;
#pragma unroll
        for (int t = 0; t < 4; t++) {
            int ix = x0 + (t & 1), iy = y0 + (t >> 1);
            float w = ((t & 1) ? wx : 1.f - wx) * ((t >> 1) ? wy : 1.f - wy);
            bool m = (ix >= 0 && ix < 64 && iy >= 0 && iy < 64);
            int pc = min(max(iy, 0), 63) * 64 + min(max(ix, 0), 63);
            float v = g_fq[pc * 256 + tid];
            a += m ? w * v : 0.f;
        }
        s_q[tid] = a;
    }

    const int ix0 = __float2int_rn(gx), iy0 = __float2int_rn(gy);
    const bool m0 = (ix0 >= 0 && ix0 < 64 && iy0 >= 0 && iy0 < 64);
    const int pix0 = min(max(iy0, 0), 63) * 64 + min(max(ix0, 0), 63);
    const float yb = m0 ? (-1.f + 0.015625f + 0.03125f * (float)iy0) : 0.f;
    const float xb = m0 ? (-1.f + 0.015625f + 0.03125f * (float)ix0) : 0.f;

    if (tid < 49) {
        const int k = tid;
        float o0 = m0 ? g_offmap[pix0 * 98 + 2 * k] : 0.f;
        float o1 = m0 ? g_offmap[pix0 * 98 + 2 * k + 1] : 0.f;
        float sy = yb + (float)(k / 7 - 3) * 0.03125f + tanhf(o0) * (2.f / 63.f);
        float sx = xb + (float)(k % 7 - 3) * 0.03125f + tanhf(o1) * (2.f / 63.f);
        s_rel[2 * k] = (cy - sy) * 64.f;
        s_rel[2 * k + 1] = (cx - sx) * 64.f;
        float gky = ((sy + 1.f) * 64.f - 1.f) * 0.5f;
        float gkx = ((sx + 1.f) * 64.f - 1.f) * 0.5f;
        int iky = __float2int_rn(gky), ikx = __float2int_rn(gkx);
        bool ok = (ikx >= 0 && ikx < 64 && iky >= 0 && iky < 64);
        s_kidx[k] = ok ? iky * 64 + ikx : -1;
        g_kidx[q * 49 + k] = s_kidx[k];
    }
    __syncthreads();

    for (int k = wid; k < 49; k += 8) {
        int pix = s_kidx[k];
        int h = lane >> 2, part = lane & 3;
        float s = 0.f;
        if (pix >= 0) {
            const float* fr = g_fk + pix * 256 + h * 32 + part * 8;
            const float* qr = s_q + h * 32 + part * 8;
#pragma unroll
            for (int i = 0; i < 8; i++) s += fr[i] * qr[i];
        }
        s += __shfl_xor_sync(0xffffffffu, s, 1);
        s += __shfl_xor_sync(0xffffffffu, s, 2);
        if (part == 0) s_av[k * 8 + h] = s * 0.17677669529663687f;
    }

    {
        float h1 = bc1[tid];
        for (int i = 0; i < 98; i++) h1 += g_Wc1T[i * 256 + tid] * s_rel[i];
        s_h[tid] = fmaxf(h1, 0.f);
    }
    __syncthreads();

    if (tid < 49) {
        float w = bc2[tid];
        for (int j = 0; j < 256; j++) w += g_Wc2T[j * 49 + tid] * s_h[j];
        s_wc[tid] = w;
    }
    if (tid >= 64 && tid < 67) {
        const int c = tid - 64;
        float gxc = fminf(fmaxf(gx, 0.f), 63.f), gyc = fminf(fmaxf(gy, 0.f), 63.f);
        float x0f = floorf(gxc), y0f = floorf(gyc);
        int x0 = (int)x0f, y0 = (int)y0f;
        float wx = gxc - x0f, wy = gyc - y0f;
        int x1 = min(x0 + 1, 63), y1 = min(y0 + 1, 63);
        const float* I = inp + c * HW;
        g_skipv[q * 3 + c] = (1.f - wx) * (1.f - wy) * I[y0 * 64 + x0]
                           + wx * (1.f - wy) * I[y0 * 64 + x1]
                           + (1.f - wx) * wy * I[y1 * 64 + x0]
                           + wx * wy * I[y1 * 64 + x1];
    }
    __syncthreads();

    if (tid < 8) {
        const int h = tid;
        float mx = -1e30f;
        for (int k = 0; k < 49; k++) mx = fmaxf(mx, s_wc[k] + s_av[k * 8 + h]);
        float sum = 0.f;
        for (int k = 0; k < 49; k++) {
            float e = expf(s_wc[k] + s_av[k * 8 + h] - mx);
            s_av[k * 8 + h] = e;
            sum += e;
        }
        float inv = 1.f / sum;
        for (int k = 0; k < 49; k++) g_attn[(q * 49 + k) * 8 + h] = s_av[k * 8 + h] * inv;
    }
}

// ---------------- big GEMM, 1-term tf32, double-buffered W ------------------
// grid 128, block 256. block: 64 q x 128 j. warp: 32q x 32j.
// dyn smem: s_a[64][260] (16640 f) + s_w[2][32][136] (8704 f) = 101376 B
__global__ void __launch_bounds__(256) gemm_kernel(
    const float* __restrict__ cell, const float* __restrict__ bi1)
{
    extern __shared__ float sm[];
    float* s_a = sm;                       // tf32-rounded A
    float* s_w = sm + 16640;               // [2][32*136]
    __shared__ float s_cell[128];

    const int t = threadIdx.x;
    const int qb = (blockIdx.x >> 1) * 64;
    const int jh = (blockIdx.x & 1) * 128;
    const int lane = t & 31, w = t >> 5;
    const int r = lane >> 2, cl = lane & 3;
    const int warpM = w >> 2, warpJ = w & 3;
    const int bq = t >> 2, hh = (t & 3) * 2;

    if (t < 128) s_cell[t] = cell[qb * 2 + t];

    float cfrag[2][4][4];
#pragma unroll
    for (int mt = 0; mt < 2; mt++)
#pragma unroll
        for (int nt = 0; nt < 4; nt++)
#pragma unroll
            for (int i = 0; i < 4; i++) cfrag[mt][nt][i] = 0.f;

    for (int k = 0; k < 49; k++) {
        __syncthreads();  // prev k's mma done reading s_a / s_w
        { // build A (tf32-rounded): s_a[q][c] = fv[pix][c] * attn[q][k][c/32]
            int pix = g_kidx[(qb + bq) * 49 + k];
            const float4* frbase = (const float4*)(g_fv + (pix < 0 ? 0 : pix) * 256);
#pragma unroll
            for (int hx = hh; hx < hh + 2; hx++) {
                float aw = g_attn[((qb + bq) * 49 + k) * 8 + hx];
                if (pix < 0) aw = 0.f;
                const float4* fr = frbase + hx * 8;
                float* dh = s_a + bq * 260 + hx * 32;
#pragma unroll
                for (int i = 0; i < 8; i++) {
                    float4 v = fr[i];
                    float4 o;
                    o.x = totf32(v.x * aw); o.y = totf32(v.y * aw);
                    o.z = totf32(v.z * aw); o.w = totf32(v.w * aw);
                    *(float4*)(dh + i * 4) = o;
                }
            }
        }
        { // stage W(k, sub=0) into buf 0
            const int rowg = k * 256;
#pragma unroll
            for (int i = 0; i < 4; i++) {
                int fi = t + i * 256;
                int c = fi >> 5, jf = fi & 31;
                ((float4*)(s_w + c * 136))[jf] =
                    ((const float4*)(g_Wi1T + (rowg + c) * 256 + jh))[jf];
            }
        }
        __syncthreads();

        for (int sub = 0; sub < 8; sub++) {
            const float* wb = s_w + (sub & 1) * 4352;
            if (sub < 7) { // stage next sub into other buffer (overlaps mma)
                float* wn = s_w + ((sub + 1) & 1) * 4352;
                const int rowg = k * 256 + (sub + 1) * 32;
#pragma unroll
                for (int i = 0; i < 4; i++) {
                    int fi = t + i * 256;
                    int c = fi >> 5, jf = fi & 31;
                    ((float4*)(wn + c * 136))[jf] =
                        ((const float4*)(g_Wi1T + (rowg + c) * 256 + jh))[jf];
                }
            }
#pragma unroll
            for (int ks = 0; ks < 4; ks++) {
                int cg = sub * 32 + ks * 8;
                int c0 = ks * 8;
                unsigned afh[2][4];
#pragma unroll
                for (int mt = 0; mt < 2; mt++) {
                    int row = warpM * 32 + mt * 16 + r;
                    afh[mt][0] = __float_as_uint(s_a[row * 260 + cg + cl]);
                    afh[mt][1] = __float_as_uint(s_a[(row + 8) * 260 + cg + cl]);
                    afh[mt][2] = __float_as_uint(s_a[row * 260 + cg + cl + 4]);
                    afh[mt][3] = __float_as_uint(s_a[(row + 8) * 260 + cg + cl + 4]);
                }
#pragma unroll
                for (int nt = 0; nt < 4; nt++) {
                    int jc = warpJ * 32 + nt * 8 + r;
                    unsigned bh[2] = {__float_as_uint(wb[(c0 + cl) * 136 + jc]),
                                      __float_as_uint(wb[(c0 + cl + 4) * 136 + jc])};
#pragma unroll
                    for (int mt = 0; mt < 2; mt++)
                        mma_tf32(cfrag[mt][nt], afh[mt], bh);
                }
            }
            __syncthreads();
        }
    }

    // epilogue: h = relu(acc + bi1 + wc0*ry + wc1*rx) -> g_hidden
#pragma unroll
    for (int nt = 0; nt < 4; nt++) {
        int jg = jh + warpJ * 32 + nt * 8 + 2 * cl;
        float b0 = bi1[jg], b1 = bi1[jg + 1];
        float w00 = g_Wi1T[12544 * 256 + jg], w01 = g_Wi1T[12544 * 256 + jg + 1];
        float w10 = g_Wi1T[12545 * 256 + jg], w11 = g_Wi1T[12545 * 256 + jg + 1];
#pragma unroll
        for (int mt = 0; mt < 2; mt++) {
#pragma unroll
            for (int half = 0; half < 2; half++) {
                int q = warpM * 32 + mt * 16 + r + half * 8;
                float ry = s_cell[q * 2 + 0] * 64.f, rx = s_cell[q * 2 + 1] * 64.f;
                float v0 = cfrag[mt][nt][half * 2 + 0] + b0 + w00 * ry + w10 * rx;
                float v1 = cfrag[mt][nt][half * 2 + 1] + b1 + w01 * ry + w11 * rx;
                g_hidden[(qb + q) * 256 + jg] = fmaxf(v0, 0.f);
                g_hidden[(qb + q) * 256 + jg + 1] = fmaxf(v1, 0.f);
            }
        }
    }
}

// ---------------- final MLP 256->3 + skip. grid 128, block 128 --------------
__global__ void __launch_bounds__(128) fin_kernel(
    const float* __restrict__ Wi2, const float* __restrict__ bi2,
    float* __restrict__ out)
{
    __shared__ float s_h[32 * 260];
    __shared__ float s_w2[768];
    const int t = threadIdx.x;
    const int qb = blockIdx.x * 32;
    const float4* src = (const float4*)(g_hidden + qb * 256);
#pragma unroll
    for (int i = 0; i < 16; i++) {
        int fi = t + i * 128;
        int q = fi >> 6, jf = fi & 63;
        ((float4*)(s_h + q * 260))[jf] = src[fi];
    }
    for (int i = t; i < 768; i += 128) s_w2[i] = Wi2[i];
    __syncthreads();
    if (t < 96) {
        int q = t / 3, c = t % 3;
        float s = 0.f;
        for (int j = 0; j < 256; j++) s += s_h[q * 260 + j] * s_w2[c * 256 + j];
        out[(qb + q) * 3 + c] = s + bi2[c] + g_skipv[(qb + q) * 3 + c];
    }
}

// ---------------- host ------------------------------------------------------
extern "C" void kernel_launch(void* const* d_in, const int* in_sizes, int n_in,
                              void* d_out, int out_size)
{
    const float* inp   = (const float*)d_in[0];
    const float* coord = (const float*)d_in[1];
    const float* cell  = (const float*)d_in[2];
    const float* W_enc = (const float*)d_in[3];
    const float* b_enc = (const float*)d_in[4];
    const float* W_ch  = (const float*)d_in[5];
    const float* b_ch  = (const float*)d_in[6];
    const float* W_q   = (const float*)d_in[7];
    const float* b_q   = (const float*)d_in[8];
    const float* W_k   = (const float*)d_in[9];
    const float* b_k   = (const float*)d_in[10];
    const float* W_v   = (const float*)d_in[11];
    const float* b_v   = (const float*)d_in[12];
    const float* W_off1= (const float*)d_in[13];
    const float* b_off1= (const float*)d_in[14];
    const float* ln_g  = (const float*)d_in[15];
    const float* ln_b  = (const float*)d_in[16];
    const float* W_off2= (const float*)d_in[17];
    const float* Wc1   = (const float*)d_in[18];
    const float* bc1   = (const float*)d_in[19];
    const float* Wc2   = (const float*)d_in[20];
    const float* bc2   = (const float*)d_in[21];
    const float* Wi1   = (const float*)d_in[22];
    const float* bi1   = (const float*)d_in[23];
    const float* Wi2   = (const float*)d_in[24];
    const float* bi2   = (const float*)d_in[25];
    float* out = (float*)d_out;

    void* p;
    cudaGetSymbolAddress(&p, g_enc);     float* enc = (float*)p;
    cudaGetSymbolAddress(&p, g_feat);    float* feat = (float*)p;
    cudaGetSymbolAddress(&p, g_fq);      float* fq = (float*)p;
    cudaGetSymbolAddress(&p, g_fk);      float* fk = (float*)p;
    cudaGetSymbolAddress(&p, g_fv);      float* fv = (float*)p;
    cudaGetSymbolAddress(&p, g_off1);    float* off1 = (float*)p;
    cudaGetSymbolAddress(&p, g_act);     float* act = (float*)p;
    cudaGetSymbolAddress(&p, g_offmap);  float* offmap = (float*)p;
    cudaGetSymbolAddress(&p, g_Wi1T);    float* wi1t = (float*)p;
    cudaGetSymbolAddress(&p, g_Wc1T);    float* wc1t = (float*)p;
    cudaGetSymbolAddress(&p, g_Wc2T);    float* wc2t = (float*)p;
    cudaGetSymbolAddress(&p, g_WchT);    float* wcht = (float*)p;
    cudaGetSymbolAddress(&p, g_WqT);     float* wqt = (float*)p;
    cudaGetSymbolAddress(&p, g_WkT);     float* wkt = (float*)p;
    cudaGetSymbolAddress(&p, g_WvT);     float* wvt = (float*)p;

    cudaFuncSetAttribute(convmma_ch_kernel<64>, cudaFuncAttributeMaxDynamicSharedMemorySize, 47232);
    cudaFuncSetAttribute(convmma_qkv_kernel, cudaFuncAttributeMaxDynamicSharedMemorySize, 65664);
    cudaFuncSetAttribute(gemm_kernel, cudaFuncAttributeMaxDynamicSharedMemorySize, 101376);

    dim3 tb(32, 8);
    // ncu (-s 5 -c 1, with 2 hidden launches) captures my launch #4 -> convmma_qkv.
    wtrans_all_kernel<<<dim3(9 * 256, 4), 256>>>(W_ch, W_q, W_k, W_v,
                                                 wcht, wqt, wkt, wvt);        // 1
    conv3x3_kernel<3, 64, true><<<dim3(4, 4, 4), 128>>>(inp, W_enc, b_enc, enc); // 2
    convmma_ch_kernel<64><<<dim3(32, 4), 256, 47232>>>(enc, wcht, b_ch, feat);   // 3
    convmma_qkv_kernel<<<dim3(32, 4), 256, 65664>>>(feat, wqt, wkt, wvt,
                                                    b_q, b_k, b_v, fq, fk, fv); // 4 <- profiled
    transpose_kernel<<<dim3(393, 8), tb>>>(Wi1, wi1t, 256, 12546, 1);         // 5
    transpose_kernel<<<dim3(4, 8), tb>>>(Wc1, wc1t, 256, 98, 0);              // 6
    transpose_kernel<<<dim3(8, 2), tb>>>(Wc2, wc2t, 49, 256, 0);              // 7
    conv5x5g_kernel<<<dim3(4, 4, 8), 256>>>(feat, W_off1, b_off1, off1);      // 8
    ln_gelu_kernel<<<512, 256>>>(off1, ln_g, ln_b, act);                      // 9
    conv1x1_kernel<<<128, 128>>>(act, W_off2, offmap);                        // 10
    qprep_kernel<<<4096, 256>>>(coord, inp, bc1, bc2);                        // 11
    gemm_kernel<<<128, 256, 101376>>>(cell, bi1);                             // 12
    fin_kernel<<<128, 128>>>(Wi2, bi2, out);                                  // 13
}

// round 15
// speedup vs baseline: 2.0304x; 1.1381x over previous
#include <cuda_runtime.h>
#include <math.h>

#define HW 4096

__device__ float g_enc[64 * HW];
__device__ float g_feat[256 * HW];
__device__ float g_fq[HW * 256];
__device__ float g_fk[HW * 256];
__device__ float g_fv[HW * 256];
__device__ float g_off1[HW * 256];
__device__ float g_act[HW * 256];
__device__ float g_offmap[HW * 98];
__device__ float g_attn[4096 * 49 * 8];
__device__ int   g_kidx[4096 * 49];
__device__ float g_skipv[4096 * 3];
__device__ float g_hidden[4096 * 256];
__device__ float g_Wi1T[12546 * 256];
__device__ float g_Wc1T[98 * 256];
__device__ float g_Wc2T[256 * 49];
__device__ float g_WchT[9 * 64 * 256];
__device__ float g_WqT[9 * 256 * 256];
__device__ float g_WkT[9 * 256 * 256];
__device__ float g_WvT[9 * 256 * 256];
__device__ float g_W5T[25 * 8 * 32 * 32];

__device__ __forceinline__ float totf32(float x) {
    float r; asm("cvt.rna.tf32.f32 %0, %1;" : "=f"(r) : "f"(x)); return r;
}
__device__ __forceinline__ void mma_tf32(float* c, const unsigned* a, const unsigned* b) {
    asm volatile("mma.sync.aligned.m16n8k8.row.col.f32.tf32.tf32.f32 "
        "{%0,%1,%2,%3}, {%4,%5,%6,%7}, {%8,%9}, {%0,%1,%2,%3};"
        : "+f"(c[0]), "+f"(c[1]), "+f"(c[2]), "+f"(c[3])
        : "r"(a[0]), "r"(a[1]), "r"(a[2]), "r"(a[3]), "r"(b[0]), "r"(b[1]));
}

// ---------------- transpose (optional tf32 rounding) ------------------------
__global__ void transpose_kernel(const float* __restrict__ src, float* __restrict__ dst,
                                 int rows, int cols, int tf32)
{
    __shared__ float tile[32][33];
    int c0 = blockIdx.x * 32, r0 = blockIdx.y * 32;
    int tx = threadIdx.x, ty = threadIdx.y;
#pragma unroll
    for (int i = 0; i < 32; i += 8) {
        int r = r0 + ty + i, c = c0 + tx;
        tile[ty + i][tx] = (r < rows && c < cols) ? src[r * cols + c] : 0.f;
    }
    __syncthreads();
#pragma unroll
    for (int i = 0; i < 32; i += 8) {
        int r = c0 + ty + i, c = r0 + tx;
        if (r < cols && c < rows) {
            float v = tile[tx][ty + i];
            if (tf32) v = totf32(v);
            dst[r * rows + c] = v;
        }
    }
}

// ---------------- conv weight transforms ------------------------------------
__global__ void wtrans_all_kernel(
    const float* __restrict__ Wch, const float* __restrict__ Wq,
    const float* __restrict__ Wk, const float* __restrict__ Wv,
    float* __restrict__ Tch, float* __restrict__ Tq,
    float* __restrict__ Tk, float* __restrict__ Tv)
{
    const int which = blockIdx.y;
    const int CIN = (which == 0) ? 64 : 256;
    int tap = blockIdx.x / 256, ci = blockIdx.x % 256, co = threadIdx.x;
    if (ci >= CIN) return;
    const float* W = (which == 0) ? Wch : (which == 1) ? Wq : (which == 2) ? Wk : Wv;
    float* T = (which == 0) ? Tch : (which == 1) ? Tq : (which == 2) ? Tk : Tv;
    T[(tap * CIN + ci) * 256 + co] = totf32(W[co * CIN * 9 + ci * 9 + tap]);
}

// 5x5 grouped: W[co_g(256)][ci(32)][tap(25)] -> T5[tap][grp][ci][co32]
__global__ void wtrans5_kernel(const float* __restrict__ W, float* __restrict__ T5)
{
    int tap = blockIdx.x, g = blockIdx.y;
    int ci = threadIdx.y, co = threadIdx.x;
    T5[((tap * 8 + g) * 32 + ci) * 32 + co] =
        totf32(W[(g * 32 + co) * 32 * 25 + ci * 25 + tap]);
}

// ---------------- 3x3 conv via tf32 mma, ch variant (32-co tiles) -----------
// grid (32 strips, 8), block 256. dyn smem: feat 9504 + w 2304 = 47232 B
template <int CIN>
__global__ void __launch_bounds__(256, 2) convmma_ch_kernel(
    const float* __restrict__ in, const float* __restrict__ T,
    const float* __restrict__ B, float* __restrict__ out)
{
    extern __shared__ float smx[];
    float* s_feat = smx;           // [(ry*66+h)*36 + ci]
    float* s_w = smx + 9504;       // [ci][72] (32 co used)

    const int t = threadIdx.x;
    const int s = blockIdx.x;
    const int cobase = blockIdx.y * 32;
    const int w = t >> 5, lane = t & 31;
    const int r = lane >> 2, cl = lane & 3;
    const int wrow = w >> 2;
    const int x0 = (w & 3) * 16;

    float cfrag[4][4];
#pragma unroll
    for (int nt = 0; nt < 4; nt++)
#pragma unroll
        for (int i = 0; i < 4; i++) cfrag[nt][i] = 0.f;

    for (int cb = 0; cb < CIN; cb += 32) {
        __syncthreads();
        for (int i = t; i < 4 * 66 * 32; i += 256) {
            int tmp = i / 66, h = i - tmp * 66;
            int ci = tmp & 31, ry = tmp >> 5;
            int row = 2 * s - 1 + ry, x = h - 1;
            float v = 0.f;
            if ((unsigned)row < 64u && (unsigned)x < 64u)
                v = in[(cb + ci) * HW + row * 64 + x];
            s_feat[(ry * 66 + h) * 36 + ci] = v;
        }
#pragma unroll
        for (int tap = 0; tap < 9; tap++) {
            const int dy = tap / 3, dx = tap % 3;
            __syncthreads();
            if (t < 256) {
                int ci = t >> 3, co4 = t & 7;
                ((float4*)(s_w + ci * 72))[co4] =
                    ((const float4*)(T + (tap * CIN + cb + ci) * 256 + cobase))[co4];
            }
            __syncthreads();
            const int rb = (wrow + dy) * 66 + x0 + dx;
#pragma unroll
            for (int ks = 0; ks < 4; ks++) {
                int c0 = ks * 8;
                unsigned ah[4];
                ah[0] = __float_as_uint(totf32(s_feat[(rb + r) * 36 + c0 + cl]));
                ah[1] = __float_as_uint(totf32(s_feat[(rb + r + 8) * 36 + c0 + cl]));
                ah[2] = __float_as_uint(totf32(s_feat[(rb + r) * 36 + c0 + cl + 4]));
                ah[3] = __float_as_uint(totf32(s_feat[(rb + r + 8) * 36 + c0 + cl + 4]));
#pragma unroll
                for (int nt = 0; nt < 4; nt++) {
                    int co = nt * 8 + r;
                    unsigned bh[2] = {__float_as_uint(s_w[(c0 + cl) * 72 + co]),
                                      __float_as_uint(s_w[(c0 + cl + 4) * 72 + co])};
                    mma_tf32(cfrag[nt], ah, bh);
                }
            }
        }
    }
    const int pixrow = (2 * s + wrow) * 64 + x0;
#pragma unroll
    for (int nt = 0; nt < 4; nt++)
#pragma unroll
        for (int i = 0; i < 4; i++) {
            int m = r + (i >> 1) * 8;
            int co = cobase + nt * 8 + 2 * cl + (i & 1);
            out[co * HW + pixrow + m] = cfrag[nt][i] + B[co];   // chan-major
        }
}

// ---------------- fused q/k/v 3x3 conv (32-co tiles) ------------------------
// grid (32 strips, 8), block 256. dyn smem: feat 9504 + 3*2304 = 65664 B
__global__ void __launch_bounds__(256, 2) convmma_qkv_kernel(
    const float* __restrict__ in,
    const float* __restrict__ Tq, const float* __restrict__ Tk, const float* __restrict__ Tv,
    const float* __restrict__ Bq, const float* __restrict__ Bk, const float* __restrict__ Bv,
    float* __restrict__ outq, float* __restrict__ outk, float* __restrict__ outv)
{
    extern __shared__ float smx[];
    float* s_feat = smx;                 // [(ry*66+h)*36 + ci]
    float* s_w = smx + 9504;             // [conv][ci][72]

    const int t = threadIdx.x;
    const int s = blockIdx.x;
    const int cobase = blockIdx.y * 32;
    const int w = t >> 5, lane = t & 31;
    const int r = lane >> 2, cl = lane & 3;
    const int wrow = w >> 2;
    const int x0 = (w & 3) * 16;

    float cfrag[3][4][4];
#pragma unroll
    for (int cv = 0; cv < 3; cv++)
#pragma unroll
        for (int nt = 0; nt < 4; nt++)
#pragma unroll
            for (int i = 0; i < 4; i++) cfrag[cv][nt][i] = 0.f;

    for (int cb = 0; cb < 256; cb += 32) {
        __syncthreads();
        for (int i = t; i < 4 * 66 * 32; i += 256) {
            int tmp = i / 66, h = i - tmp * 66;
            int ci = tmp & 31, ry = tmp >> 5;
            int row = 2 * s - 1 + ry, x = h - 1;
            float v = 0.f;
            if ((unsigned)row < 64u && (unsigned)x < 64u)
                v = in[(cb + ci) * HW + row * 64 + x];
            s_feat[(ry * 66 + h) * 36 + ci] = v;
        }
#pragma unroll
        for (int tap = 0; tap < 9; tap++) {
            const int dy = tap / 3, dx = tap % 3;
            __syncthreads();
            {
                int ci = t >> 3, co4 = t & 7;
                ((float4*)(s_w + ci * 72))[co4] =
                    ((const float4*)(Tq + (tap * 256 + cb + ci) * 256 + cobase))[co4];
                ((float4*)(s_w + 2304 + ci * 72))[co4] =
                    ((const float4*)(Tk + (tap * 256 + cb + ci) * 256 + cobase))[co4];
                ((float4*)(s_w + 4608 + ci * 72))[co4] =
                    ((const float4*)(Tv + (tap * 256 + cb + ci) * 256 + cobase))[co4];
            }
            __syncthreads();
            const int rb = (wrow + dy) * 66 + x0 + dx;
#pragma unroll
            for (int ks = 0; ks < 4; ks++) {
                int c0 = ks * 8;
                unsigned ah[4];
                ah[0] = __float_as_uint(totf32(s_feat[(rb + r) * 36 + c0 + cl]));
                ah[1] = __float_as_uint(totf32(s_feat[(rb + r + 8) * 36 + c0 + cl]));
                ah[2] = __float_as_uint(totf32(s_feat[(rb + r) * 36 + c0 + cl + 4]));
                ah[3] = __float_as_uint(totf32(s_feat[(rb + r + 8) * 36 + c0 + cl + 4]));
#pragma unroll
                for (int cv = 0; cv < 3; cv++) {
                    const float* wbase = s_w + cv * 2304;
#pragma unroll
                    for (int nt = 0; nt < 4; nt++) {
                        int co = nt * 8 + r;
                        unsigned bh[2] = {__float_as_uint(wbase[(c0 + cl) * 72 + co]),
                                          __float_as_uint(wbase[(c0 + cl + 4) * 72 + co])};
                        mma_tf32(cfrag[cv][nt], ah, bh);
                    }
                }
            }
        }
    }
    const int pixrow = (2 * s + wrow) * 64 + x0;
#pragma unroll
    for (int cv = 0; cv < 3; cv++) {
        float* outp = (cv == 0) ? outq : (cv == 1) ? outk : outv;
        const float* Bp = (cv == 0) ? Bq : (cv == 1) ? Bk : Bv;
#pragma unroll
        for (int nt = 0; nt < 4; nt++)
#pragma unroll
            for (int i = 0; i < 4; i++) {
                int m = r + (i >> 1) * 8;
                int co = cobase + nt * 8 + 2 * cl + (i & 1);
                outp[(pixrow + m) * 256 + co] = cfrag[cv][nt][i] + Bp[co];  // pix-major
            }
    }
}

// ---------------- grouped 5x5 via tf32 mma. grid (32 strips, 8 groups) ------
// dyn smem: feat 6*68*36=14688 f + w 2304 f = 67968 B
__global__ void __launch_bounds__(256, 2) convmma5_kernel(
    const float* __restrict__ in, const float* __restrict__ T5,
    const float* __restrict__ B, float* __restrict__ out)
{
    extern __shared__ float smx[];
    float* s_feat = smx;            // [(ry*68+h)*36 + ci], ry 0..5, h 0..67
    float* s_w = smx + 14688;       // [ci][72] (32 co used)

    const int t = threadIdx.x;
    const int s = blockIdx.x;
    const int g = blockIdx.y;
    const int w = t >> 5, lane = t & 31;
    const int r = lane >> 2, cl = lane & 3;
    const int wrow = w >> 2;
    const int x0 = (w & 3) * 16;

    float cfrag[4][4];
#pragma unroll
    for (int nt = 0; nt < 4; nt++)
#pragma unroll
        for (int i = 0; i < 4; i++) cfrag[nt][i] = 0.f;

    // stage feat rows 2s-2..2s+3 with x halo -2..65, 32 ci of this group
    for (int i = t; i < 6 * 68 * 32; i += 256) {
        int tmp = i / 68, h = i - tmp * 68;
        int ci = tmp & 31, ry = tmp >> 5;
        int row = 2 * s - 2 + ry, x = h - 2;
        float v = 0.f;
        if ((unsigned)row < 64u && (unsigned)x < 64u)
            v = in[(g * 32 + ci) * HW + row * 64 + x];
        s_feat[(ry * 68 + h) * 36 + ci] = v;
    }
    __syncthreads();

    for (int tap = 0; tap < 25; tap++) {
        const int dy = tap / 5, dx = tap % 5;
        if (tap) __syncthreads();
        {
            int ci = t >> 3, co4 = t & 7;
            ((float4*)(s_w + ci * 72))[co4] =
                ((const float4*)(T5 + ((tap * 8 + g) * 32) * 32))[t];
        }
        __syncthreads();
        const int rb = (wrow + dy) * 68 + x0 + dx;
#pragma unroll
        for (int ks = 0; ks < 4; ks++) {
            int c0 = ks * 8;
            unsigned ah[4];
            ah[0] = __float_as_uint(totf32(s_feat[(rb + r) * 36 + c0 + cl]));
            ah[1] = __float_as_uint(totf32(s_feat[(rb + r + 8) * 36 + c0 + cl]));
            ah[2] = __float_as_uint(totf32(s_feat[(rb + r) * 36 + c0 + cl + 4]));
            ah[3] = __float_as_uint(totf32(s_feat[(rb + r + 8) * 36 + c0 + cl + 4]));
#pragma unroll
            for (int nt = 0; nt < 4; nt++) {
                int co = nt * 8 + r;
                unsigned bh[2] = {__float_as_uint(s_w[(c0 + cl) * 72 + co]),
                                  __float_as_uint(s_w[(c0 + cl + 4) * 72 + co])};
                mma_tf32(cfrag[nt], ah, bh);
            }
        }
    }
    const int pixrow = (2 * s + wrow) * 64 + x0;
#pragma unroll
    for (int nt = 0; nt < 4; nt++)
#pragma unroll
        for (int i = 0; i < 4; i++) {
            int m = r + (i >> 1) * 8;
            int co = g * 32 + nt * 8 + 2 * cl + (i & 1);
            out[(pixrow + m) * 256 + co] = cfrag[nt][i] + B[co];  // pix-major
        }
}

// ---------------- scalar 3x3 conv (enc only). grid(4,4,4), block 128 --------
template <int CIN, int COUT, bool RELU>
__global__ void __launch_bounds__(128) conv3x3_kernel(
    const float* __restrict__ in, const float* __restrict__ W,
    const float* __restrict__ B, float* __restrict__ out)
{
    __shared__ float s_in[18 * 18];
    __shared__ float s_w[16 * 9];
    const int tid = threadIdx.x;
    const int cog = tid >> 6, qid = tid & 63;
    const int qy = qid >> 3, qx = qid & 7;
    const int ty0 = blockIdx.y * 16, tx0 = blockIdx.x * 16;
    const int cobase = blockIdx.z * 16;

    int l_src[3]; bool l_ok[3];
#pragma unroll
    for (int t = 0; t < 3; t++) {
        int i = tid + t * 128; l_ok[t] = false; l_src[t] = 0;
        if (i < 324) {
            int r = i / 18, c = i % 18;
            int y = ty0 + r - 1, x = tx0 + c - 1;
            l_ok[t] = (y >= 0 && y < 64 && x >= 0 && x < 64);
            l_src[t] = y * 64 + x;
        }
    }
    float acc[2][2][8];
#pragma unroll
    for (int a = 0; a < 2; a++)
#pragma unroll
        for (int b = 0; b < 2; b++)
#pragma unroll
            for (int j = 0; j < 8; j++) acc[a][b][j] = 0.f;

    for (int ci = 0; ci < CIN; ci++) {
        const float* inc = in + ci * HW;
#pragma unroll
        for (int t = 0; t < 3; t++) {
            int i = tid + t * 128;
            if (i < 324) s_in[i] = l_ok[t] ? inc[l_src[t]] : 0.f;
        }
#pragma unroll
        for (int i = tid; i < 144; i += 128)
            s_w[i] = W[((cobase + i / 9) * CIN + ci) * 9 + i % 9];
        __syncthreads();
        float p[4][4];
#pragma unroll
        for (int r = 0; r < 4; r++)
#pragma unroll
            for (int c = 0; c < 4; c++)
                p[r][c] = s_in[(qy * 2 + r) * 18 + qx * 2 + c];
#pragma unroll
        for (int j = 0; j < 8; j++) {
            const float* w = &s_w[(cog * 8 + j) * 9];
#pragma unroll
            for (int oy = 0; oy < 2; oy++)
#pragma unroll
                for (int ox = 0; ox < 2; ox++)
                    acc[oy][ox][j] += w[0]*p[oy][ox]   + w[1]*p[oy][ox+1]   + w[2]*p[oy][ox+2]
                                    + w[3]*p[oy+1][ox] + w[4]*p[oy+1][ox+1] + w[5]*p[oy+1][ox+2]
                                    + w[6]*p[oy+2][ox] + w[7]*p[oy+2][ox+1] + w[8]*p[oy+2][ox+2];
        }
        __syncthreads();
    }
#pragma unroll
    for (int oy = 0; oy < 2; oy++)
#pragma unroll
        for (int ox = 0; ox < 2; ox++) {
            int pix = (ty0 + qy * 2 + oy) * 64 + tx0 + qx * 2 + ox;
#pragma unroll
            for (int j = 0; j < 8; j++) {
                int co = cobase + cog * 8 + j;
                float v = acc[oy][ox][j] + B[co];
                if (RELU) v = fmaxf(v, 0.f);
                out[co * HW + pix] = v;
            }
        }
}

// ---------------- LayerNorm + exact GELU. grid 512, block 256 ---------------
__global__ void __launch_bounds__(256) ln_gelu_kernel(
    const float* __restrict__ in, const float* __restrict__ gam,
    const float* __restrict__ bet, float* __restrict__ out)
{
    const int lane = threadIdx.x & 31, wid = threadIdx.x >> 5;
    const int pix = blockIdx.x * 8 + wid;
    float x[8];
#pragma unroll
    for (int i = 0; i < 8; i++) x[i] = in[pix * 256 + i * 32 + lane];
    float s = 0.f;
#pragma unroll
    for (int i = 0; i < 8; i++) s += x[i];
#pragma unroll
    for (int o = 16; o; o >>= 1) s += __shfl_xor_sync(0xffffffffu, s, o);
    float mu = s * (1.f / 256.f);
    float d = 0.f;
#pragma unroll
    for (int i = 0; i < 8; i++) { float t = x[i] - mu; d += t * t; }
#pragma unroll
    for (int o = 16; o; o >>= 1) d += __shfl_xor_sync(0xffffffffu, d, o);
    float inv = rsqrtf(d * (1.f / 256.f) + 1e-5f);
#pragma unroll
    for (int i = 0; i < 8; i++) {
        int c = i * 32 + lane;
        float y = (x[i] - mu) * inv * gam[c] + bet[c];
        out[pix * 256 + c] = 0.5f * y * (1.f + erff(y * 0.70710678118654752f));
    }
}

// ---------------- 1x1 conv 256->98. grid 128, block 128 ---------------------
__global__ void __launch_bounds__(128) conv1x1_kernel(
    const float* __restrict__ act, const float* __restrict__ W2, float* __restrict__ out)
{
    __shared__ float s_act[32 * 256];
    const int tid = threadIdx.x;
    const int pb = blockIdx.x * 32;
    const float4* src = (const float4*)(act + pb * 256);
    float4* dst = (float4*)s_act;
    for (int i = tid; i < 32 * 64; i += 128) dst[i] = src[i];
    __syncthreads();
    if (tid < 98) {
        float acc[32];
#pragma unroll
        for (int p = 0; p < 32; p++) acc[p] = 0.f;
        for (int c = 0; c < 256; c++) {
            float w = W2[tid * 256 + c];
#pragma unroll
            for (int p = 0; p < 32; p++) acc[p] += w * s_act[p * 256 + c];
        }
#pragma unroll
        for (int p = 0; p < 32; p++) out[(pb + p) * 98 + tid] = acc[p];
    }
}

// ---------------- per-query prep. grid 4096, block 256 ----------------------
__global__ void __launch_bounds__(256) qprep_kernel(
    const float* __restrict__ coord, const float* __restrict__ inp,
    const float* __restrict__ bc1, const float* __restrict__ bc2)
{
    __shared__ float s_q[256];
    __shared__ float s_rel[98];
    __shared__ float s_av[49 * 8];
    __shared__ float s_wc[49];
    __shared__ float s_h[256];
    __shared__ int   s_kidx[49];

    const int q = blockIdx.x;
    const int tid = threadIdx.x, lane = tid & 31, wid = tid >> 5;
    const float cy = coord[q * 2 + 0], cx = coord[q * 2 + 1];
    const float gx = ((cx + 1.f) * 64.f - 1.f) * 0.5f;
    const float gy = ((cy + 1.f) * 64.f - 1.f) * 0.5f;

    {
        float x0f = floorf(gx), y0f = floorf(gy);
        int x0 = (int)x0f, y0 = (int)y0f;
        float wx = gx - x0f, wy = gy - y0f;
        float a = 0.f;
#pragma unroll
        for (int t = 0; t < 4; t++) {
            int ix = x0 + (t & 1), iy = y0 + (t >> 1);
            float w = ((t & 1) ? wx : 1.f - wx) * ((t >> 1) ? wy : 1.f - wy);
            bool m = (ix >= 0 && ix < 64 && iy >= 0 && iy < 64);
            int pc = min(max(iy, 0), 63) * 64 + min(max(ix, 0), 63);
            float v = g_fq[pc * 256 + tid];
            a += m ? w * v : 0.f;
        }
        s_q[tid] = a;
    }

    const int ix0 = __float2int_rn(gx), iy0 = __float2int_rn(gy);
    const bool m0 = (ix0 >= 0 && ix0 < 64 && iy0 >= 0 && iy0 < 64);
    const int pix0 = min(max(iy0, 0), 63) * 64 + min(max(ix0, 0), 63);
    const float yb = m0 ? (-1.f + 0.015625f + 0.03125f * (float)iy0) : 0.f;
    const float xb = m0 ? (-1.f + 0.015625f + 0.03125f * (float)ix0) : 0.f;

    if (tid < 49) {
        const int k = tid;
        float o0 = m0 ? g_offmap[pix0 * 98 + 2 * k] : 0.f;
        float o1 = m0 ? g_offmap[pix0 * 98 + 2 * k + 1] : 0.f;
        float sy = yb + (float)(k / 7 - 3) * 0.03125f + tanhf(o0) * (2.f / 63.f);
        float sx = xb + (float)(k % 7 - 3) * 0.03125f + tanhf(o1) * (2.f / 63.f);
        s_rel[2 * k] = (cy - sy) * 64.f;
        s_rel[2 * k + 1] = (cx - sx) * 64.f;
        float gky = ((sy + 1.f) * 64.f - 1.f) * 0.5f;
        float gkx = ((sx + 1.f) * 64.f - 1.f) * 0.5f;
        int iky = __float2int_rn(gky), ikx = __float2int_rn(gkx);
        bool ok = (ikx >= 0 && ikx < 64 && iky >= 0 && iky < 64);
        s_kidx[k] = ok ? iky * 64 + ikx : -1;
        g_kidx[q * 49 + k] = s_kidx[k];
    }
    __syncthreads();

    for (int k = wid; k < 49; k += 8) {
        int pix = s_kidx[k];
        int h = lane >> 2, part = lane & 3;
        float s = 0.f;
        if (pix >= 0) {
            const float* fr = g_fk + pix * 256 + h * 32 + part * 8;
            const float* qr = s_q + h * 32 + part * 8;
#pragma unroll
            for (int i = 0; i < 8; i++) s += fr[i] * qr[i];
        }
        s += __shfl_xor_sync(0xffffffffu, s, 1);
        s += __shfl_xor_sync(0xffffffffu, s, 2);
        if (part == 0) s_av[k * 8 + h] = s * 0.17677669529663687f;
    }

    {
        float h1 = bc1[tid];
        for (int i = 0; i < 98; i++) h1 += g_Wc1T[i * 256 + tid] * s_rel[i];
        s_h[tid] = fmaxf(h1, 0.f);
    }
    __syncthreads();

    if (tid < 49) {
        float w = bc2[tid];
        for (int j = 0; j < 256; j++) w += g_Wc2T[j * 49 + tid] * s_h[j];
        s_wc[tid] = w;
    }
    if (tid >= 64 && tid < 67) {
        const int c = tid - 64;
        float gxc = fminf(fmaxf(gx, 0.f), 63.f), gyc = fminf(fmaxf(gy, 0.f), 63.f);
        float x0f = floorf(gxc), y0f = floorf(gyc);
        int x0 = (int)x0f, y0 = (int)y0f;
        float wx = gxc - x0f, wy = gyc - y0f;
        int x1 = min(x0 + 1, 63), y1 = min(y0 + 1, 63);
        const float* I = inp + c * HW;
        g_skipv[q * 3 + c] = (1.f - wx) * (1.f - wy) * I[y0 * 64 + x0]
                           + wx * (1.f - wy) * I[y0 * 64 + x1]
                           + (1.f - wx) * wy * I[y1 * 64 + x0]
                           + wx * wy * I[y1 * 64 + x1];
    }
    __syncthreads();

    if (tid < 8) {
        const int h = tid;
        float mx = -1e30f;
        for (int k = 0; k < 49; k++) mx = fmaxf(mx, s_wc[k] + s_av[k * 8 + h]);
        float sum = 0.f;
        for (int k = 0; k < 49; k++) {
            float e = expf(s_wc[k] + s_av[k * 8 + h] - mx);
            s_av[k * 8 + h] = e;
            sum += e;
        }
        float inv = 1.f / sum;
        for (int k = 0; k < 49; k++) g_attn[(q * 49 + k) * 8 + h] = s_av[k * 8 + h] * inv;
    }
}

// ---------------- big GEMM, 1-term tf32, double-buffered W ------------------
// grid 128, block 256. block: 64 q x 128 j. warp: 32q x 32j.
// dyn smem: s_a[64][260] (16640 f) + s_w[2][32][136] (8704 f) = 101376 B
__global__ void __launch_bounds__(256) gemm_kernel(
    const float* __restrict__ cell, const float* __restrict__ bi1)
{
    extern __shared__ float sm[];
    float* s_a = sm;
    float* s_w = sm + 16640;
    __shared__ float s_cell[128];

    const int t = threadIdx.x;
    const int qb = (blockIdx.x >> 1) * 64;
    const int jh = (blockIdx.x & 1) * 128;
    const int lane = t & 31, w = t >> 5;
    const int r = lane >> 2, cl = lane & 3;
    const int warpM = w >> 2, warpJ = w & 3;
    const int bq = t >> 2, hh = (t & 3) * 2;

    if (t < 128) s_cell[t] = cell[qb * 2 + t];

    float cfrag[2][4][4];
#pragma unroll
    for (int mt = 0; mt < 2; mt++)
#pragma unroll
        for (int nt = 0; nt < 4; nt++)
#pragma unroll
            for (int i = 0; i < 4; i++) cfrag[mt][nt][i] = 0.f;

    for (int k = 0; k < 49; k++) {
        __syncthreads();
        {
            int pix = g_kidx[(qb + bq) * 49 + k];
            const float4* frbase = (const float4*)(g_fv + (pix < 0 ? 0 : pix) * 256);
#pragma unroll
            for (int hx = hh; hx < hh + 2; hx++) {
                float aw = g_attn[((qb + bq) * 49 + k) * 8 + hx];
                if (pix < 0) aw = 0.f;
                const float4* fr = frbase + hx * 8;
                float* dh = s_a + bq * 260 + hx * 32;
#pragma unroll
                for (int i = 0; i < 8; i++) {
                    float4 v = fr[i];
                    float4 o;
                    o.x = totf32(v.x * aw); o.y = totf32(v.y * aw);
                    o.z = totf32(v.z * aw); o.w = totf32(v.w * aw);
                    *(float4*)(dh + i * 4) = o;
                }
            }
        }
        {
            const int rowg = k * 256;
#pragma unroll
            for (int i = 0; i < 4; i++) {
                int fi = t + i * 256;
                int c = fi >> 5, jf = fi & 31;
                ((float4*)(s_w + c * 136))[jf] =
                    ((const float4*)(g_Wi1T + (rowg + c) * 256 + jh))[jf];
            }
        }
        __syncthreads();

        for (int sub = 0; sub < 8; sub++) {
            const float* wb = s_w + (sub & 1) * 4352;
            if (sub < 7) {
                float* wn = s_w + ((sub + 1) & 1) * 4352;
                const int rowg = k * 256 + (sub + 1) * 32;
#pragma unroll
                for (int i = 0; i < 4; i++) {
                    int fi = t + i * 256;
                    int c = fi >> 5, jf = fi & 31;
                    ((float4*)(wn + c * 136))[jf] =
                        ((const float4*)(g_Wi1T + (rowg + c) * 256 + jh))[jf];
                }
            }
#pragma unroll
            for (int ks = 0; ks < 4; ks++) {
                int cg = sub * 32 + ks * 8;
                int c0 = ks * 8;
                unsigned afh[2][4];
#pragma unroll
                for (int mt = 0; mt < 2; mt++) {
                    int row = warpM * 32 + mt * 16 + r;
                    afh[mt][0] = __float_as_uint(s_a[row * 260 + cg + cl]);
                    afh[mt][1] = __float_as_uint(s_a[(row + 8) * 260 + cg + cl]);
                    afh[mt][2] = __float_as_uint(s_a[row * 260 + cg + cl + 4]);
                    afh[mt][3] = __float_as_uint(s_a[(row + 8) * 260 + cg + cl + 4]);
                }
#pragma unroll
                for (int nt = 0; nt < 4; nt++) {
                    int jc = warpJ * 32 + nt * 8 + r;
                    unsigned bh[2] = {__float_as_uint(wb[(c0 + cl) * 136 + jc]),
                                      __float_as_uint(wb[(c0 + cl + 4) * 136 + jc])};
#pragma unroll
                    for (int mt = 0; mt < 2; mt++)
                        mma_tf32(cfrag[mt][nt], afh[mt], bh);
                }
            }
            __syncthreads();
        }
    }

#pragma unroll
    for (int nt = 0; nt < 4; nt++) {
        int jg = jh + warpJ * 32 + nt * 8 + 2 * cl;
        float b0 = bi1[jg], b1 = bi1[jg + 1];
        float w00 = g_Wi1T[12544 * 256 + jg], w01 = g_Wi1T[12544 * 256 + jg + 1];
        float w10 = g_Wi1T[12545 * 256 + jg], w11 = g_Wi1T[12545 * 256 + jg + 1];
#pragma unroll
        for (int mt = 0; mt < 2; mt++) {
#pragma unroll
            for (int half = 0; half < 2; half++) {
                int q = warpM * 32 + mt * 16 + r + half * 8;
                float ry = s_cell[q * 2 + 0] * 64.f, rx = s_cell[q * 2 + 1] * 64.f;
                float v0 = cfrag[mt][nt][half * 2 + 0] + b0 + w00 * ry + w10 * rx;
                float v1 = cfrag[mt][nt][half * 2 + 1] + b1 + w01 * ry + w11 * rx;
                g_hidden[(qb + q) * 256 + jg] = fmaxf(v0, 0.f);
                g_hidden[(qb + q) * 256 + jg + 1] = fmaxf(v1, 0.f);
            }
        }
    }
}

// ---------------- final MLP 256->3 + skip. grid 128, block 128 --------------
__global__ void __launch_bounds__(128) fin_kernel(
    const float* __restrict__ Wi2, const float* __restrict__ bi2,
    float* __restrict__ out)
{
    __shared__ float s_h[32 * 260];
    __shared__ float s_w2[768];
    const int t = threadIdx.x;
    const int qb = blockIdx.x * 32;
    const float4* src = (const float4*)(g_hidden + qb * 256);
#pragma unroll
    for (int i = 0; i < 16; i++) {
        int fi = t + i * 128;
        int q = fi >> 6, jf = fi & 63;
        ((float4*)(s_h + q * 260))[jf] = src[fi];
    }
    for (int i = t; i < 768; i += 128) s_w2[i] = Wi2[i];
    __syncthreads();
    if (t < 96) {
        int q = t / 3, c = t % 3;
        float s = 0.f;
        for (int j = 0; j < 256; j++) s += s_h[q * 260 + j] * s_w2[c * 256 + j];
        out[(qb + q) * 3 + c] = s + bi2[c] + g_skipv[(qb + q) * 3 + c];
    }
}

// ---------------- host ------------------------------------------------------
extern "C" void kernel_launch(void* const* d_in, const int* in_sizes, int n_in,
                              void* d_out, int out_size)
{
    const float* inp   = (const float*)d_in[0];
    const float* coord = (const float*)d_in[1];
    const float* cell  = (const float*)d_in[2];
    const float* W_enc = (const float*)d_in[3];
    const float* b_enc = (const float*)d_in[4];
    const float* W_ch  = (const float*)d_in[5];
    const float* b_ch  = (const float*)d_in[6];
    const float* W_q   = (const float*)d_in[7];
    const float* b_q   = (const float*)d_in[8];
    const float* W_k   = (const float*)d_in[9];
    const float* b_k   = (const float*)d_in[10];
    const float* W_v   = (const float*)d_in[11];
    const float* b_v   = (const float*)d_in[12];
    const float* W_off1= (const float*)d_in[13];
    const float* b_off1= (const float*)d_in[14];
    const float* ln_g  = (const float*)d_in[15];
    const float* ln_b  = (const float*)d_in[16];
    const float* W_off2= (const float*)d_in[17];
    const float* Wc1   = (const float*)d_in[18];
    const float* bc1   = (const float*)d_in[19];
    const float* Wc2   = (const float*)d_in[20];
    const float* bc2   = (const float*)d_in[21];
    const float* Wi1   = (const float*)d_in[22];
    const float* bi1   = (const float*)d_in[23];
    const float* Wi2   = (const float*)d_in[24];
    const float* bi2   = (const float*)d_in[25];
    float* out = (float*)d_out;

    void* p;
    cudaGetSymbolAddress(&p, g_enc);     float* enc = (float*)p;
    cudaGetSymbolAddress(&p, g_feat);    float* feat = (float*)p;
    cudaGetSymbolAddress(&p, g_fq);      float* fq = (float*)p;
    cudaGetSymbolAddress(&p, g_fk);      float* fk = (float*)p;
    cudaGetSymbolAddress(&p, g_fv);      float* fv = (float*)p;
    cudaGetSymbolAddress(&p, g_off1);    float* off1 = (float*)p;
    cudaGetSymbolAddress(&p, g_act);     float* act = (float*)p;
    cudaGetSymbolAddress(&p, g_offmap);  float* offmap = (float*)p;
    cudaGetSymbolAddress(&p, g_Wi1T);    float* wi1t = (float*)p;
    cudaGetSymbolAddress(&p, g_Wc1T);    float* wc1t = (float*)p;
    cudaGetSymbolAddress(&p, g_Wc2T);    float* wc2t = (float*)p;
    cudaGetSymbolAddress(&p, g_WchT);    float* wcht = (float*)p;
    cudaGetSymbolAddress(&p, g_WqT);     float* wqt = (float*)p;
    cudaGetSymbolAddress(&p, g_WkT);     float* wkt = (float*)p;
    cudaGetSymbolAddress(&p, g_WvT);     float* wvt = (float*)p;
    cudaGetSymbolAddress(&p, g_W5T);     float* w5t = (float*)p;

    cudaFuncSetAttribute(convmma_ch_kernel<64>, cudaFuncAttributeMaxDynamicSharedMemorySize, 47232);
    cudaFuncSetAttribute(convmma_qkv_kernel, cudaFuncAttributeMaxDynamicSharedMemorySize, 65664);
    cudaFuncSetAttribute(convmma5_kernel, cudaFuncAttributeMaxDynamicSharedMemorySize, 67968);
    cudaFuncSetAttribute(gemm_kernel, cudaFuncAttributeMaxDynamicSharedMemorySize, 101376);

    dim3 tb(32, 8);
    wtrans_all_kernel<<<dim3(9 * 256, 4), 256>>>(W_ch, W_q, W_k, W_v,
                                                 wcht, wqt, wkt, wvt);           // 1
    conv3x3_kernel<3, 64, true><<<dim3(4, 4, 4), 128>>>(inp, W_enc, b_enc, enc); // 2
    convmma_ch_kernel<64><<<dim3(32, 8), 256, 47232>>>(enc, wcht, b_ch, feat);   // 3
    convmma_qkv_kernel<<<dim3(32, 8), 256, 65664>>>(feat, wqt, wkt, wvt,
                                                    b_q, b_k, b_v, fq, fk, fv);  // 4 <- profiled
    wtrans5_kernel<<<dim3(25, 8), dim3(32, 32)>>>(W_off1, w5t);                  // 5
    convmma5_kernel<<<dim3(32, 8), 256, 67968>>>(feat, w5t, b_off1, off1);       // 6
    transpose_kernel<<<dim3(393, 8), tb>>>(Wi1, wi1t, 256, 12546, 1);            // 7
    transpose_kernel<<<dim3(4, 8), tb>>>(Wc1, wc1t, 256, 98, 0);                 // 8
    transpose_kernel<<<dim3(8, 2), tb>>>(Wc2, wc2t, 49, 256, 0);                 // 9
    ln_gelu_kernel<<<512, 256>>>(off1, ln_g, ln_b, act);                         // 10
    conv1x1_kernel<<<128, 128>>>(act, W_off2, offmap);                           // 11
    qprep_kernel<<<4096, 256>>>(coord, inp, bc1, bc2);                           // 12
    gemm_kernel<<<128, 256, 101376>>>(cell, bi1);                                // 13
    fin_kernel<<<128, 128>>>(Wi2, bi2, out);                                     // 14
}

// round 16
// speedup vs baseline: 2.2889x; 1.1273x over previous
#include <cuda_runtime.h>
#include <cuda_bf16.h>
#include <math.h>

#define HW 4096

__device__ float g_enc[64 * HW];
__device__ float g_feat[256 * HW];
__device__ float g_fq[HW * 256];
__device__ float g_fk[HW * 256];
__device__ float g_fv[HW * 256];
__device__ float g_off1[HW * 256];
__device__ float g_act[HW * 256];
__device__ float g_offmap[HW * 98];
__device__ float g_attn[4096 * 49 * 8];
__device__ int   g_kidx[4096 * 49];
__device__ float g_skipv[4096 * 3];
__device__ float g_hidden[4096 * 256];
__device__ float g_Wc1T[98 * 256];
__device__ float g_Wc2T[256 * 49];
__device__ float g_WchT[9 * 64 * 256];          // tf32 [tap][ci][co]
__device__ float g_W5T[25 * 8 * 32 * 32];       // tf32
__device__ __nv_bfloat16 g_WqB[9 * 256 * 256];  // bf16 [tap][co][ci]
__device__ __nv_bfloat16 g_WkB[9 * 256 * 256];
__device__ __nv_bfloat16 g_WvB[9 * 256 * 256];
__device__ __nv_bfloat16 g_Wi1B[256 * 12560];   // bf16 [j][c], padded rows

__device__ __forceinline__ float totf32(float x) {
    float r; asm("cvt.rna.tf32.f32 %0, %1;" : "=f"(r) : "f"(x)); return r;
}
// pack two fp32 -> bf16x2 word, lo in bits[15:0]
__device__ __forceinline__ unsigned pbf2(float lo, float hi) {
    unsigned r; asm("cvt.rn.bf16x2.f32 %0, %1, %2;" : "=r"(r) : "f"(hi), "f"(lo)); return r;
}
__device__ __forceinline__ void mma_tf32(float* c, const unsigned* a, const unsigned* b) {
    asm volatile("mma.sync.aligned.m16n8k8.row.col.f32.tf32.tf32.f32 "
        "{%0,%1,%2,%3}, {%4,%5,%6,%7}, {%8,%9}, {%0,%1,%2,%3};"
        : "+f"(c[0]), "+f"(c[1]), "+f"(c[2]), "+f"(c[3])
        : "r"(a[0]), "r"(a[1]), "r"(a[2]), "r"(a[3]), "r"(b[0]), "r"(b[1]));
}
__device__ __forceinline__ void mma_bf16(float* c, const unsigned* a, const unsigned* b) {
    asm volatile("mma.sync.aligned.m16n8k16.row.col.f32.bf16.bf16.f32 "
        "{%0,%1,%2,%3}, {%4,%5,%6,%7}, {%8,%9}, {%0,%1,%2,%3};"
        : "+f"(c[0]), "+f"(c[1]), "+f"(c[2]), "+f"(c[3])
        : "r"(a[0]), "r"(a[1]), "r"(a[2]), "r"(a[3]), "r"(b[0]), "r"(b[1]));
}

// ---------------- transpose (tf32 optional) for Wc1/Wc2 ---------------------
__global__ void transpose_kernel(const float* __restrict__ src, float* __restrict__ dst,
                                 int rows, int cols, int tf32)
{
    __shared__ float tile[32][33];
    int c0 = blockIdx.x * 32, r0 = blockIdx.y * 32;
    int tx = threadIdx.x, ty = threadIdx.y;
#pragma unroll
    for (int i = 0; i < 32; i += 8) {
        int r = r0 + ty + i, c = c0 + tx;
        tile[ty + i][tx] = (r < rows && c < cols) ? src[r * cols + c] : 0.f;
    }
    __syncthreads();
#pragma unroll
    for (int i = 0; i < 32; i += 8) {
        int r = c0 + ty + i, c = r0 + tx;
        if (r < cols && c < rows) {
            float v = tile[tx][ty + i];
            if (tf32) v = totf32(v);
            dst[r * rows + c] = v;
        }
    }
}

// ---------------- conv weight transforms ------------------------------------
// which 0: ch tf32 [tap][ci][co]; which 1..3: q/k/v bf16 [tap][co][ci]
__global__ void wtrans2_kernel(
    const float* __restrict__ Wch, const float* __restrict__ Wq,
    const float* __restrict__ Wk, const float* __restrict__ Wv)
{
    const int which = blockIdx.y, bx = blockIdx.x, t = threadIdx.x;
    if (which == 0) {
        int tap = bx / 256, ci = bx % 256;
        if (ci < 64)
            g_WchT[(tap * 64 + ci) * 256 + t] = totf32(Wch[t * 64 * 9 + ci * 9 + tap]);
    } else {
        int tap = bx / 256, co = bx % 256;
        const float* W = (which == 1) ? Wq : (which == 2) ? Wk : Wv;
        __nv_bfloat16* T = (which == 1) ? g_WqB : (which == 2) ? g_WkB : g_WvB;
        T[(tap * 256 + co) * 256 + t] = __float2bfloat16(W[co * 256 * 9 + t * 9 + tap]);
    }
}

__global__ void wtrans5_kernel(const float* __restrict__ W, float* __restrict__ T5)
{
    int tap = blockIdx.x, g = blockIdx.y;
    int ci = threadIdx.y, co = threadIdx.x;
    T5[((tap * 8 + g) * 32 + ci) * 32 + co] =
        totf32(W[(g * 32 + co) * 32 * 25 + ci * 25 + tap]);
}

// Wi1 fp32 [j][12546] -> bf16 [j][12560] (padded row)
__global__ void wi1b_kernel(const float* __restrict__ Wi1)
{
    int j = blockIdx.x;
    for (int c = threadIdx.x; c < 12546; c += 256)
        g_Wi1B[j * 12560 + c] = __float2bfloat16(Wi1[j * 12546 + c]);
}

// ---------------- 3x3 conv via tf32 mma, ch variant (unchanged) -------------
template <int CIN>
__global__ void __launch_bounds__(256, 2) convmma_ch_kernel(
    const float* __restrict__ in, const float* __restrict__ T,
    const float* __restrict__ B, float* __restrict__ out)
{
    extern __shared__ float smx[];
    float* s_feat = smx;
    float* s_w = smx + 9504;

    const int t = threadIdx.x;
    const int s = blockIdx.x;
    const int cobase = blockIdx.y * 32;
    const int w = t >> 5, lane = t & 31;
    const int r = lane >> 2, cl = lane & 3;
    const int wrow = w >> 2;
    const int x0 = (w & 3) * 16;

    float cfrag[4][4];
#pragma unroll
    for (int nt = 0; nt < 4; nt++)
#pragma unroll
        for (int i = 0; i < 4; i++) cfrag[nt][i] = 0.f;

    for (int cb = 0; cb < CIN; cb += 32) {
        __syncthreads();
        for (int i = t; i < 4 * 66 * 32; i += 256) {
            int tmp = i / 66, h = i - tmp * 66;
            int ci = tmp & 31, ry = tmp >> 5;
            int row = 2 * s - 1 + ry, x = h - 1;
            float v = 0.f;
            if ((unsigned)row < 64u && (unsigned)x < 64u)
                v = in[(cb + ci) * HW + row * 64 + x];
            s_feat[(ry * 66 + h) * 36 + ci] = v;
        }
#pragma unroll
        for (int tap = 0; tap < 9; tap++) {
            const int dy = tap / 3, dx = tap % 3;
            __syncthreads();
            {
                int ci = t >> 3, co4 = t & 7;
                ((float4*)(s_w + ci * 72))[co4] =
                    ((const float4*)(T + (tap * CIN + cb + ci) * 256 + cobase))[co4];
            }
            __syncthreads();
            const int rb = (wrow + dy) * 66 + x0 + dx;
#pragma unroll
            for (int ks = 0; ks < 4; ks++) {
                int c0 = ks * 8;
                unsigned ah[4];
                ah[0] = __float_as_uint(totf32(s_feat[(rb + r) * 36 + c0 + cl]));
                ah[1] = __float_as_uint(totf32(s_feat[(rb + r + 8) * 36 + c0 + cl]));
                ah[2] = __float_as_uint(totf32(s_feat[(rb + r) * 36 + c0 + cl + 4]));
                ah[3] = __float_as_uint(totf32(s_feat[(rb + r + 8) * 36 + c0 + cl + 4]));
#pragma unroll
                for (int nt = 0; nt < 4; nt++) {
                    int co = nt * 8 + r;
                    unsigned bh[2] = {__float_as_uint(s_w[(c0 + cl) * 72 + co]),
                                      __float_as_uint(s_w[(c0 + cl + 4) * 72 + co])};
                    mma_tf32(cfrag[nt], ah, bh);
                }
            }
        }
    }
    const int pixrow = (2 * s + wrow) * 64 + x0;
#pragma unroll
    for (int nt = 0; nt < 4; nt++)
#pragma unroll
        for (int i = 0; i < 4; i++) {
            int m = r + (i >> 1) * 8;
            int co = cobase + nt * 8 + 2 * cl + (i & 1);
            out[co * HW + pixrow + m] = cfrag[nt][i] + B[co];
        }
}

// ---------------- fused q/k/v 3x3 conv via bf16 mma (m16n8k16) --------------
// grid (32 strips, 8), block 256.
// smem words: s_feat 4*66*20=5280 + s_w 3*640=1920 -> 28800 B
__global__ void __launch_bounds__(256, 2) convmma_qkv_kernel(
    const float* __restrict__ in,
    const float* __restrict__ Bq, const float* __restrict__ Bk, const float* __restrict__ Bv,
    float* __restrict__ outq, float* __restrict__ outk, float* __restrict__ outv)
{
    extern __shared__ unsigned smu[];
    unsigned* s_feat = smu;          // [(ry*66+h)*20 + w], w = ci word (2 ci)
    unsigned* s_w = smu + 5280;      // [cv][co][20]

    const int t = threadIdx.x;
    const int s = blockIdx.x;
    const int cobase = blockIdx.y * 32;
    const int w = t >> 5, lane = t & 31;
    const int r = lane >> 2, cl = lane & 3;
    const int wrow = w >> 2;
    const int x0 = (w & 3) * 16;

    float cfrag[3][4][4];
#pragma unroll
    for (int cv = 0; cv < 3; cv++)
#pragma unroll
        for (int nt = 0; nt < 4; nt++)
#pragma unroll
            for (int i = 0; i < 4; i++) cfrag[cv][nt][i] = 0.f;

    for (int cb = 0; cb < 256; cb += 32) {
        __syncthreads();
        // stage feat as bf16x2 words; h fastest for coalesced global reads
        for (int i = t; i < 4 * 16 * 66; i += 256) {
            int h = i % 66, tmp = i / 66;
            int wd = tmp & 15, ry = tmp >> 4;
            int row = 2 * s - 1 + ry, x = h - 1;
            float v0 = 0.f, v1 = 0.f;
            if ((unsigned)row < 64u && (unsigned)x < 64u) {
                v0 = in[(cb + 2 * wd) * HW + row * 64 + x];
                v1 = in[(cb + 2 * wd + 1) * HW + row * 64 + x];
            }
            s_feat[(ry * 66 + h) * 20 + wd] = pbf2(v0, v1);
        }
#pragma unroll
        for (int tap = 0; tap < 9; tap++) {
            const int dy = tap / 3, dx = tap % 3;
            __syncthreads();
            { // stage weights: per conv 32 co x 16 words (uint4 x4 per co)
                for (int i = t; i < 384; i += 256) {
                    int cv = i >> 7, rem = i & 127, co = rem >> 2, seg = rem & 3;
                    const __nv_bfloat16* T = (cv == 0) ? g_WqB : (cv == 1) ? g_WkB : g_WvB;
                    const uint4* src = (const uint4*)(T + (tap * 256 + cobase + co) * 256 + cb);
                    ((uint4*)(s_w + cv * 640 + co * 20))[seg] = src[seg];
                }
            }
            __syncthreads();
            const int rb = (wrow + dy) * 66 + x0 + dx;
#pragma unroll
            for (int ks = 0; ks < 2; ks++) {
                int wb = ks * 8;
                unsigned ah[4];
                ah[0] = s_feat[(rb + r) * 20 + wb + cl];
                ah[1] = s_feat[(rb + r + 8) * 20 + wb + cl];
                ah[2] = s_feat[(rb + r) * 20 + wb + cl + 4];
                ah[3] = s_feat[(rb + r + 8) * 20 + wb + cl + 4];
#pragma unroll
                for (int cv = 0; cv < 3; cv++) {
                    const unsigned* wbase = s_w + cv * 640;
#pragma unroll
                    for (int nt = 0; nt < 4; nt++) {
                        int co = nt * 8 + r;
                        unsigned bh[2] = {wbase[co * 20 + wb + cl],
                                          wbase[co * 20 + wb + cl + 4]};
                        mma_bf16(cfrag[cv][nt], ah, bh);
                    }
                }
            }
        }
    }
    const int pixrow = (2 * s + wrow) * 64 + x0;
#pragma unroll
    for (int cv = 0; cv < 3; cv++) {
        float* outp = (cv == 0) ? outq : (cv == 1) ? outk : outv;
        const float* Bp = (cv == 0) ? Bq : (cv == 1) ? Bk : Bv;
#pragma unroll
        for (int nt = 0; nt < 4; nt++)
#pragma unroll
            for (int i = 0; i < 4; i++) {
                int m = r + (i >> 1) * 8;
                int co = cobase + nt * 8 + 2 * cl + (i & 1);
                outp[(pixrow + m) * 256 + co] = cfrag[cv][nt][i] + Bp[co];
            }
    }
}

// ---------------- grouped 5x5 via tf32 mma (unchanged) ----------------------
__global__ void __launch_bounds__(256, 2) convmma5_kernel(
    const float* __restrict__ in, const float* __restrict__ T5,
    const float* __restrict__ B, float* __restrict__ out)
{
    extern __shared__ float smx[];
    float* s_feat = smx;
    float* s_w = smx + 14688;

    const int t = threadIdx.x;
    const int s = blockIdx.x;
    const int g = blockIdx.y;
    const int w = t >> 5, lane = t & 31;
    const int r = lane >> 2, cl = lane & 3;
    const int wrow = w >> 2;
    const int x0 = (w & 3) * 16;

    float cfrag[4][4];
#pragma unroll
    for (int nt = 0; nt < 4; nt++)
#pragma unroll
        for (int i = 0; i < 4; i++) cfrag[nt][i] = 0.f;

    for (int i = t; i < 6 * 68 * 32; i += 256) {
        int tmp = i / 68, h = i - tmp * 68;
        int ci = tmp & 31, ry = tmp >> 5;
        int row = 2 * s - 2 + ry, x = h - 2;
        float v = 0.f;
        if ((unsigned)row < 64u && (unsigned)x < 64u)
            v = in[(g * 32 + ci) * HW + row * 64 + x];
        s_feat[(ry * 68 + h) * 36 + ci] = v;
    }
    __syncthreads();

    for (int tap = 0; tap < 25; tap++) {
        const int dy = tap / 5, dx = tap % 5;
        if (tap) __syncthreads();
        {
            int ci = t >> 3, co4 = t & 7;
            ((float4*)(s_w + ci * 72))[co4] =
                ((const float4*)(T5 + ((tap * 8 + g) * 32) * 32))[t];
        }
        __syncthreads();
        const int rb = (wrow + dy) * 68 + x0 + dx;
#pragma unroll
        for (int ks = 0; ks < 4; ks++) {
            int c0 = ks * 8;
            unsigned ah[4];
            ah[0] = __float_as_uint(totf32(s_feat[(rb + r) * 36 + c0 + cl]));
            ah[1] = __float_as_uint(totf32(s_feat[(rb + r + 8) * 36 + c0 + cl]));
            ah[2] = __float_as_uint(totf32(s_feat[(rb + r) * 36 + c0 + cl + 4]));
            ah[3] = __float_as_uint(totf32(s_feat[(rb + r + 8) * 36 + c0 + cl + 4]));
#pragma unroll
            for (int nt = 0; nt < 4; nt++) {
                int co = nt * 8 + r;
                unsigned bh[2] = {__float_as_uint(s_w[(c0 + cl) * 72 + co]),
                                  __float_as_uint(s_w[(c0 + cl + 4) * 72 + co])};
                mma_tf32(cfrag[nt], ah, bh);
            }
        }
    }
    const int pixrow = (2 * s + wrow) * 64 + x0;
#pragma unroll
    for (int nt = 0; nt < 4; nt++)
#pragma unroll
        for (int i = 0; i < 4; i++) {
            int m = r + (i >> 1) * 8;
            int co = g * 32 + nt * 8 + 2 * cl + (i & 1);
            out[(pixrow + m) * 256 + co] = cfrag[nt][i] + B[co];
        }
}

// ---------------- scalar 3x3 conv (enc only) --------------------------------
template <int CIN, int COUT, bool RELU>
__global__ void __launch_bounds__(128) conv3x3_kernel(
    const float* __restrict__ in, const float* __restrict__ W,
    const float* __restrict__ B, float* __restrict__ out)
{
    __shared__ float s_in[18 * 18];
    __shared__ float s_w[16 * 9];
    const int tid = threadIdx.x;
    const int cog = tid >> 6, qid = tid & 63;
    const int qy = qid >> 3, qx = qid & 7;
    const int ty0 = blockIdx.y * 16, tx0 = blockIdx.x * 16;
    const int cobase = blockIdx.z * 16;

    int l_src[3]; bool l_ok[3];
#pragma unroll
    for (int t = 0; t < 3; t++) {
        int i = tid + t * 128; l_ok[t] = false; l_src[t] = 0;
        if (i < 324) {
            int r = i / 18, c = i % 18;
            int y = ty0 + r - 1, x = tx0 + c - 1;
            l_ok[t] = (y >= 0 && y < 64 && x >= 0 && x < 64);
            l_src[t] = y * 64 + x;
        }
    }
    float acc[2][2][8];
#pragma unroll
    for (int a = 0; a < 2; a++)
#pragma unroll
        for (int b = 0; b < 2; b++)
#pragma unroll
            for (int j = 0; j < 8; j++) acc[a][b][j] = 0.f;

    for (int ci = 0; ci < CIN; ci++) {
        const float* inc = in + ci * HW;
#pragma unroll
        for (int t = 0; t < 3; t++) {
            int i = tid + t * 128;
            if (i < 324) s_in[i] = l_ok[t] ? inc[l_src[t]] : 0.f;
        }
#pragma unroll
        for (int i = tid; i < 144; i += 128)
            s_w[i] = W[((cobase + i / 9) * CIN + ci) * 9 + i % 9];
        __syncthreads();
        float p[4][4];
#pragma unroll
        for (int r = 0; r < 4; r++)
#pragma unroll
            for (int c = 0; c < 4; c++)
                p[r][c] = s_in[(qy * 2 + r) * 18 + qx * 2 + c];
#pragma unroll
        for (int j = 0; j < 8; j++) {
            const float* w = &s_w[(cog * 8 + j) * 9];
#pragma unroll
            for (int oy = 0; oy < 2; oy++)
#pragma unroll
                for (int ox = 0; ox < 2; ox++)
                    acc[oy][ox][j] += w[0]*p[oy][ox]   + w[1]*p[oy][ox+1]   + w[2]*p[oy][ox+2]
                                    + w[3]*p[oy+1][ox] + w[4]*p[oy+1][ox+1] + w[5]*p[oy+1][ox+2]
                                    + w[6]*p[oy+2][ox] + w[7]*p[oy+2][ox+1] + w[8]*p[oy+2][ox+2];
        }
        __syncthreads();
    }
#pragma unroll
    for (int oy = 0; oy < 2; oy++)
#pragma unroll
        for (int ox = 0; ox < 2; ox++) {
            int pix = (ty0 + qy * 2 + oy) * 64 + tx0 + qx * 2 + ox;
#pragma unroll
            for (int j = 0; j < 8; j++) {
                int co = cobase + cog * 8 + j;
                float v = acc[oy][ox][j] + B[co];
                if (RELU) v = fmaxf(v, 0.f);
                out[co * HW + pix] = v;
            }
        }
}

// ---------------- LayerNorm + exact GELU ------------------------------------
__global__ void __launch_bounds__(256) ln_gelu_kernel(
    const float* __restrict__ in, const float* __restrict__ gam,
    const float* __restrict__ bet, float* __restrict__ out)
{
    const int lane = threadIdx.x & 31, wid = threadIdx.x >> 5;
    const int pix = blockIdx.x * 8 + wid;
    float x[8];
#pragma unroll
    for (int i = 0; i < 8; i++) x[i] = in[pix * 256 + i * 32 + lane];
    float s = 0.f;
#pragma unroll
    for (int i = 0; i < 8; i++) s += x[i];
#pragma unroll
    for (int o = 16; o; o >>= 1) s += __shfl_xor_sync(0xffffffffu, s, o);
    float mu = s * (1.f / 256.f);
    float d = 0.f;
#pragma unroll
    for (int i = 0; i < 8; i++) { float t = x[i] - mu; d += t * t; }
#pragma unroll
    for (int o = 16; o; o >>= 1) d += __shfl_xor_sync(0xffffffffu, d, o);
    float inv = rsqrtf(d * (1.f / 256.f) + 1e-5f);
#pragma unroll
    for (int i = 0; i < 8; i++) {
        int c = i * 32 + lane;
        float y = (x[i] - mu) * inv * gam[c] + bet[c];
        out[pix * 256 + c] = 0.5f * y * (1.f + erff(y * 0.70710678118654752f));
    }
}

// ---------------- 1x1 conv 256->98 ------------------------------------------
__global__ void __launch_bounds__(128) conv1x1_kernel(
    const float* __restrict__ act, const float* __restrict__ W2, float* __restrict__ out)
{
    __shared__ float s_act[32 * 256];
    const int tid = threadIdx.x;
    const int pb = blockIdx.x * 32;
    const float4* src = (const float4*)(act + pb * 256);
    float4* dst = (float4*)s_act;
    for (int i = tid; i < 32 * 64; i += 128) dst[i] = src[i];
    __syncthreads();
    if (tid < 98) {
        float acc[32];
#pragma unroll
        for (int p = 0; p < 32; p++) acc[p] = 0.f;
        for (int c = 0; c < 256; c++) {
            float w = W2[tid * 256 + c];
#pragma unroll
            for (int p = 0; p < 32; p++) acc[p] += w * s_act[p * 256 + c];
        }
#pragma unroll
        for (int p = 0; p < 32; p++) out[(pb + p) * 98 + tid] = acc[p];
    }
}

// ---------------- per-query prep --------------------------------------------
__global__ void __launch_bounds__(256) qprep_kernel(
    const float* __restrict__ coord, const float* __restrict__ inp,
    const float* __restrict__ bc1, const float* __restrict__ bc2)
{
    __shared__ float s_q[256];
    __shared__ float s_rel[98];
    __shared__ float s_av[49 * 8];
    __shared__ float s_wc[49];
    __shared__ float s_h[256];
    __shared__ int   s_kidx[49];

    const int q = blockIdx.x;
    const int tid = threadIdx.x, lane = tid & 31, wid = tid >> 5;
    const float cy = coord[q * 2 + 0], cx = coord[q * 2 + 1];
    const float gx = ((cx + 1.f) * 64.f - 1.f) * 0.5f;
    const float gy = ((cy + 1.f) * 64.f - 1.f) * 0.5f;

    {
        float x0f = floorf(gx), y0f = floorf(gy);
        int x0 = (int)x0f, y0 = (int)y0f;
        float wx = gx - x0f, wy = gy - y0f;
        float a = 0.f;
#pragma unroll
        for (int t = 0; t < 4; t++) {
            int ix = x0 + (t & 1), iy = y0 + (t >> 1);
            float w = ((t & 1) ? wx : 1.f - wx) * ((t >> 1) ? wy : 1.f - wy);
            bool m = (ix >= 0 && ix < 64 && iy >= 0 && iy < 64);
            int pc = min(max(iy, 0), 63) * 64 + min(max(ix, 0), 63);
            float v = g_fq[pc * 256 + tid];
            a += m ? w * v : 0.f;
        }
        s_q[tid] = a;
    }

    const int ix0 = __float2int_rn(gx), iy0 = __float2int_rn(gy);
    const bool m0 = (ix0 >= 0 && ix0 < 64 && iy0 >= 0 && iy0 < 64);
    const int pix0 = min(max(iy0, 0), 63) * 64 + min(max(ix0, 0), 63);
    const float yb = m0 ? (-1.f + 0.015625f + 0.03125f * (float)iy0) : 0.f;
    const float xb = m0 ? (-1.f + 0.015625f + 0.03125f * (float)ix0) : 0.f;

    if (tid < 49) {
        const int k = tid;
        float o0 = m0 ? g_offmap[pix0 * 98 + 2 * k] : 0.f;
        float o1 = m0 ? g_offmap[pix0 * 98 + 2 * k + 1] : 0.f;
        float sy = yb + (float)(k / 7 - 3) * 0.03125f + tanhf(o0) * (2.f / 63.f);
        float sx = xb + (float)(k % 7 - 3) * 0.03125f + tanhf(o1) * (2.f / 63.f);
        s_rel[2 * k] = (cy - sy) * 64.f;
        s_rel[2 * k + 1] = (cx - sx) * 64.f;
        float gky = ((sy + 1.f) * 64.f - 1.f) * 0.5f;
        float gkx = ((sx + 1.f) * 64.f - 1.f) * 0.5f;
        int iky = __float2int_rn(gky), ikx = __float2int_rn(gkx);
        bool ok = (ikx >= 0 && ikx < 64 && iky >= 0 && iky < 64);
        s_kidx[k] = ok ? iky * 64 + ikx : -1;
        g_kidx[q * 49 + k] = s_kidx[k];
    }
    __syncthreads();

    for (int k = wid; k < 49; k += 8) {
        int pix = s_kidx[k];
        int h = lane >> 2, part = lane & 3;
        float s = 0.f;
        if (pix >= 0) {
            const float* fr = g_fk + pix * 256 + h * 32 + part * 8;
            const float* qr = s_q + h * 32 + part * 8;
#pragma unroll
            for (int i = 0; i < 8; i++) s += fr[i] * qr[i];
        }
        s += __shfl_xor_sync(0xffffffffu, s, 1);
        s += __shfl_xor_sync(0xffffffffu, s, 2);
        if (part == 0) s_av[k * 8 + h] = s * 0.17677669529663687f;
    }

    {
        float h1 = bc1[tid];
        for (int i = 0; i < 98; i++) h1 += g_Wc1T[i * 256 + tid] * s_rel[i];
        s_h[tid] = fmaxf(h1, 0.f);
    }
    __syncthreads();

    if (tid < 49) {
        float w = bc2[tid];
        for (int j = 0; j < 256; j++) w += g_Wc2T[j * 49 + tid] * s_h[j];
        s_wc[tid] = w;
    }
    if (tid >= 64 && tid < 67) {
        const int c = tid - 64;
        float gxc = fminf(fmaxf(gx, 0.f), 63.f), gyc = fminf(fmaxf(gy, 0.f), 63.f);
        float x0f = floorf(gxc), y0f = floorf(gyc);
        int x0 = (int)x0f, y0 = (int)y0f;
        float wx = gxc - x0f, wy = gyc - y0f;
        int x1 = min(x0 + 1, 63), y1 = min(y0 + 1, 63);
        const float* I = inp + c * HW;
        g_skipv[q * 3 + c] = (1.f - wx) * (1.f - wy) * I[y0 * 64 + x0]
                           + wx * (1.f - wy) * I[y0 * 64 + x1]
                           + (1.f - wx) * wy * I[y1 * 64 + x0]
                           + wx * wy * I[y1 * 64 + x1];
    }
    __syncthreads();

    if (tid < 8) {
        const int h = tid;
        float mx = -1e30f;
        for (int k = 0; k < 49; k++) mx = fmaxf(mx, s_wc[k] + s_av[k * 8 + h]);
        float sum = 0.f;
        for (int k = 0; k < 49; k++) {
            float e = expf(s_wc[k] + s_av[k * 8 + h] - mx);
            s_av[k * 8 + h] = e;
            sum += e;
        }
        float inv = 1.f / sum;
        for (int k = 0; k < 49; k++) g_attn[(q * 49 + k) * 8 + h] = s_av[k * 8 + h] * inv;
    }
}

// ---------------- big GEMM via bf16 m16n8k16 --------------------------------
// grid 256, block 256. block: 32 q x 128 j. warp: 16q x 32j.
// smem words: s_a[32][132] + s_w[128][132] = 160*132 = 21120 w = 84480 B
__global__ void __launch_bounds__(256) gemm_kernel(
    const float* __restrict__ cell, const float* __restrict__ bi1,
    const float* __restrict__ Wi1)
{
    extern __shared__ unsigned smu[];
    unsigned* s_a = smu;             // [q][c-words], bf16x2
    unsigned* s_w = smu + 32 * 132;  // [j][c-words]
    __shared__ float s_cell[64];

    const int t = threadIdx.x;
    const int qb = (blockIdx.x >> 1) * 32;
    const int jh = (blockIdx.x & 1) * 128;
    const int lane = t & 31, w = t >> 5;
    const int r = lane >> 2, cl = lane & 3;
    const int warpM = w >> 2, warpJ = w & 3;
    const int bq = t >> 3, hx = t & 7;  // A-build: 32q x 8 heads

    if (t < 64) s_cell[t] = cell[qb * 2 + t];

    float cfrag[4][4];
#pragma unroll
    for (int nt = 0; nt < 4; nt++)
#pragma unroll
        for (int i = 0; i < 4; i++) cfrag[nt][i] = 0.f;

    for (int k = 0; k < 49; k++) {
        __syncthreads();
        { // build A: bf16x2(fv[pix][c] * attn)
            int pix = g_kidx[(qb + bq) * 49 + k];
            float aw = g_attn[((qb + bq) * 49 + k) * 8 + hx];
            if (pix < 0) aw = 0.f;
            const float4* fr = (const float4*)(g_fv + (pix < 0 ? 0 : pix) * 256) + hx * 8;
            uint2* dst = (uint2*)(s_a + bq * 132 + hx * 16);
#pragma unroll
            for (int i = 0; i < 8; i++) {
                float4 v = fr[i];
                uint2 o;
                o.x = pbf2(v.x * aw, v.y * aw);
                o.y = pbf2(v.z * aw, v.w * aw);
                dst[i] = o;
            }
        }
        { // stage whole W(k): 128 j x 128 words
            int j = t >> 1, seg = t & 1;
            const uint4* src = (const uint4*)(g_Wi1B + (jh + j) * 12560 + k * 256);
            uint4* d = (uint4*)(s_w + j * 132);
#pragma unroll
            for (int i = 0; i < 16; i++) d[seg * 16 + i] = src[seg * 16 + i];
        }
        __syncthreads();

#pragma unroll 2
        for (int sub = 0; sub < 8; sub++) {
#pragma unroll
            for (int ks = 0; ks < 2; ks++) {
                int wb = sub * 16 + ks * 8;
                int row = warpM * 16 + r;
                unsigned a[4];
                a[0] = s_a[row * 132 + wb + cl];
                a[1] = s_a[(row + 8) * 132 + wb + cl];
                a[2] = s_a[row * 132 + wb + cl + 4];
                a[3] = s_a[(row + 8) * 132 + wb + cl + 4];
#pragma unroll
                for (int nt = 0; nt < 4; nt++) {
                    int jrow = warpJ * 32 + nt * 8 + r;
                    unsigned b[2] = {s_w[jrow * 132 + wb + cl],
                                     s_w[jrow * 132 + wb + cl + 4]};
                    mma_bf16(cfrag[nt], a, b);
                }
            }
        }
    }

    // epilogue: h = relu(acc + bi1 + wc0*ry + wc1*rx) -> g_hidden
#pragma unroll
    for (int nt = 0; nt < 4; nt++) {
        int jg = jh + warpJ * 32 + nt * 8 + 2 * cl;
        float b0 = bi1[jg], b1 = bi1[jg + 1];
        float w00 = Wi1[jg * 12546 + 12544], w01 = Wi1[(jg + 1) * 12546 + 12544];
        float w10 = Wi1[jg * 12546 + 12545], w11 = Wi1[(jg + 1) * 12546 + 12545];
#pragma unroll
        for (int half = 0; half < 2; half++) {
            int q = warpM * 16 + r + half * 8;
            float ry = s_cell[q * 2 + 0] * 64.f, rx = s_cell[q * 2 + 1] * 64.f;
            float v0 = cfrag[nt][half * 2 + 0] + b0 + w00 * ry + w10 * rx;
            float v1 = cfrag[nt][half * 2 + 1] + b1 + w01 * ry + w11 * rx;
            g_hidden[(qb + q) * 256 + jg] = fmaxf(v0, 0.f);
            g_hidden[(qb + q) * 256 + jg + 1] = fmaxf(v1, 0.f);
        }
    }
}

// ---------------- final MLP 256->3 + skip -----------------------------------
__global__ void __launch_bounds__(128) fin_kernel(
    const float* __restrict__ Wi2, const float* __restrict__ bi2,
    float* __restrict__ out)
{
    __shared__ float s_h[32 * 260];
    __shared__ float s_w2[768];
    const int t = threadIdx.x;
    const int qb = blockIdx.x * 32;
    const float4* src = (const float4*)(g_hidden + qb * 256);
#pragma unroll
    for (int i = 0; i < 16; i++) {
        int fi = t + i * 128;
        int q = fi >> 6, jf = fi & 63;
        ((float4*)(s_h + q * 260))[jf] = src[fi];
    }
    for (int i = t; i < 768; i += 128) s_w2[i] = Wi2[i];
    __syncthreads();
    if (t < 96) {
        int q = t / 3, c = t % 3;
        float s = 0.f;
        for (int j = 0; j < 256; j++) s += s_h[q * 260 + j] * s_w2[c * 256 + j];
        out[(qb + q) * 3 + c] = s + bi2[c] + g_skipv[(qb + q) * 3 + c];
    }
}

// ---------------- host ------------------------------------------------------
extern "C" void kernel_launch(void* const* d_in, const int* in_sizes, int n_in,
                              void* d_out, int out_size)
{
    const float* inp   = (const float*)d_in[0];
    const float* coord = (const float*)d_in[1];
    const float* cell  = (const float*)d_in[2];
    const float* W_enc = (const float*)d_in[3];
    const float* b_enc = (const float*)d_in[4];
    const float* W_ch  = (const float*)d_in[5];
    const float* b_ch  = (const float*)d_in[6];
    const float* W_q   = (const float*)d_in[7];
    const float* b_q   = (const float*)d_in[8];
    const float* W_k   = (const float*)d_in[9];
    const float* b_k   = (const float*)d_in[10];
    const float* W_v   = (const float*)d_in[11];
    const float* b_v   = (const float*)d_in[12];
    const float* W_off1= (const float*)d_in[13];
    const float* b_off1= (const float*)d_in[14];
    const float* ln_g  = (const float*)d_in[15];
    const float* ln_b  = (const float*)d_in[16];
    const float* W_off2= (const float*)d_in[17];
    const float* Wc1   = (const float*)d_in[18];
    const float* bc1   = (const float*)d_in[19];
    const float* Wc2   = (const float*)d_in[20];
    const float* bc2   = (const float*)d_in[21];
    const float* Wi1   = (const float*)d_in[22];
    const float* bi1   = (const float*)d_in[23];
    const float* Wi2   = (const float*)d_in[24];
    const float* bi2   = (const float*)d_in[25];
    float* out = (float*)d_out;

    void* p;
    cudaGetSymbolAddress(&p, g_enc);     float* enc = (float*)p;
    cudaGetSymbolAddress(&p, g_feat);    float* feat = (float*)p;
    cudaGetSymbolAddress(&p, g_fq);      float* fq = (float*)p;
    cudaGetSymbolAddress(&p, g_fk);      float* fk = (float*)p;
    cudaGetSymbolAddress(&p, g_fv);      float* fv = (float*)p;
    cudaGetSymbolAddress(&p, g_off1);    float* off1 = (float*)p;
    cudaGetSymbolAddress(&p, g_act);     float* act = (float*)p;
    cudaGetSymbolAddress(&p, g_offmap);  float* offmap = (float*)p;
    cudaGetSymbolAddress(&p, g_Wc1T);    float* wc1t = (float*)p;
    cudaGetSymbolAddress(&p, g_Wc2T);    float* wc2t = (float*)p;
    cudaGetSymbolAddress(&p, g_WchT);    float* wcht = (float*)p;
    cudaGetSymbolAddress(&p, g_W5T);     float* w5t = (float*)p;

    cudaFuncSetAttribute(convmma_ch_kernel<64>, cudaFuncAttributeMaxDynamicSharedMemorySize, 47232);
    cudaFuncSetAttribute(convmma_qkv_kernel, cudaFuncAttributeMaxDynamicSharedMemorySize, 28800);
    cudaFuncSetAttribute(convmma5_kernel, cudaFuncAttributeMaxDynamicSharedMemorySize, 67968);
    cudaFuncSetAttribute(gemm_kernel, cudaFuncAttributeMaxDynamicSharedMemorySize, 84480);

    dim3 tb(32, 8);
    wtrans2_kernel<<<dim3(9 * 256, 4), 256>>>(W_ch, W_q, W_k, W_v);              // 1
    conv3x3_kernel<3, 64, true><<<dim3(4, 4, 4), 128>>>(inp, W_enc, b_enc, enc); // 2
    convmma_ch_kernel<64><<<dim3(32, 8), 256, 47232>>>(enc, wcht, b_ch, feat);   // 3
    convmma_qkv_kernel<<<dim3(32, 8), 256, 28800>>>(feat, b_q, b_k, b_v,
                                                    fq, fk, fv);                 // 4 <- profiled
    wtrans5_kernel<<<dim3(25, 8), dim3(32, 32)>>>(W_off1, w5t);                  // 5
    convmma5_kernel<<<dim3(32, 8), 256, 67968>>>(feat, w5t, b_off1, off1);       // 6
    wi1b_kernel<<<256, 256>>>(Wi1);                                              // 7
    transpose_kernel<<<dim3(4, 8), tb>>>(Wc1, wc1t, 256, 98, 0);                 // 8
    transpose_kernel<<<dim3(8, 2), tb>>>(Wc2, wc2t, 49, 256, 0);                 // 9
    ln_gelu_kernel<<<512, 256>>>(off1, ln_g, ln_b, act);                         // 10
    conv1x1_kernel<<<128, 128>>>(act, W_off2, offmap);                           // 11
    qprep_kernel<<<4096, 256>>>(coord, inp, bc1, bc2);                           // 12
    gemm_kernel<<<256, 256, 84480>>>(cell, bi1, Wi1);                            // 13
    fin_kernel<<<128, 128>>>(Wi2, bi2, out);                                     // 14
}

// round 17
// speedup vs baseline: 2.3433x; 1.0238x over previous
#include <cuda_runtime.h>
#include <cuda_bf16.h>
#include <math.h>

#define HW 4096

__device__ float g_enc[64 * HW];
__device__ float g_feat[256 * HW];
__device__ float g_fq[HW * 256];
__device__ float g_fk[HW * 256];
__device__ float g_fv[HW * 256];
__device__ float g_off1[HW * 256];
__device__ float g_act[HW * 256];
__device__ float g_offmap[HW * 98];
__device__ float g_attn[4096 * 49 * 8];
__device__ int   g_kidx[4096 * 49];
__device__ float g_skipv[4096 * 3];
__device__ float g_hidden[4096 * 256];
__device__ float g_Wc1T[98 * 256];
__device__ float g_Wc2T[256 * 49];
__device__ float g_WchT[9 * 64 * 256];          // tf32 [tap][ci][co]
__device__ float g_W5T[25 * 8 * 32 * 32];       // tf32
__device__ __nv_bfloat16 g_WqB[9 * 256 * 256];  // bf16 [tap][co][ci]
__device__ __nv_bfloat16 g_WkB[9 * 256 * 256];
__device__ __nv_bfloat16 g_WvB[9 * 256 * 256];
__device__ __nv_bfloat16 g_Wi1B[256 * 12560];   // bf16 [j][c], padded rows

__device__ __forceinline__ float totf32(float x) {
    float r; asm("cvt.rna.tf32.f32 %0, %1;" : "=f"(r) : "f"(x)); return r;
}
// pack two fp32 -> bf16x2 word, lo in bits[15:0]
__device__ __forceinline__ unsigned pbf2(float lo, float hi) {
    unsigned r; asm("cvt.rn.bf16x2.f32 %0, %1, %2;" : "=r"(r) : "f"(hi), "f"(lo)); return r;
}
__device__ __forceinline__ void mma_tf32(float* c, const unsigned* a, const unsigned* b) {
    asm volatile("mma.sync.aligned.m16n8k8.row.col.f32.tf32.tf32.f32 "
        "{%0,%1,%2,%3}, {%4,%5,%6,%7}, {%8,%9}, {%0,%1,%2,%3};"
        : "+f"(c[0]), "+f"(c[1]), "+f"(c[2]), "+f"(c[3])
        : "r"(a[0]), "r"(a[1]), "r"(a[2]), "r"(a[3]), "r"(b[0]), "r"(b[1]));
}
__device__ __forceinline__ void mma_bf16(float* c, const unsigned* a, const unsigned* b) {
    asm volatile("mma.sync.aligned.m16n8k16.row.col.f32.bf16.bf16.f32 "
        "{%0,%1,%2,%3}, {%4,%5,%6,%7}, {%8,%9}, {%0,%1,%2,%3};"
        : "+f"(c[0]), "+f"(c[1]), "+f"(c[2]), "+f"(c[3])
        : "r"(a[0]), "r"(a[1]), "r"(a[2]), "r"(a[3]), "r"(b[0]), "r"(b[1]));
}

// ---------------- transpose (tf32 optional) for Wc1/Wc2 ---------------------
__global__ void transpose_kernel(const float* __restrict__ src, float* __restrict__ dst,
                                 int rows, int cols, int tf32)
{
    __shared__ float tile[32][33];
    int c0 = blockIdx.x * 32, r0 = blockIdx.y * 32;
    int tx = threadIdx.x, ty = threadIdx.y;
#pragma unroll
    for (int i = 0; i < 32; i += 8) {
        int r = r0 + ty + i, c = c0 + tx;
        tile[ty + i][tx] = (r < rows && c < cols) ? src[r * cols + c] : 0.f;
    }
    __syncthreads();
#pragma unroll
    for (int i = 0; i < 32; i += 8) {
        int r = c0 + ty + i, c = r0 + tx;
        if (r < cols && c < rows) {
            float v = tile[tx][ty + i];
            if (tf32) v = totf32(v);
            dst[r * rows + c] = v;
        }
    }
}

// ---------------- conv weight transforms ------------------------------------
__global__ void wtrans2_kernel(
    const float* __restrict__ Wch, const float* __restrict__ Wq,
    const float* __restrict__ Wk, const float* __restrict__ Wv)
{
    const int which = blockIdx.y, bx = blockIdx.x, t = threadIdx.x;
    if (which == 0) {
        int tap = bx / 256, ci = bx % 256;
        if (ci < 64)
            g_WchT[(tap * 64 + ci) * 256 + t] = totf32(Wch[t * 64 * 9 + ci * 9 + tap]);
    } else {
        int tap = bx / 256, co = bx % 256;
        const float* W = (which == 1) ? Wq : (which == 2) ? Wk : Wv;
        __nv_bfloat16* T = (which == 1) ? g_WqB : (which == 2) ? g_WkB : g_WvB;
        T[(tap * 256 + co) * 256 + t] = __float2bfloat16(W[co * 256 * 9 + t * 9 + tap]);
    }
}

__global__ void wtrans5_kernel(const float* __restrict__ W, float* __restrict__ T5)
{
    int tap = blockIdx.x, g = blockIdx.y;
    int ci = threadIdx.y, co = threadIdx.x;
    T5[((tap * 8 + g) * 32 + ci) * 32 + co] =
        totf32(W[(g * 32 + co) * 32 * 25 + ci * 25 + tap]);
}

// Wi1 fp32 [j][12546] -> bf16 [j][12560] (padded row)
__global__ void wi1b_kernel(const float* __restrict__ Wi1)
{
    int j = blockIdx.x;
    for (int c = threadIdx.x; c < 12546; c += 256)
        g_Wi1B[j * 12560 + c] = __float2bfloat16(Wi1[j * 12546 + c]);
}

// ---------------- 3x3 conv via tf32 mma, ch variant (unchanged) -------------
template <int CIN>
__global__ void __launch_bounds__(256, 2) convmma_ch_kernel(
    const float* __restrict__ in, const float* __restrict__ T,
    const float* __restrict__ B, float* __restrict__ out)
{
    extern __shared__ float smx[];
    float* s_feat = smx;
    float* s_w = smx + 9504;

    const int t = threadIdx.x;
    const int s = blockIdx.x;
    const int cobase = blockIdx.y * 32;
    const int w = t >> 5, lane = t & 31;
    const int r = lane >> 2, cl = lane & 3;
    const int wrow = w >> 2;
    const int x0 = (w & 3) * 16;

    float cfrag[4][4];
#pragma unroll
    for (int nt = 0; nt < 4; nt++)
#pragma unroll
        for (int i = 0; i < 4; i++) cfrag[nt][i] = 0.f;

    for (int cb = 0; cb < CIN; cb += 32) {
        __syncthreads();
        for (int i = t; i < 4 * 66 * 32; i += 256) {
            int tmp = i / 66, h = i - tmp * 66;
            int ci = tmp & 31, ry = tmp >> 5;
            int row = 2 * s - 1 + ry, x = h - 1;
            float v = 0.f;
            if ((unsigned)row < 64u && (unsigned)x < 64u)
                v = in[(cb + ci) * HW + row * 64 + x];
            s_feat[(ry * 66 + h) * 36 + ci] = v;
        }
#pragma unroll
        for (int tap = 0; tap < 9; tap++) {
            const int dy = tap / 3, dx = tap % 3;
            __syncthreads();
            {
                int ci = t >> 3, co4 = t & 7;
                ((float4*)(s_w + ci * 72))[co4] =
                    ((const float4*)(T + (tap * CIN + cb + ci) * 256 + cobase))[co4];
            }
            __syncthreads();
            const int rb = (wrow + dy) * 66 + x0 + dx;
#pragma unroll
            for (int ks = 0; ks < 4; ks++) {
                int c0 = ks * 8;
                unsigned ah[4];
                ah[0] = __float_as_uint(totf32(s_feat[(rb + r) * 36 + c0 + cl]));
                ah[1] = __float_as_uint(totf32(s_feat[(rb + r + 8) * 36 + c0 + cl]));
                ah[2] = __float_as_uint(totf32(s_feat[(rb + r) * 36 + c0 + cl + 4]));
                ah[3] = __float_as_uint(totf32(s_feat[(rb + r + 8) * 36 + c0 + cl + 4]));
#pragma unroll
                for (int nt = 0; nt < 4; nt++) {
                    int co = nt * 8 + r;
                    unsigned bh[2] = {__float_as_uint(s_w[(c0 + cl) * 72 + co]),
                                      __float_as_uint(s_w[(c0 + cl + 4) * 72 + co])};
                    mma_tf32(cfrag[nt], ah, bh);
                }
            }
        }
    }
    const int pixrow = (2 * s + wrow) * 64 + x0;
#pragma unroll
    for (int nt = 0; nt < 4; nt++)
#pragma unroll
        for (int i = 0; i < 4; i++) {
            int m = r + (i >> 1) * 8;
            int co = cobase + nt * 8 + 2 * cl + (i & 1);
            out[co * HW + pixrow + m] = cfrag[nt][i] + B[co];
        }
}

// ---------------- fused q/k/v 3x3 conv via bf16 mma, hoisted weights --------
// grid (32 strips, 8), block 256.
// smem words: s_feat 4*66*20=5280 + s_w 3*9*32*20=17280 -> 90240 B
__global__ void __launch_bounds__(256, 2) convmma_qkv_kernel(
    const float* __restrict__ in,
    const float* __restrict__ Bq, const float* __restrict__ Bk, const float* __restrict__ Bv,
    float* __restrict__ outq, float* __restrict__ outk, float* __restrict__ outv)
{
    extern __shared__ unsigned smu[];
    unsigned* s_feat = smu;          // [(ry*66+h)*20 + wd], wd = ci word (2 ci)
    unsigned* s_w = smu + 5280;      // [cv][tap][co][20] (16 words used)

    const int t = threadIdx.x;
    const int s = blockIdx.x;
    const int cobase = blockIdx.y * 32;
    const int w = t >> 5, lane = t & 31;
    const int r = lane >> 2, cl = lane & 3;
    const int wrow = w >> 2;
    const int x0 = (w & 3) * 16;

    float cfrag[3][4][4];
#pragma unroll
    for (int cv = 0; cv < 3; cv++)
#pragma unroll
        for (int nt = 0; nt < 4; nt++)
#pragma unroll
            for (int i = 0; i < 4; i++) cfrag[cv][nt][i] = 0.f;

    for (int cb = 0; cb < 256; cb += 32) {
        __syncthreads();
        // stage feat as bf16x2 words; h fastest for coalesced global reads
        for (int i = t; i < 4 * 16 * 66; i += 256) {
            int h = i % 66, tmp = i / 66;
            int wd = tmp & 15, ry = tmp >> 4;
            int row = 2 * s - 1 + ry, x = h - 1;
            float v0 = 0.f, v1 = 0.f;
            if ((unsigned)row < 64u && (unsigned)x < 64u) {
                v0 = in[(cb + 2 * wd) * HW + row * 64 + x];
                v1 = in[(cb + 2 * wd + 1) * HW + row * 64 + x];
            }
            s_feat[(ry * 66 + h) * 20 + wd] = pbf2(v0, v1);
        }
        // stage ALL 9 taps x 3 convs weights for this cb: 3456 uint4
        for (int i = t; i < 3456; i += 256) {
            int seg = i & 3;
            int q4 = i >> 2;                 // 0..863
            int co = q4 & 31;
            int tq = q4 >> 5;                // 0..26
            int tap = tq % 9, cv = tq / 9;
            const __nv_bfloat16* T = (cv == 0) ? g_WqB : (cv == 1) ? g_WkB : g_WvB;
            const uint4* src = (const uint4*)(T + (tap * 256 + cobase + co) * 256 + cb);
            ((uint4*)(s_w + ((cv * 9 + tap) * 32 + co) * 20))[seg] = src[seg];
        }
        __syncthreads();
#pragma unroll
        for (int tap = 0; tap < 9; tap++) {
            const int dy = tap / 3, dx = tap % 3;
            const int rb = (wrow + dy) * 66 + x0 + dx;
#pragma unroll
            for (int ks = 0; ks < 2; ks++) {
                int wb = ks * 8;
                unsigned ah[4];
                ah[0] = s_feat[(rb + r) * 20 + wb + cl];
                ah[1] = s_feat[(rb + r + 8) * 20 + wb + cl];
                ah[2] = s_feat[(rb + r) * 20 + wb + cl + 4];
                ah[3] = s_feat[(rb + r + 8) * 20 + wb + cl + 4];
#pragma unroll
                for (int cv = 0; cv < 3; cv++) {
                    const unsigned* wbase = s_w + (cv * 9 + tap) * 32 * 20;
#pragma unroll
                    for (int nt = 0; nt < 4; nt++) {
                        int co = nt * 8 + r;
                        unsigned bh[2] = {wbase[co * 20 + wb + cl],
                                          wbase[co * 20 + wb + cl + 4]};
                        mma_bf16(cfrag[cv][nt], ah, bh);
                    }
                }
            }
        }
    }
    const int pixrow = (2 * s + wrow) * 64 + x0;
#pragma unroll
    for (int cv = 0; cv < 3; cv++) {
        float* outp = (cv == 0) ? outq : (cv == 1) ? outk : outv;
        const float* Bp = (cv == 0) ? Bq : (cv == 1) ? Bk : Bv;
#pragma unroll
        for (int nt = 0; nt < 4; nt++)
#pragma unroll
            for (int i = 0; i < 4; i++) {
                int m = r + (i >> 1) * 8;
                int co = cobase + nt * 8 + 2 * cl + (i & 1);
                outp[(pixrow + m) * 256 + co] = cfrag[cv][nt][i] + Bp[co];
            }
    }
}

// ---------------- grouped 5x5 via tf32 mma (unchanged) ----------------------
__global__ void __launch_bounds__(256, 2) convmma5_kernel(
    const float* __restrict__ in, const float* __restrict__ T5,
    const float* __restrict__ B, float* __restrict__ out)
{
    extern __shared__ float smx[];
    float* s_feat = smx;
    float* s_w = smx + 14688;

    const int t = threadIdx.x;
    const int s = blockIdx.x;
    const int g = blockIdx.y;
    const int w = t >> 5, lane = t & 31;
    const int r = lane >> 2, cl = lane & 3;
    const int wrow = w >> 2;
    const int x0 = (w & 3) * 16;

    float cfrag[4][4];
#pragma unroll
    for (int nt = 0; nt < 4; nt++)
#pragma unroll
        for (int i = 0; i < 4; i++) cfrag[nt][i] = 0.f;

    for (int i = t; i < 6 * 68 * 32; i += 256) {
        int tmp = i / 68, h = i - tmp * 68;
        int ci = tmp & 31, ry = tmp >> 5;
        int row = 2 * s - 2 + ry, x = h - 2;
        float v = 0.f;
        if ((unsigned)row < 64u && (unsigned)x < 64u)
            v = in[(g * 32 + ci) * HW + row * 64 + x];
        s_feat[(ry * 68 + h) * 36 + ci] = v;
    }
    __syncthreads();

    for (int tap = 0; tap < 25; tap++) {
        const int dy = tap / 5, dx = tap % 5;
        if (tap) __syncthreads();
        {
            int ci = t >> 3, co4 = t & 7;
            ((float4*)(s_w + ci * 72))[co4] =
                ((const float4*)(T5 + ((tap * 8 + g) * 32) * 32))[t];
        }
        __syncthreads();
        const int rb = (wrow + dy) * 68 + x0 + dx;
#pragma unroll
        for (int ks = 0; ks < 4; ks++) {
            int c0 = ks * 8;
            unsigned ah[4];
            ah[0] = __float_as_uint(totf32(s_feat[(rb + r) * 36 + c0 + cl]));
            ah[1] = __float_as_uint(totf32(s_feat[(rb + r + 8) * 36 + c0 + cl]));
            ah[2] = __float_as_uint(totf32(s_feat[(rb + r) * 36 + c0 + cl + 4]));
            ah[3] = __float_as_uint(totf32(s_feat[(rb + r + 8) * 36 + c0 + cl + 4]));
#pragma unroll
            for (int nt = 0; nt < 4; nt++) {
                int co = nt * 8 + r;
                unsigned bh[2] = {__float_as_uint(s_w[(c0 + cl) * 72 + co]),
                                  __float_as_uint(s_w[(c0 + cl + 4) * 72 + co])};
                mma_tf32(cfrag[nt], ah, bh);
            }
        }
    }
    const int pixrow = (2 * s + wrow) * 64 + x0;
#pragma unroll
    for (int nt = 0; nt < 4; nt++)
#pragma unroll
        for (int i = 0; i < 4; i++) {
            int m = r + (i >> 1) * 8;
            int co = g * 32 + nt * 8 + 2 * cl + (i & 1);
            out[(pixrow + m) * 256 + co] = cfrag[nt][i] + B[co];
        }
}

// ---------------- scalar 3x3 conv (enc only) --------------------------------
template <int CIN, int COUT, bool RELU>
__global__ void __launch_bounds__(128) conv3x3_kernel(
    const float* __restrict__ in, const float* __restrict__ W,
    const float* __restrict__ B, float* __restrict__ out)
{
    __shared__ float s_in[18 * 18];
    __shared__ float s_w[16 * 9];
    const int tid = threadIdx.x;
    const int cog = tid >> 6, qid = tid & 63;
    const int qy = qid >> 3, qx = qid & 7;
    const int ty0 = blockIdx.y * 16, tx0 = blockIdx.x * 16;
    const int cobase = blockIdx.z * 16;

    int l_src[3]; bool l_ok[3];
#pragma unroll
    for (int t = 0; t < 3; t++) {
        int i = tid + t * 128; l_ok[t] = false; l_src[t] = 0;
        if (i < 324) {
            int r = i / 18, c = i % 18;
            int y = ty0 + r - 1, x = tx0 + c - 1;
            l_ok[t] = (y >= 0 && y < 64 && x >= 0 && x < 64);
            l_src[t] = y * 64 + x;
        }
    }
    float acc[2][2][8];
#pragma unroll
    for (int a = 0; a < 2; a++)
#pragma unroll
        for (int b = 0; b < 2; b++)
#pragma unroll
            for (int j = 0; j < 8; j++) acc[a][b][j] = 0.f;

    for (int ci = 0; ci < CIN; ci++) {
        const float* inc = in + ci * HW;
#pragma unroll
        for (int t = 0; t < 3; t++) {
            int i = tid + t * 128;
            if (i < 324) s_in[i] = l_ok[t] ? inc[l_src[t]] : 0.f;
        }
#pragma unroll
        for (int i = tid; i < 144; i += 128)
            s_w[i] = W[((cobase + i / 9) * CIN + ci) * 9 + i % 9];
        __syncthreads();
        float p[4][4];
#pragma unroll
        for (int r = 0; r < 4; r++)
#pragma unroll
            for (int c = 0; c < 4; c++)
                p[r][c] = s_in[(qy * 2 + r) * 18 + qx * 2 + c];
#pragma unroll
        for (int j = 0; j < 8; j++) {
            const float* w = &s_w[(cog * 8 + j) * 9];
#pragma unroll
            for (int oy = 0; oy < 2; oy++)
#pragma unroll
                for (int ox = 0; ox < 2; ox++)
                    acc[oy][ox][j] += w[0]*p[oy][ox]   + w[1]*p[oy][ox+1]   + w[2]*p[oy][ox+2]
                                    + w[3]*p[oy+1][ox] + w[4]*p[oy+1][ox+1] + w[5]*p[oy+1][ox+2]
                                    + w[6]*p[oy+2][ox] + w[7]*p[oy+2][ox+1] + w[8]*p[oy+2][ox+2];
        }
        __syncthreads();
    }
#pragma unroll
    for (int oy = 0; oy < 2; oy++)
#pragma unroll
        for (int ox = 0; ox < 2; ox++) {
            int pix = (ty0 + qy * 2 + oy) * 64 + tx0 + qx * 2 + ox;
#pragma unroll
            for (int j = 0; j < 8; j++) {
                int co = cobase + cog * 8 + j;
                float v = acc[oy][ox][j] + B[co];
                if (RELU) v = fmaxf(v, 0.f);
                out[co * HW + pix] = v;
            }
        }
}

// ---------------- LayerNorm + exact GELU ------------------------------------
__global__ void __launch_bounds__(256) ln_gelu_kernel(
    const float* __restrict__ in, const float* __restrict__ gam,
    const float* __restrict__ bet, float* __restrict__ out)
{
    const int lane = threadIdx.x & 31, wid = threadIdx.x >> 5;
    const int pix = blockIdx.x * 8 + wid;
    float x[8];
#pragma unroll
    for (int i = 0; i < 8; i++) x[i] = in[pix * 256 + i * 32 + lane];
    float s = 0.f;
#pragma unroll
    for (int i = 0; i < 8; i++) s += x[i];
#pragma unroll
    for (int o = 16; o; o >>= 1) s += __shfl_xor_sync(0xffffffffu, s, o);
    float mu = s * (1.f / 256.f);
    float d = 0.f;
#pragma unroll
    for (int i = 0; i < 8; i++) { float t = x[i] - mu; d += t * t; }
#pragma unroll
    for (int o = 16; o; o >>= 1) d += __shfl_xor_sync(0xffffffffu, d, o);
    float inv = rsqrtf(d * (1.f / 256.f) + 1e-5f);
#pragma unroll
    for (int i = 0; i < 8; i++) {
        int c = i * 32 + lane;
        float y = (x[i] - mu) * inv * gam[c] + bet[c];
        out[pix * 256 + c] = 0.5f * y * (1.f + erff(y * 0.70710678118654752f));
    }
}

// ---------------- 1x1 conv 256->98 ------------------------------------------
__global__ void __launch_bounds__(128) conv1x1_kernel(
    const float* __restrict__ act, const float* __restrict__ W2, float* __restrict__ out)
{
    __shared__ float s_act[32 * 256];
    const int tid = threadIdx.x;
    const int pb = blockIdx.x * 32;
    const float4* src = (const float4*)(act + pb * 256);
    float4* dst = (float4*)s_act;
    for (int i = tid; i < 32 * 64; i += 128) dst[i] = src[i];
    __syncthreads();
    if (tid < 98) {
        float acc[32];
#pragma unroll
        for (int p = 0; p < 32; p++) acc[p] = 0.f;
        for (int c = 0; c < 256; c++) {
            float w = W2[tid * 256 + c];
#pragma unroll
            for (int p = 0; p < 32; p++) acc[p] += w * s_act[p * 256 + c];
        }
#pragma unroll
        for (int p = 0; p < 32; p++) out[(pb + p) * 98 + tid] = acc[p];
    }
}

// ---------------- per-query prep --------------------------------------------
__global__ void __launch_bounds__(256) qprep_kernel(
    const float* __restrict__ coord, const float* __restrict__ inp,
    const float* __restrict__ bc1, const float* __restrict__ bc2)
{
    __shared__ float s_q[256];
    __shared__ float s_rel[98];
    __shared__ float s_av[49 * 8];
    __shared__ float s_wc[49];
    __shared__ float s_h[256];
    __shared__ int   s_kidx[49];

    const int q = blockIdx.x;
    const int tid = threadIdx.x, lane = tid & 31, wid = tid >> 5;
    const float cy = coord[q * 2 + 0], cx = coord[q * 2 + 1];
    const float gx = ((cx + 1.f) * 64.f - 1.f) * 0.5f;
    const float gy = ((cy + 1.f) * 64.f - 1.f) * 0.5f;

    {
        float x0f = floorf(gx), y0f = floorf(gy);
        int x0 = (int)x0f, y0 = (int)y0f;
        float wx = gx - x0f, wy = gy - y0f;
        float a = 0.f;
#pragma unroll
        for (int t = 0; t < 4; t++) {
            int ix = x0 + (t & 1), iy = y0 + (t >> 1);
            float w = ((t & 1) ? wx : 1.f - wx) * ((t >> 1) ? wy : 1.f - wy);
            bool m = (ix >= 0 && ix < 64 && iy >= 0 && iy < 64);
            int pc = min(max(iy, 0), 63) * 64 + min(max(ix, 0), 63);
            float v = g_fq[pc * 256 + tid];
            a += m ? w * v : 0.f;
        }
        s_q[tid] = a;
    }

    const int ix0 = __float2int_rn(gx), iy0 = __float2int_rn(gy);
    const bool m0 = (ix0 >= 0 && ix0 < 64 && iy0 >= 0 && iy0 < 64);
    const int pix0 = min(max(iy0, 0), 63) * 64 + min(max(ix0, 0), 63);
    const float yb = m0 ? (-1.f + 0.015625f + 0.03125f * (float)iy0) : 0.f;
    const float xb = m0 ? (-1.f + 0.015625f + 0.03125f * (float)ix0) : 0.f;

    if (tid < 49) {
        const int k = tid;
        float o0 = m0 ? g_offmap[pix0 * 98 + 2 * k] : 0.f;
        float o1 = m0 ? g_offmap[pix0 * 98 + 2 * k + 1] : 0.f;
        float sy = yb + (float)(k / 7 - 3) * 0.03125f + tanhf(o0) * (2.f / 63.f);
        float sx = xb + (float)(k % 7 - 3) * 0.03125f + tanhf(o1) * (2.f / 63.f);
        s_rel[2 * k] = (cy - sy) * 64.f;
        s_rel[2 * k + 1] = (cx - sx) * 64.f;
        float gky = ((sy + 1.f) * 64.f - 1.f) * 0.5f;
        float gkx = ((sx + 1.f) * 64.f - 1.f) * 0.5f;
        int iky = __float2int_rn(gky), ikx = __float2int_rn(gkx);
        bool ok = (ikx >= 0 && ikx < 64 && iky >= 0 && iky < 64);
        s_kidx[k] = ok ? iky * 64 + ikx : -1;
        g_kidx[q * 49 + k] = s_kidx[k];
    }
    __syncthreads();

    for (int k = wid; k < 49; k += 8) {
        int pix = s_kidx[k];
        int h = lane >> 2, part = lane & 3;
        float s = 0.f;
        if (pix >= 0) {
            const float* fr = g_fk + pix * 256 + h * 32 + part * 8;
            const float* qr = s_q + h * 32 + part * 8;
#pragma unroll
            for (int i = 0; i < 8; i++) s += fr[i] * qr[i];
        }
        s += __shfl_xor_sync(0xffffffffu, s, 1);
        s += __shfl_xor_sync(0xffffffffu, s, 2);
        if (part == 0) s_av[k * 8 + h] = s * 0.17677669529663687f;
    }

    {
        float h1 = bc1[tid];
        for (int i = 0; i < 98; i++) h1 += g_Wc1T[i * 256 + tid] * s_rel[i];
        s_h[tid] = fmaxf(h1, 0.f);
    }
    __syncthreads();

    if (tid < 49) {
        float w = bc2[tid];
        for (int j = 0; j < 256; j++) w += g_Wc2T[j * 49 + tid] * s_h[j];
        s_wc[tid] = w;
    }
    if (tid >= 64 && tid < 67) {
        const int c = tid - 64;
        float gxc = fminf(fmaxf(gx, 0.f), 63.f), gyc = fminf(fmaxf(gy, 0.f), 63.f);
        float x0f = floorf(gxc), y0f = floorf(gyc);
        int x0 = (int)x0f, y0 = (int)y0f;
        float wx = gxc - x0f, wy = gyc - y0f;
        int x1 = min(x0 + 1, 63), y1 = min(y0 + 1, 63);
        const float* I = inp + c * HW;
        g_skipv[q * 3 + c] = (1.f - wx) * (1.f - wy) * I[y0 * 64 + x0]
                           + wx * (1.f - wy) * I[y0 * 64 + x1]
                           + (1.f - wx) * wy * I[y1 * 64 + x0]
                           + wx * wy * I[y1 * 64 + x1];
    }
    __syncthreads();

    if (tid < 8) {
        const int h = tid;
        float mx = -1e30f;
        for (int k = 0; k < 49; k++) mx = fmaxf(mx, s_wc[k] + s_av[k * 8 + h]);
        float sum = 0.f;
        for (int k = 0; k < 49; k++) {
            float e = expf(s_wc[k] + s_av[k * 8 + h] - mx);
            s_av[k * 8 + h] = e;
            sum += e;
        }
        float inv = 1.f / sum;
        for (int k = 0; k < 49; k++) g_attn[(q * 49 + k) * 8 + h] = s_av[k * 8 + h] * inv;
    }
}

// ---------------- big GEMM via bf16 m16n8k16 (unchanged) --------------------
// grid 256, block 256. block: 32 q x 128 j. warp: 16q x 32j.
__global__ void __launch_bounds__(256) gemm_kernel(
    const float* __restrict__ cell, const float* __restrict__ bi1,
    const float* __restrict__ Wi1)
{
    extern __shared__ unsigned smu[];
    unsigned* s_a = smu;             // [q][c-words], bf16x2
    unsigned* s_w = smu + 32 * 132;  // [j][c-words]
    __shared__ float s_cell[64];

    const int t = threadIdx.x;
    const int qb = (blockIdx.x >> 1) * 32;
    const int jh = (blockIdx.x & 1) * 128;
    const int lane = t & 31, w = t >> 5;
    const int r = lane >> 2, cl = lane & 3;
    const int warpM = w >> 2, warpJ = w & 3;
    const int bq = t >> 3, hx = t & 7;  // A-build: 32q x 8 heads

    if (t < 64) s_cell[t] = cell[qb * 2 + t];

    float cfrag[4][4];
#pragma unroll
    for (int nt = 0; nt < 4; nt++)
#pragma unroll
        for (int i = 0; i < 4; i++) cfrag[nt][i] = 0.f;

    for (int k = 0; k < 49; k++) {
        __syncthreads();
        { // build A: bf16x2(fv[pix][c] * attn)
            int pix = g_kidx[(qb + bq) * 49 + k];
            float aw = g_attn[((qb + bq) * 49 + k) * 8 + hx];
            if (pix < 0) aw = 0.f;
            const float4* fr = (const float4*)(g_fv + (pix < 0 ? 0 : pix) * 256) + hx * 8;
            uint2* dst = (uint2*)(s_a + bq * 132 + hx * 16);
#pragma unroll
            for (int i = 0; i < 8; i++) {
                float4 v = fr[i];
                uint2 o;
                o.x = pbf2(v.x * aw, v.y * aw);
                o.y = pbf2(v.z * aw, v.w * aw);
                dst[i] = o;
            }
        }
        { // stage whole W(k): 128 j x 128 words
            int j = t >> 1, seg = t & 1;
            const uint4* src = (const uint4*)(g_Wi1B + (jh + j) * 12560 + k * 256);
            uint4* d = (uint4*)(s_w + j * 132);
#pragma unroll
            for (int i = 0; i < 16; i++) d[seg * 16 + i] = src[seg * 16 + i];
        }
        __syncthreads();

#pragma unroll 2
        for (int sub = 0; sub < 8; sub++) {
#pragma unroll
            for (int ks = 0; ks < 2; ks++) {
                int wb = sub * 16 + ks * 8;
                int row = warpM * 16 + r;
                unsigned a[4];
                a[0] = s_a[row * 132 + wb + cl];
                a[1] = s_a[(row + 8) * 132 + wb + cl];
                a[2] = s_a[row * 132 + wb + cl + 4];
                a[3] = s_a[(row + 8) * 132 + wb + cl + 4];
#pragma unroll
                for (int nt = 0; nt < 4; nt++) {
                    int jrow = warpJ * 32 + nt * 8 + r;
                    unsigned b[2] = {s_w[jrow * 132 + wb + cl],
                                     s_w[jrow * 132 + wb + cl + 4]};
                    mma_bf16(cfrag[nt], a, b);
                }
            }
        }
    }

#pragma unroll
    for (int nt = 0; nt < 4; nt++) {
        int jg = jh + warpJ * 32 + nt * 8 + 2 * cl;
        float b0 = bi1[jg], b1 = bi1[jg + 1];
        float w00 = Wi1[jg * 12546 + 12544], w01 = Wi1[(jg + 1) * 12546 + 12544];
        float w10 = Wi1[jg * 12546 + 12545], w11 = Wi1[(jg + 1) * 12546 + 12545];
#pragma unroll
        for (int half = 0; half < 2; half++) {
            int q = warpM * 16 + r + half * 8;
            float ry = s_cell[q * 2 + 0] * 64.f, rx = s_cell[q * 2 + 1] * 64.f;
            float v0 = cfrag[nt][half * 2 + 0] + b0 + w00 * ry + w10 * rx;
            float v1 = cfrag[nt][half * 2 + 1] + b1 + w01 * ry + w11 * rx;
            g_hidden[(qb + q) * 256 + jg] = fmaxf(v0, 0.f);
            g_hidden[(qb + q) * 256 + jg + 1] = fmaxf(v1, 0.f);
        }
    }
}

// ---------------- final MLP 256->3 + skip -----------------------------------
__global__ void __launch_bounds__(128) fin_kernel(
    const float* __restrict__ Wi2, const float* __restrict__ bi2,
    float* __restrict__ out)
{
    __shared__ float s_h[32 * 260];
    __shared__ float s_w2[768];
    const int t = threadIdx.x;
    const int qb = blockIdx.x * 32;
    const float4* src = (const float4*)(g_hidden + qb * 256);
#pragma unroll
    for (int i = 0; i < 16; i++) {
        int fi = t + i * 128;
        int q = fi >> 6, jf = fi & 63;
        ((float4*)(s_h + q * 260))[jf] = src[fi];
    }
    for (int i = t; i < 768; i += 128) s_w2[i] = Wi2[i];
    __syncthreads();
    if (t < 96) {
        int q = t / 3, c = t % 3;
        float s = 0.f;
        for (int j = 0; j < 256; j++) s += s_h[q * 260 + j] * s_w2[c * 256 + j];
        out[(qb + q) * 3 + c] = s + bi2[c] + g_skipv[(qb + q) * 3 + c];
    }
}

// ---------------- host ------------------------------------------------------
extern "C" void kernel_launch(void* const* d_in, const int* in_sizes, int n_in,
                              void* d_out, int out_size)
{
    const float* inp   = (const float*)d_in[0];
    const float* coord = (const float*)d_in[1];
    const float* cell  = (const float*)d_in[2];
    const float* W_enc = (const float*)d_in[3];
    const float* b_enc = (const float*)d_in[4];
    const float* W_ch  = (const float*)d_in[5];
    const float* b_ch  = (const float*)d_in[6];
    const float* W_q   = (const float*)d_in[7];
    const float* b_q   = (const float*)d_in[8];
    const float* W_k   = (const float*)d_in[9];
    const float* b_k   = (const float*)d_in[10];
    const float* W_v   = (const float*)d_in[11];
    const float* b_v   = (const float*)d_in[12];
    const float* W_off1= (const float*)d_in[13];
    const float* b_off1= (const float*)d_in[14];
    const float* ln_g  = (const float*)d_in[15];
    const float* ln_b  = (const float*)d_in[16];
    const float* W_off2= (const float*)d_in[17];
    const float* Wc1   = (const float*)d_in[18];
    const float* bc1   = (const float*)d_in[19];
    const float* Wc2   = (const float*)d_in[20];
    const float* bc2   = (const float*)d_in[21];
    const float* Wi1   = (const float*)d_in[22];
    const float* bi1   = (const float*)d_in[23];
    const float* Wi2   = (const float*)d_in[24];
    const float* bi2   = (const float*)d_in[25];
    float* out = (float*)d_out;

    void* p;
    cudaGetSymbolAddress(&p, g_enc);     float* enc = (float*)p;
    cudaGetSymbolAddress(&p, g_feat);    float* feat = (float*)p;
    cudaGetSymbolAddress(&p, g_fq);      float* fq = (float*)p;
    cudaGetSymbolAddress(&p, g_fk);      float* fk = (float*)p;
    cudaGetSymbolAddress(&p, g_fv);      float* fv = (float*)p;
    cudaGetSymbolAddress(&p, g_off1);    float* off1 = (float*)p;
    cudaGetSymbolAddress(&p, g_act);     float* act = (float*)p;
    cudaGetSymbolAddress(&p, g_offmap);  float* offmap = (float*)p;
    cudaGetSymbolAddress(&p, g_Wc1T);    float* wc1t = (float*)p;
    cudaGetSymbolAddress(&p, g_Wc2T);    float* wc2t = (float*)p;
    cudaGetSymbolAddress(&p, g_WchT);    float* wcht = (float*)p;
    cudaGetSymbolAddress(&p, g_W5T);     float* w5t = (float*)p;

    cudaFuncSetAttribute(convmma_ch_kernel<64>, cudaFuncAttributeMaxDynamicSharedMemorySize, 47232);
    cudaFuncSetAttribute(convmma_qkv_kernel, cudaFuncAttributeMaxDynamicSharedMemorySize, 90240);
    cudaFuncSetAttribute(convmma5_kernel, cudaFuncAttributeMaxDynamicSharedMemorySize, 67968);
    cudaFuncSetAttribute(gemm_kernel, cudaFuncAttributeMaxDynamicSharedMemorySize, 84480);

    dim3 tb(32, 8);
    wtrans2_kernel<<<dim3(9 * 256, 4), 256>>>(W_ch, W_q, W_k, W_v);              // 1
    conv3x3_kernel<3, 64, true><<<dim3(4, 4, 4), 128>>>(inp, W_enc, b_enc, enc); // 2
    convmma_ch_kernel<64><<<dim3(32, 8), 256, 47232>>>(enc, wcht, b_ch, feat);   // 3
    convmma_qkv_kernel<<<dim3(32, 8), 256, 90240>>>(feat, b_q, b_k, b_v,
                                                    fq, fk, fv);                 // 4 <- profiled
    wtrans5_kernel<<<dim3(25, 8), dim3(32, 32)>>>(W_off1, w5t);                  // 5
    convmma5_kernel<<<dim3(32, 8), 256, 67968>>>(feat, w5t, b_off1, off1);       // 6
    wi1b_kernel<<<256, 256>>>(Wi1);                                              // 7
    transpose_kernel<<<dim3(4, 8), tb>>>(Wc1, wc1t, 256, 98, 0);                 // 8
    transpose_kernel<<<dim3(8, 2), tb>>>(Wc2, wc2t, 49, 256, 0);                 // 9
    ln_gelu_kernel<<<512, 256>>>(off1, ln_g, ln_b, act);                         // 10
    conv1x1_kernel<<<128, 128>>>(act, W_off2, offmap);                           // 11
    qprep_kernel<<<4096, 256>>>(coord, inp, bc1, bc2);                           // 12
    gemm_kernel<<<256, 256, 84480>>>(cell, bi1, Wi1);                            // 13
    fin_kernel<<<128, 128>>>(Wi2, bi2, out);                                     // 14
}